// round 2
// baseline (speedup 1.0000x reference)
#include <cuda_runtime.h>
#include <cuda_bf16.h>
#include <cstdint>

// Problem constants (fixed by setup_inputs)
#define BSZ 256
#define SEQ 64
#define EMB 1024
#define HID 512
#define MAXN 127           // 2*S-1
#define NSTEP 63           // S-1
#define NCAT 511

typedef unsigned long long ull;

// ---------------- f32x2 helpers (FFMA2 path: 2x fp32 throughput on sm_103a) ----
__device__ __forceinline__ ull pack2(float lo, float hi) {
    ull r; asm("mov.b64 %0,{%1,%2};" : "=l"(r) : "f"(lo), "f"(hi)); return r;
}
__device__ __forceinline__ void unpack2(ull v, float &lo, float &hi) {
    asm("mov.b64 {%0,%1},%2;" : "=f"(lo), "=f"(hi) : "l"(v));
}
__device__ __forceinline__ void fma2(ull &d, ull a, ull b) {
    asm("fma.rn.f32x2 %0, %1, %2, %0;" : "+l"(d) : "l"(a), "l"(b));
}

// ---------------- scratch (device globals: allocation-free) -------------------
__device__ float g_comb[(size_t)BSZ * SEQ * HID];        // 33.5 MB  relu(GEMM1)
__device__ float g_nodes[(size_t)BSZ * MAXN * HID];      // 66.6 MB  node vectors

// ==============================================================================
// GEMM1: comb[m,n] = relu( sum_{k<512} X[m,k]W1[k,n] + sum_{k>=512} X[m,k]W2[k-512,n] )
// M=16384, N=512, K=1024.  BM=128, BN=64, BK=16, 256 thr, thread tile 8x4, f32x2.
// ==============================================================================
#define G_BM 128
#define G_BN 64
#define G_BK 16
#define SSTR 18   // smem row stride (even -> 8B aligned float2 reads, spread banks)

__global__ __launch_bounds__(256, 2) void gemm1_kernel(
    const float* __restrict__ X, const float* __restrict__ W1, const float* __restrict__ W2)
{
    __shared__ __align__(16) float As[G_BM * SSTR];
    __shared__ __align__(16) float Bs[G_BN * SSTR];

    const int tid  = threadIdx.x;
    const int warp = tid >> 5, lane = tid & 31;
    const int tmBase = (warp >> 1) * 32 + (lane >> 3);  // rows: tmBase + 4*i, i<8
    const int tnBase = (warp & 1) * 32 + (lane & 7);    // cols: tnBase + 8*j, j<4
    const int m0 = blockIdx.x * G_BM;
    const int n0 = blockIdx.y * G_BN;

    const int aRow = tid >> 1;
    const int aK   = (tid & 1) * 8;
    const int bK   = tid >> 4;        // 0..15
    const int bN   = (tid & 15) * 4;  // 0..60

    ull acc[8][4];
#pragma unroll
    for (int i = 0; i < 8; i++)
#pragma unroll
        for (int j = 0; j < 4; j++) acc[i][j] = 0ull;

    const float* aG = X + (size_t)(m0 + aRow) * EMB + aK;

    for (int kt = 0; kt < EMB; kt += G_BK) {
        float4 av0 = *(const float4*)(aG + kt);
        float4 av1 = *(const float4*)(aG + kt + 4);
        int kk = kt + bK;
        const float* wp = (kk < HID) ? (W1 + (size_t)kk * HID + (n0 + bN))
                                     : (W2 + (size_t)(kk - HID) * HID + (n0 + bN));
        float4 bv = *(const float4*)wp;

        __syncthreads();
        float* as = &As[aRow * SSTR + aK];
        as[0]=av0.x; as[1]=av0.y; as[2]=av0.z; as[3]=av0.w;
        as[4]=av1.x; as[5]=av1.y; as[6]=av1.z; as[7]=av1.w;
        Bs[(bN+0)*SSTR + bK] = bv.x;
        Bs[(bN+1)*SSTR + bK] = bv.y;
        Bs[(bN+2)*SSTR + bK] = bv.z;
        Bs[(bN+3)*SSTR + bK] = bv.w;
        __syncthreads();

#pragma unroll
        for (int kp = 0; kp < G_BK; kp += 2) {
            ull af[8], bf[4];
#pragma unroll
            for (int i = 0; i < 8; i++)
                af[i] = *(const ull*)&As[(tmBase + i*4) * SSTR + kp];
#pragma unroll
            for (int j = 0; j < 4; j++)
                bf[j] = *(const ull*)&Bs[(tnBase + j*8) * SSTR + kp];
#pragma unroll
            for (int i = 0; i < 8; i++)
#pragma unroll
                for (int j = 0; j < 4; j++)
                    fma2(acc[i][j], af[i], bf[j]);
        }
    }

#pragma unroll
    for (int i = 0; i < 8; i++) {
        float* cp = g_comb + (size_t)(m0 + tmBase + i*4) * HID + n0;
#pragma unroll
        for (int j = 0; j < 4; j++) {
            float lo, hi; unpack2(acc[i][j], lo, hi);
            float v = lo + hi;
            cp[tnBase + j*8] = v > 0.f ? v : 0.f;
        }
    }
}

// ==============================================================================
// Normalize rows of comb and scatter into g_nodes per original_pos.
// One block per (b,s) row. 128 threads, float4 each.
// ==============================================================================
__global__ __launch_bounds__(128) void normalize_scatter_kernel(const int* __restrict__ opos)
{
    const int row = blockIdx.x;          // 0..16383
    const int b = row >> 6;
    const int dst = opos[(row << 1) + 0];
    const int src = opos[(row << 1) + 1];
    const int tid = threadIdx.x;

    const float4* cp = (const float4*)(g_comb + ((size_t)(b * SEQ + src)) * HID);
    float4 v = cp[tid];
    float ss = v.x*v.x + v.y*v.y + v.z*v.z + v.w*v.w;
#pragma unroll
    for (int o = 16; o; o >>= 1) ss += __shfl_xor_sync(0xffffffffu, ss, o);
    __shared__ float ws[4];
    if ((tid & 31) == 0) ws[tid >> 5] = ss;
    __syncthreads();
    float tot = ws[0] + ws[1] + ws[2] + ws[3];
    float sc = 1.f / (sqrtf(tot) + 1e-6f);
    float4 o4 = make_float4(v.x*sc, v.y*sc, v.z*sc, v.w*sc);
    ((float4*)(g_nodes + ((size_t)(b * MAXN + dst)) * HID))[tid] = o4;
}

// ==============================================================================
// Chain: one block per batch, 63 sequential circular-correlation steps.
// c[n] = sum_j L[j] * R[(j+n) mod 512], then L2-normalize, write node p.
// 128 threads, 4 consecutive outputs each, f32x2 pairwise-j accumulation,
// R duplicated (1024) in smem to eliminate the modulo, sliding register window.
// ==============================================================================
__global__ __launch_bounds__(128) void chain_kernel(const int* __restrict__ cinfo)
{
    const int b = blockIdx.x;
    const int tid = threadIdx.x;
    __shared__ __align__(16) float sL[512];
    __shared__ __align__(16) float sR2[1024];
    __shared__ float ws[4];

    float* nb = g_nodes + (size_t)b * MAXN * HID;
    const int* info = cinfo + (size_t)b * NSTEP * 4;
    const int n0 = tid * 4;

    for (int k = 0; k < NSTEP; k++) {
        const int t = info[k*4 + 0];
        const int p = info[k*4 + 1];
        const int l = info[k*4 + 2];
        const int r = info[k*4 + 3];

        __syncthreads();  // prior writes visible; smem free to overwrite
        float4 lv = ((const float4*)(nb + (size_t)l * HID))[tid];
        float4 rv = ((const float4*)(nb + (size_t)r * HID))[tid];
        ((float4*)sL)[tid] = lv;
        ((float4*)sR2)[tid] = rv;
        ((float4*)sR2)[tid + 128] = rv;
        __syncthreads();

        if (t == 2) {
            ull a0 = 0ull, a1 = 0ull, a2 = 0ull, a3 = 0ull;
            float w0 = sR2[n0], w1 = sR2[n0 + 1], w2 = sR2[n0 + 2];
#pragma unroll 8
            for (int j = 0; j < 512; j += 2) {
                float w3 = sR2[n0 + j + 3];
                float w4 = sR2[n0 + j + 4];
                ull aa = *(const ull*)&sL[j];
                fma2(a0, aa, pack2(w0, w1));
                fma2(a1, aa, pack2(w1, w2));
                fma2(a2, aa, pack2(w2, w3));
                fma2(a3, aa, pack2(w3, w4));
                w0 = w2; w1 = w3; w2 = w4;
            }
            float lo, hi, c0, c1, c2, c3;
            unpack2(a0, lo, hi); c0 = lo + hi;
            unpack2(a1, lo, hi); c1 = lo + hi;
            unpack2(a2, lo, hi); c2 = lo + hi;
            unpack2(a3, lo, hi); c3 = lo + hi;

            float ss = c0*c0 + c1*c1 + c2*c2 + c3*c3;
#pragma unroll
            for (int o = 16; o; o >>= 1) ss += __shfl_xor_sync(0xffffffffu, ss, o);
            if ((tid & 31) == 0) ws[tid >> 5] = ss;
            __syncthreads();
            float sc = 1.f / (sqrtf(ws[0] + ws[1] + ws[2] + ws[3]) + 1e-6f);
            float4 o4 = make_float4(c0*sc, c1*sc, c2*sc, c3*sc);
            ((float4*)(nb + (size_t)p * HID))[tid] = o4;
        } else if (t == 1) {
            ((float4*)(nb + (size_t)p * HID))[tid] = lv;
        }
        // t == other: node p keeps its current value (no write)
    }
}

// ==============================================================================
// GEMM2: out[m,n] = sum_k nodes[m,k] * LW[n,k] + LB[n]   (NT, both K-contiguous)
// M = 32512 (=256*127), N = 511, K = 512.
// ==============================================================================
__global__ __launch_bounds__(256, 2) void gemm2_kernel(
    const float* __restrict__ LW, const float* __restrict__ LB, float* __restrict__ out)
{
    __shared__ __align__(16) float As[G_BM * SSTR];
    __shared__ __align__(16) float Bs[G_BN * SSTR];

    const int tid  = threadIdx.x;
    const int warp = tid >> 5, lane = tid & 31;
    const int tmBase = (warp >> 1) * 32 + (lane >> 3);
    const int tnBase = (warp & 1) * 32 + (lane & 7);
    const int m0 = blockIdx.x * G_BM;
    const int n0 = blockIdx.y * G_BN;

    const int aRow = tid >> 1;
    const int aK   = (tid & 1) * 8;
    const int bRow = tid >> 2;        // 0..63 (n within tile)
    const int bK4  = (tid & 3) * 4;   // 0..12

    ull acc[8][4];
#pragma unroll
    for (int i = 0; i < 8; i++)
#pragma unroll
        for (int j = 0; j < 4; j++) acc[i][j] = 0ull;

    const float* aG = g_nodes + (size_t)(m0 + aRow) * HID + aK;
    const int nIdx = n0 + bRow;
    const bool bValid = (nIdx < NCAT);

    for (int kt = 0; kt < HID; kt += G_BK) {
        float4 av0 = *(const float4*)(aG + kt);
        float4 av1 = *(const float4*)(aG + kt + 4);
        float4 bv = make_float4(0.f, 0.f, 0.f, 0.f);
        if (bValid) bv = *(const float4*)(LW + (size_t)nIdx * HID + kt + bK4);

        __syncthreads();
        float* as = &As[aRow * SSTR + aK];
        as[0]=av0.x; as[1]=av0.y; as[2]=av0.z; as[3]=av0.w;
        as[4]=av1.x; as[5]=av1.y; as[6]=av1.z; as[7]=av1.w;
        float* bs = &Bs[bRow * SSTR + bK4];
        bs[0]=bv.x; bs[1]=bv.y; bs[2]=bv.z; bs[3]=bv.w;
        __syncthreads();

#pragma unroll
        for (int kp = 0; kp < G_BK; kp += 2) {
            ull af[8], bf[4];
#pragma unroll
            for (int i = 0; i < 8; i++)
                af[i] = *(const ull*)&As[(tmBase + i*4) * SSTR + kp];
#pragma unroll
            for (int j = 0; j < 4; j++)
                bf[j] = *(const ull*)&Bs[(tnBase + j*8) * SSTR + kp];
#pragma unroll
            for (int i = 0; i < 8; i++)
#pragma unroll
                for (int j = 0; j < 4; j++)
                    fma2(acc[i][j], af[i], bf[j]);
        }
    }

#pragma unroll
    for (int i = 0; i < 8; i++) {
        float* cp = out + (size_t)(m0 + tmBase + i*4) * NCAT;
#pragma unroll
        for (int j = 0; j < 4; j++) {
            int n = n0 + tnBase + j*8;
            if (n < NCAT) {
                float lo, hi; unpack2(acc[i][j], lo, hi);
                cp[n] = lo + hi + LB[n];
            }
        }
    }
}

// ==============================================================================
extern "C" void kernel_launch(void* const* d_in, const int* in_sizes, int n_in,
                              void* d_out, int out_size)
{
    const float* seq  = (const float*)d_in[0];   // (256,64,1024)
    const float* W1   = (const float*)d_in[1];   // (512,512)
    const float* W2   = (const float*)d_in[2];   // (512,512)
    const float* LW   = (const float*)d_in[3];   // (511,512)
    const float* LB   = (const float*)d_in[4];   // (511,)
    const int*   opos = (const int*)d_in[7];     // (256,64,2)
    const int*   cinf = (const int*)d_in[8];     // (256,63,4)
    float* out = (float*)d_out;                  // (256,127,511)

    dim3 g1(BSZ * SEQ / G_BM, HID / G_BN);       // 128 x 8
    gemm1_kernel<<<g1, 256>>>(seq, W1, W2);

    normalize_scatter_kernel<<<BSZ * SEQ, 128>>>(opos);

    chain_kernel<<<BSZ, 128>>>(cinf);

    dim3 g2(BSZ * MAXN / G_BM, (NCAT + G_BN - 1) / G_BN);  // 254 x 8
    gemm2_kernel<<<g2, 256>>>(LW, LB, out);
}

// round 4
// speedup vs baseline: 1.6603x; 1.6603x over previous
#include <cuda_runtime.h>
#include <cuda_bf16.h>
#include <cstdint>

// Problem constants (fixed by setup_inputs)
#define BSZ 256
#define SEQ 64
#define EMB 1024
#define HID 512
#define MAXN 127           // 2*S-1
#define NSTEP 63           // S-1
#define NCAT 511

typedef unsigned long long ull;
typedef __nv_bfloat16 bf16;

// ---------------- f32x2 helpers (chain kernel) --------------------------------
__device__ __forceinline__ ull pack2(float lo, float hi) {
    ull r; asm("mov.b64 %0,{%1,%2};" : "=l"(r) : "f"(lo), "f"(hi)); return r;
}
__device__ __forceinline__ void unpack2(ull v, float &lo, float &hi) {
    asm("mov.b64 {%0,%1},%2;" : "=f"(lo), "=f"(hi) : "l"(v));
}
__device__ __forceinline__ void fma2(ull &d, ull a, ull b) {
    asm("fma.rn.f32x2 %0, %1, %2, %0;" : "+l"(d) : "l"(a), "l"(b));
}

// ---------------- HMMA helpers (base ISA, no 'a' features) --------------------
__device__ __forceinline__ uint32_t smem_u32(const void* p) {
    uint32_t a;
    asm("{ .reg .u64 t; cvta.to.shared.u64 t, %1; cvt.u32.u64 %0, t; }" : "=r"(a) : "l"(p));
    return a;
}
__device__ __forceinline__ void cpasync16(uint32_t dst, const void* src) {
    asm volatile("cp.async.cg.shared.global [%0], [%1], 16;" :: "r"(dst), "l"(src) : "memory");
}
__device__ __forceinline__ void ldsm4(uint32_t &d0, uint32_t &d1, uint32_t &d2, uint32_t &d3,
                                      uint32_t addr) {
    asm volatile("ldmatrix.sync.aligned.m8n8.x4.shared.b16 {%0,%1,%2,%3}, [%4];"
                 : "=r"(d0), "=r"(d1), "=r"(d2), "=r"(d3) : "r"(addr));
}
__device__ __forceinline__ void mma16816(float* c, const uint32_t* a, uint32_t b0, uint32_t b1) {
    asm volatile("mma.sync.aligned.m16n8k16.row.col.f32.bf16.bf16.f32 "
                 "{%0,%1,%2,%3}, {%4,%5,%6,%7}, {%8,%9}, {%0,%1,%2,%3};"
                 : "+f"(c[0]), "+f"(c[1]), "+f"(c[2]), "+f"(c[3])
                 : "r"(a[0]), "r"(a[1]), "r"(a[2]), "r"(a[3]), "r"(b0), "r"(b1));
}

// ---------------- scratch (device globals: allocation-free) -------------------
__device__ float g_comb[(size_t)BSZ * SEQ * HID];                // relu(GEMM1) fp32
__device__ float g_nodes[(size_t)BSZ * MAXN * HID];              // node vectors fp32
__device__ bf16  g_ae1[(size_t)BSZ * SEQ * (3 * EMB)];           // seq K-extended
__device__ bf16  g_be1[(size_t)HID * (3 * EMB)];                 // W  K-extended [n][k']
__device__ bf16  g_ae2[(size_t)BSZ * MAXN * (3 * HID)];          // nodes K-extended
__device__ bf16  g_be2[(size_t)512 * (3 * HID)];                 // LW K-extended (pad n=512)

// ==============================================================================
// Prep kernels: fp32 -> bf16 hi/lo K-extension.
// A layout per row: [ah(0..K) | ah | al];  B per row: [bh | bl | bh]
// Product over K'=3K gives ah*bh + ah*bl + al*bh.
// ==============================================================================
__global__ void prep_a_kernel(const float* __restrict__ src, bf16* __restrict__ dst, int K)
{
    size_t id = (size_t)blockIdx.x * 256 + threadIdx.x;   // over M*K
    size_t m = id / K; int k = (int)(id % K);
    float v = src[id];
    bf16 h = __float2bfloat16(v);
    bf16 l = __float2bfloat16(v - __bfloat162float(h));
    bf16* row = dst + m * (size_t)(3 * K);
    row[k] = h; row[K + k] = h; row[2 * K + k] = l;
}

__global__ void prep_b1_kernel(const float* __restrict__ W1, const float* __restrict__ W2)
{
    int id = blockIdx.x * 256 + threadIdx.x;              // over 512*1024
    int n = id >> 10, k = id & 1023;
    float v = (k < HID) ? W1[(size_t)k * HID + n] : W2[(size_t)(k - HID) * HID + n];
    bf16 h = __float2bfloat16(v);
    bf16 l = __float2bfloat16(v - __bfloat162float(h));
    bf16* row = g_be1 + (size_t)n * (3 * EMB);
    row[k] = h; row[EMB + k] = l; row[2 * EMB + k] = h;
}

__global__ void prep_b2_kernel(const float* __restrict__ LW)
{
    int id = blockIdx.x * 256 + threadIdx.x;              // over 512*512
    int n = id >> 9, k = id & 511;
    float v = (n < NCAT) ? LW[(size_t)n * HID + k] : 0.f;
    bf16 h = __float2bfloat16(v);
    bf16 l = __float2bfloat16(v - __bfloat162float(h));
    bf16* row = g_be2 + (size_t)n * (3 * HID);
    row[k] = h; row[HID + k] = l; row[2 * HID + k] = h;
}

// ==============================================================================
// bf16 HMMA GEMM: out[M,N] = Ae[M,K'] @ Be[N,K']^T  (+relu or +bias)
// Block 128x128, BK=32, 8 warps (4m x 2n), warp tile 32x64, cp.async 2-stage.
// Smem XOR swizzle: 16B chunk c at row r stored at chunk c ^ ((r>>1)&3).
// EPI=0: out = relu(D), ldo=512.   EPI=1: out = D + bias[n], n<511 guard, ldo=511.
// ==============================================================================
#define BM 128
#define BN 128
#define BKK 32
#define ATILE (BM * BKK * 2)   // bytes per A stage (bf16)
#define BTILE (BN * BKK * 2)

template<int EPI>
__global__ void __launch_bounds__(256, 2) mm_hmma_kernel(
    const bf16* __restrict__ Ae, const bf16* __restrict__ Be,
    const float* __restrict__ bias, float* __restrict__ out, int Kp, int ldo)
{
    __shared__ __align__(16) bf16 smA[2][BM * BKK];
    __shared__ __align__(16) bf16 smB[2][BN * BKK];

    const int tid  = threadIdx.x;
    const int lane = tid & 31;
    const int wid  = tid >> 5;
    const int wm   = (wid & 3) * 32;
    const int wn   = (wid >> 2) * 64;
    const int n0   = blockIdx.x * BN;
    const int m0   = blockIdx.y * BM;

    const uint32_t sA0 = smem_u32(smA);
    const uint32_t sB0 = smem_u32(smB);

    float acc[2][8][4];
#pragma unroll
    for (int mt = 0; mt < 2; mt++)
#pragma unroll
        for (int nt = 0; nt < 8; nt++)
#pragma unroll
            for (int i = 0; i < 4; i++) acc[mt][nt][i] = 0.f;

    const bf16* Abase = Ae + (size_t)m0 * Kp;
    const bf16* Bbase = Be + (size_t)n0 * Kp;

    // loader: each thread moves 2 A chunks + 2 B chunks (16B each) per stage
    const int ld_row0 = tid >> 1;              // id = tid+256*i -> row = id>>2
    // (computed inline below to keep it simple)

    auto load_tile = [&](int kt, int buf) {
#pragma unroll
        for (int i = 0; i < 2; i++) {
            int id = tid + 256 * i;
            int row = id >> 2, cc = id & 3;
            uint32_t dst = sA0 + buf * ATILE + row * 64 + ((cc ^ ((row >> 1) & 3)) << 4);
            cpasync16(dst, Abase + (size_t)row * Kp + kt + cc * 8);
        }
#pragma unroll
        for (int i = 0; i < 2; i++) {
            int id = tid + 256 * i;
            int row = id >> 2, cc = id & 3;
            uint32_t dst = sB0 + buf * BTILE + row * 64 + ((cc ^ ((row >> 1) & 3)) << 4);
            cpasync16(dst, Bbase + (size_t)row * Kp + kt + cc * 8);
        }
    };
    (void)ld_row0;

    load_tile(0, 0);
    asm volatile("cp.async.commit_group;" ::: "memory");

    // per-lane ldmatrix constants
    const int rA  = wm + (lane & 15);          // A row within tile
    const int hA  = lane >> 4;                 // k-chunk offset 0/1
    const int sAx = (rA >> 1) & 3;
    const int rB  = wn + (lane & 7) + ((lane >> 4) << 3);   // B row (n) within tile
    const int hB  = (lane >> 3) & 1;
    const int sBx = (rB >> 1) & 3;

    const int C = Kp / BKK;
    for (int c = 0; c < C; c++) {
        const int buf = c & 1;
        if (c + 1 < C) load_tile((c + 1) * BKK, buf ^ 1);
        asm volatile("cp.async.commit_group;" ::: "memory");
        asm volatile("cp.async.wait_group 1;" ::: "memory");
        __syncthreads();

        const uint32_t baseA = sA0 + buf * ATILE;
        const uint32_t baseB = sB0 + buf * BTILE;
#pragma unroll
        for (int ks = 0; ks < 2; ks++) {
            uint32_t a[2][4], b[4][4];
            const int chA = ((ks * 2 + hA) ^ sAx) << 4;
            const int chB = ((ks * 2 + hB) ^ sBx) << 4;
#pragma unroll
            for (int mt = 0; mt < 2; mt++)
                ldsm4(a[mt][0], a[mt][1], a[mt][2], a[mt][3],
                      baseA + (rA + mt * 16) * 64 + chA);
#pragma unroll
            for (int g = 0; g < 4; g++)
                ldsm4(b[g][0], b[g][1], b[g][2], b[g][3],
                      baseB + (rB + g * 16) * 64 + chB);
#pragma unroll
            for (int mt = 0; mt < 2; mt++)
#pragma unroll
                for (int nt = 0; nt < 8; nt++)
                    mma16816(acc[mt][nt], a[mt],
                             b[nt >> 1][(nt & 1) * 2], b[nt >> 1][(nt & 1) * 2 + 1]);
        }
        __syncthreads();
    }

    // epilogue: direct gmem stores
#pragma unroll
    for (int mt = 0; mt < 2; mt++) {
        const int mrow = m0 + wm + mt * 16 + (lane >> 2);
#pragma unroll
        for (int nt = 0; nt < 8; nt++) {
            const int ncol = n0 + wn + nt * 8 + 2 * (lane & 3);
            float* cc = acc[mt][nt];
            if (EPI == 0) {
                float2 v0 = make_float2(fmaxf(cc[0], 0.f), fmaxf(cc[1], 0.f));
                float2 v1 = make_float2(fmaxf(cc[2], 0.f), fmaxf(cc[3], 0.f));
                *(float2*)(out + (size_t)mrow * ldo + ncol) = v0;
                *(float2*)(out + (size_t)(mrow + 8) * ldo + ncol) = v1;
            } else {
                if (ncol < NCAT) {
                    float bv = bias[ncol];
                    out[(size_t)mrow * ldo + ncol] = cc[0] + bv;
                    out[(size_t)(mrow + 8) * ldo + ncol] = cc[2] + bv;
                }
                if (ncol + 1 < NCAT) {
                    float bv = bias[ncol + 1];
                    out[(size_t)mrow * ldo + ncol + 1] = cc[1] + bv;
                    out[(size_t)(mrow + 8) * ldo + ncol + 1] = cc[3] + bv;
                }
            }
        }
    }
}

// ==============================================================================
// Normalize rows of comb and scatter into g_nodes per original_pos.
// ==============================================================================
__global__ void __launch_bounds__(128) normalize_scatter_kernel(const int* __restrict__ opos)
{
    const int row = blockIdx.x;          // 0..16383
    const int b = row >> 6;
    const int dst = opos[(row << 1) + 0];
    const int src = opos[(row << 1) + 1];
    const int tid = threadIdx.x;

    const float4* cp = (const float4*)(g_comb + ((size_t)(b * SEQ + src)) * HID);
    float4 v = cp[tid];
    float ss = v.x*v.x + v.y*v.y + v.z*v.z + v.w*v.w;
#pragma unroll
    for (int o = 16; o; o >>= 1) ss += __shfl_xor_sync(0xffffffffu, ss, o);
    __shared__ float ws[4];
    if ((tid & 31) == 0) ws[tid >> 5] = ss;
    __syncthreads();
    float tot = ws[0] + ws[1] + ws[2] + ws[3];
    float sc = 1.f / (sqrtf(tot) + 1e-6f);
    float4 o4 = make_float4(v.x*sc, v.y*sc, v.z*sc, v.w*sc);
    ((float4*)(g_nodes + ((size_t)(b * MAXN + dst)) * HID))[tid] = o4;
}

// ==============================================================================
// Chain: one block per batch, 63 sequential circular-correlation steps.
// ==============================================================================
__global__ void __launch_bounds__(128) chain_kernel(const int* __restrict__ cinfo)
{
    const int b = blockIdx.x;
    const int tid = threadIdx.x;
    __shared__ __align__(16) float sL[512];
    __shared__ __align__(16) float sR2[1024];
    __shared__ float ws[4];

    float* nb = g_nodes + (size_t)b * MAXN * HID;
    const int* info = cinfo + (size_t)b * NSTEP * 4;
    const int n0 = tid * 4;

    for (int k = 0; k < NSTEP; k++) {
        const int t = info[k*4 + 0];
        const int p = info[k*4 + 1];
        const int l = info[k*4 + 2];
        const int r = info[k*4 + 3];

        __syncthreads();
        float4 lv = ((const float4*)(nb + (size_t)l * HID))[tid];
        float4 rv = ((const float4*)(nb + (size_t)r * HID))[tid];
        ((float4*)sL)[tid] = lv;
        ((float4*)sR2)[tid] = rv;
        ((float4*)sR2)[tid + 128] = rv;
        __syncthreads();

        if (t == 2) {
            ull a0 = 0ull, a1 = 0ull, a2 = 0ull, a3 = 0ull;
            float w0 = sR2[n0], w1 = sR2[n0 + 1], w2 = sR2[n0 + 2];
#pragma unroll 8
            for (int j = 0; j < 512; j += 2) {
                float w3 = sR2[n0 + j + 3];
                float w4 = sR2[n0 + j + 4];
                ull aa = *(const ull*)&sL[j];
                fma2(a0, aa, pack2(w0, w1));
                fma2(a1, aa, pack2(w1, w2));
                fma2(a2, aa, pack2(w2, w3));
                fma2(a3, aa, pack2(w3, w4));
                w0 = w2; w1 = w3; w2 = w4;
            }
            float lo, hi, c0, c1, c2, c3;
            unpack2(a0, lo, hi); c0 = lo + hi;
            unpack2(a1, lo, hi); c1 = lo + hi;
            unpack2(a2, lo, hi); c2 = lo + hi;
            unpack2(a3, lo, hi); c3 = lo + hi;

            float ss = c0*c0 + c1*c1 + c2*c2 + c3*c3;
#pragma unroll
            for (int o = 16; o; o >>= 1) ss += __shfl_xor_sync(0xffffffffu, ss, o);
            if ((tid & 31) == 0) ws[tid >> 5] = ss;
            __syncthreads();
            float sc = 1.f / (sqrtf(ws[0] + ws[1] + ws[2] + ws[3]) + 1e-6f);
            float4 o4 = make_float4(c0*sc, c1*sc, c2*sc, c3*sc);
            ((float4*)(nb + (size_t)p * HID))[tid] = o4;
        } else if (t == 1) {
            ((float4*)(nb + (size_t)p * HID))[tid] = lv;
        }
    }
}

// ==============================================================================
extern "C" void kernel_launch(void* const* d_in, const int* in_sizes, int n_in,
                              void* d_out, int out_size)
{
    const float* seq  = (const float*)d_in[0];   // (256,64,1024)
    const float* W1   = (const float*)d_in[1];   // (512,512)
    const float* W2   = (const float*)d_in[2];   // (512,512)
    const float* LW   = (const float*)d_in[3];   // (511,512)
    const float* LB   = (const float*)d_in[4];   // (511,)
    const int*   opos = (const int*)d_in[7];     // (256,64,2)
    const int*   cinf = (const int*)d_in[8];     // (256,63,4)
    float* out = (float*)d_out;                  // (256,127,511)

    bf16 *ae1, *be1, *ae2, *be2; float *comb, *nodes;
    cudaGetSymbolAddress((void**)&ae1, g_ae1);
    cudaGetSymbolAddress((void**)&be1, g_be1);
    cudaGetSymbolAddress((void**)&ae2, g_ae2);
    cudaGetSymbolAddress((void**)&be2, g_be2);
    cudaGetSymbolAddress((void**)&comb, g_comb);
    cudaGetSymbolAddress((void**)&nodes, g_nodes);

    // --- prep GEMM1 operands ---
    prep_b1_kernel<<<(HID * EMB) / 256, 256>>>(W1, W2);
    prep_a_kernel<<<(BSZ * SEQ * EMB) / 256, 256>>>(seq, ae1, EMB);

    // --- GEMM1: comb = relu(seq @ [W1;W2]);  M=16384, N=512, K'=3072 ---
    {
        dim3 g(HID / BN, BSZ * SEQ / BM);     // (4, 128)  n-blocks fastest -> A reuse in L2
        mm_hmma_kernel<0><<<g, 256>>>(ae1, be1, nullptr, comb, 3 * EMB, HID);
    }

    normalize_scatter_kernel<<<BSZ * SEQ, 128>>>(opos);
    chain_kernel<<<BSZ, 128>>>(cinf);

    // --- prep GEMM2 operands ---
    prep_b2_kernel<<<(512 * HID) / 256, 256>>>(LW);
    prep_a_kernel<<<(BSZ * MAXN * HID) / 256, 256>>>(nodes, ae2, HID);

    // --- GEMM2: out = nodes @ LW^T + LB;  M=32512, N=511(pad 512), K'=1536 ---
    {
        dim3 g(512 / BN, BSZ * MAXN / BM);    // (4, 254)
        mm_hmma_kernel<1><<<g, 256>>>(ae2, be2, LB, out, 3 * HID, NCAT);
    }
}

// round 5
// speedup vs baseline: 2.0940x; 1.2612x over previous
#include <cuda_runtime.h>
#include <cuda_bf16.h>
#include <cstdint>

// Problem constants (fixed by setup_inputs)
#define BSZ 256
#define SEQ 64
#define EMB 1024
#define HID 512
#define MAXN 127           // 2*S-1
#define NSTEP 63           // S-1
#define NCAT 511
#define SPST 520           // spec row stride (floats): 257 complex padded to 260

typedef unsigned long long ull;
typedef __nv_bfloat16 bf16;

// ---------------- HMMA helpers (base ISA, no 'a' features) --------------------
__device__ __forceinline__ uint32_t smem_u32(const void* p) {
    uint32_t a;
    asm("{ .reg .u64 t; cvta.to.shared.u64 t, %1; cvt.u32.u64 %0, t; }" : "=r"(a) : "l"(p));
    return a;
}
__device__ __forceinline__ void cpasync16(uint32_t dst, const void* src) {
    asm volatile("cp.async.cg.shared.global [%0], [%1], 16;" :: "r"(dst), "l"(src) : "memory");
}
__device__ __forceinline__ void ldsm4(uint32_t &d0, uint32_t &d1, uint32_t &d2, uint32_t &d3,
                                      uint32_t addr) {
    asm volatile("ldmatrix.sync.aligned.m8n8.x4.shared.b16 {%0,%1,%2,%3}, [%4];"
                 : "=r"(d0), "=r"(d1), "=r"(d2), "=r"(d3) : "r"(addr));
}
__device__ __forceinline__ void mma16816(float* c, const uint32_t* a, uint32_t b0, uint32_t b1) {
    asm volatile("mma.sync.aligned.m16n8k16.row.col.f32.bf16.bf16.f32 "
                 "{%0,%1,%2,%3}, {%4,%5,%6,%7}, {%8,%9}, {%0,%1,%2,%3};"
                 : "+f"(c[0]), "+f"(c[1]), "+f"(c[2]), "+f"(c[3])
                 : "r"(a[0]), "r"(a[1]), "r"(a[2]), "r"(a[3]), "r"(b0), "r"(b1));
}

// ---------------- scratch (device globals: allocation-free) -------------------
__device__ float g_comb[(size_t)BSZ * SEQ * HID];                // relu(GEMM1) fp32
__device__ float g_nodes[(size_t)BSZ * MAXN * HID];              // node vectors fp32
__device__ __align__(16) float g_spec[(size_t)BSZ * MAXN * SPST];// node spectra (257 cplx)
__device__ bf16  g_ae1[(size_t)BSZ * SEQ * (3 * EMB)];           // seq K-extended
__device__ bf16  g_be1[(size_t)HID * (3 * EMB)];                 // W  K-extended [n][k']
__device__ bf16  g_ae2[(size_t)BSZ * MAXN * (3 * HID)];          // nodes K-extended
__device__ bf16  g_be2[(size_t)512 * (3 * HID)];                 // LW K-extended (pad n=512)
// FFT twiddle tables (forward/inverse)
__device__ float2 g_twf[128], g_twi[128], g_w512f[256], g_w512i[256];

// ==============================================================================
// Twiddle table init (one block of 256 threads)
// ==============================================================================
__global__ void init_tables_kernel()
{
    int t = threadIdx.x;
    const float PI2 = 6.283185307179586f;
    if (t < 128) {
        float th = PI2 * t / 256.0f;
        float s, c; sincosf(th, &s, &c);
        g_twf[t] = make_float2(c, -s);
        g_twi[t] = make_float2(c,  s);
    }
    float ph = PI2 * t / 512.0f;
    float s, c; sincosf(ph, &s, &c);
    g_w512f[t] = make_float2(c, -s);
    g_w512i[t] = make_float2(c,  s);
}

// ==============================================================================
// Prep kernels: fp32 -> bf16 hi/lo K-extension.
// A layout per row: [ah | ah | al];  B per row: [bh | bl | bh]
// ==============================================================================
__global__ void prep_a_kernel(const float* __restrict__ src, bf16* __restrict__ dst, int K)
{
    size_t id = (size_t)blockIdx.x * 256 + threadIdx.x;   // over M*K
    size_t m = id / K; int k = (int)(id % K);
    float v = src[id];
    bf16 h = __float2bfloat16(v);
    bf16 l = __float2bfloat16(v - __bfloat162float(h));
    bf16* row = dst + m * (size_t)(3 * K);
    row[k] = h; row[K + k] = h; row[2 * K + k] = l;
}

__global__ void prep_b1_kernel(const float* __restrict__ W1, const float* __restrict__ W2)
{
    int id = blockIdx.x * 256 + threadIdx.x;              // over 512*1024
    int n = id >> 10, k = id & 1023;
    float v = (k < HID) ? W1[(size_t)k * HID + n] : W2[(size_t)(k - HID) * HID + n];
    bf16 h = __float2bfloat16(v);
    bf16 l = __float2bfloat16(v - __bfloat162float(h));
    bf16* row = g_be1 + (size_t)n * (3 * EMB);
    row[k] = h; row[EMB + k] = l; row[2 * EMB + k] = h;
}

__global__ void prep_b2_kernel(const float* __restrict__ LW)
{
    int id = blockIdx.x * 256 + threadIdx.x;              // over 512*512
    int n = id >> 9, k = id & 511;
    float v = (n < NCAT) ? LW[(size_t)n * HID + k] : 0.f;
    bf16 h = __float2bfloat16(v);
    bf16 l = __float2bfloat16(v - __bfloat162float(h));
    bf16* row = g_be2 + (size_t)n * (3 * HID);
    row[k] = h; row[HID + k] = l; row[2 * HID + k] = h;
}

// ==============================================================================
// bf16 HMMA GEMM (same as R3, passing): block 128x128, BK=32, 8 warps, 2-stage.
// EPI=0: relu.  EPI=1: +bias with n<NCAT guard.
// ==============================================================================
#define BM 128
#define BN 128
#define BKK 32
#define ATILE (BM * BKK * 2)
#define BTILE (BN * BKK * 2)

template<int EPI>
__global__ void __launch_bounds__(256, 2) mm_hmma_kernel(
    const bf16* __restrict__ Ae, const bf16* __restrict__ Be,
    const float* __restrict__ bias, float* __restrict__ out, int Kp, int ldo)
{
    __shared__ __align__(16) bf16 smA[2][BM * BKK];
    __shared__ __align__(16) bf16 smB[2][BN * BKK];

    const int tid  = threadIdx.x;
    const int lane = tid & 31;
    const int wid  = tid >> 5;
    const int wm   = (wid & 3) * 32;
    const int wn   = (wid >> 2) * 64;
    const int n0   = blockIdx.x * BN;
    const int m0   = blockIdx.y * BM;

    const uint32_t sA0 = smem_u32(smA);
    const uint32_t sB0 = smem_u32(smB);

    float acc[2][8][4];
#pragma unroll
    for (int mt = 0; mt < 2; mt++)
#pragma unroll
        for (int nt = 0; nt < 8; nt++)
#pragma unroll
            for (int i = 0; i < 4; i++) acc[mt][nt][i] = 0.f;

    const bf16* Abase = Ae + (size_t)m0 * Kp;
    const bf16* Bbase = Be + (size_t)n0 * Kp;

    auto load_tile = [&](int kt, int buf) {
#pragma unroll
        for (int i = 0; i < 2; i++) {
            int id = tid + 256 * i;
            int row = id >> 2, cc = id & 3;
            uint32_t dst = sA0 + buf * ATILE + row * 64 + ((cc ^ ((row >> 1) & 3)) << 4);
            cpasync16(dst, Abase + (size_t)row * Kp + kt + cc * 8);
        }
#pragma unroll
        for (int i = 0; i < 2; i++) {
            int id = tid + 256 * i;
            int row = id >> 2, cc = id & 3;
            uint32_t dst = sB0 + buf * BTILE + row * 64 + ((cc ^ ((row >> 1) & 3)) << 4);
            cpasync16(dst, Bbase + (size_t)row * Kp + kt + cc * 8);
        }
    };

    load_tile(0, 0);
    asm volatile("cp.async.commit_group;" ::: "memory");

    const int rA  = wm + (lane & 15);
    const int hA  = lane >> 4;
    const int sAx = (rA >> 1) & 3;
    const int rB  = wn + (lane & 7) + ((lane >> 4) << 3);
    const int hB  = (lane >> 3) & 1;
    const int sBx = (rB >> 1) & 3;

    const int C = Kp / BKK;
    for (int c = 0; c < C; c++) {
        const int buf = c & 1;
        if (c + 1 < C) load_tile((c + 1) * BKK, buf ^ 1);
        asm volatile("cp.async.commit_group;" ::: "memory");
        asm volatile("cp.async.wait_group 1;" ::: "memory");
        __syncthreads();

        const uint32_t baseA = sA0 + buf * ATILE;
        const uint32_t baseB = sB0 + buf * BTILE;
#pragma unroll
        for (int ks = 0; ks < 2; ks++) {
            uint32_t a[2][4], b[4][4];
            const int chA = ((ks * 2 + hA) ^ sAx) << 4;
            const int chB = ((ks * 2 + hB) ^ sBx) << 4;
#pragma unroll
            for (int mt = 0; mt < 2; mt++)
                ldsm4(a[mt][0], a[mt][1], a[mt][2], a[mt][3],
                      baseA + (rA + mt * 16) * 64 + chA);
#pragma unroll
            for (int g = 0; g < 4; g++)
                ldsm4(b[g][0], b[g][1], b[g][2], b[g][3],
                      baseB + (rB + g * 16) * 64 + chB);
#pragma unroll
            for (int mt = 0; mt < 2; mt++)
#pragma unroll
                for (int nt = 0; nt < 8; nt++)
                    mma16816(acc[mt][nt], a[mt],
                             b[nt >> 1][(nt & 1) * 2], b[nt >> 1][(nt & 1) * 2 + 1]);
        }
        __syncthreads();
    }

#pragma unroll
    for (int mt = 0; mt < 2; mt++) {
        const int mrow = m0 + wm + mt * 16 + (lane >> 2);
#pragma unroll
        for (int nt = 0; nt < 8; nt++) {
            const int ncol = n0 + wn + nt * 8 + 2 * (lane & 3);
            float* cc = acc[mt][nt];
            if (EPI == 0) {
                float2 v0 = make_float2(fmaxf(cc[0], 0.f), fmaxf(cc[1], 0.f));
                float2 v1 = make_float2(fmaxf(cc[2], 0.f), fmaxf(cc[3], 0.f));
                *(float2*)(out + (size_t)mrow * ldo + ncol) = v0;
                *(float2*)(out + (size_t)(mrow + 8) * ldo + ncol) = v1;
            } else {
                if (ncol < NCAT) {
                    float bv = bias[ncol];
                    out[(size_t)mrow * ldo + ncol] = cc[0] + bv;
                    out[(size_t)(mrow + 8) * ldo + ncol] = cc[2] + bv;
                }
                if (ncol + 1 < NCAT) {
                    float bv = bias[ncol + 1];
                    out[(size_t)mrow * ldo + ncol + 1] = cc[1] + bv;
                    out[(size_t)(mrow + 8) * ldo + ncol + 1] = cc[3] + bv;
                }
            }
        }
    }
}

// ==============================================================================
// Normalize rows of comb and scatter into g_nodes per original_pos.
// ==============================================================================
__global__ void __launch_bounds__(128) normalize_scatter_kernel(const int* __restrict__ opos)
{
    const int row = blockIdx.x;          // 0..16383
    const int b = row >> 6;
    const int dst = opos[(row << 1) + 0];
    const int src = opos[(row << 1) + 1];
    const int tid = threadIdx.x;

    const float4* cp = (const float4*)(g_comb + ((size_t)(b * SEQ + src)) * HID);
    float4 v = cp[tid];
    float ss = v.x*v.x + v.y*v.y + v.z*v.z + v.w*v.w;
#pragma unroll
    for (int o = 16; o; o >>= 1) ss += __shfl_xor_sync(0xffffffffu, ss, o);
    __shared__ float ws[4];
    if ((tid & 31) == 0) ws[tid >> 5] = ss;
    __syncthreads();
    float tot = ws[0] + ws[1] + ws[2] + ws[3];
    float sc = 1.f / (sqrtf(tot) + 1e-6f);
    float4 o4 = make_float4(v.x*sc, v.y*sc, v.z*sc, v.w*sc);
    ((float4*)(g_nodes + ((size_t)(b * MAXN + dst)) * HID))[tid] = o4;
}

// ==============================================================================
// rfft of the 64 leaf nodes per batch: 512-pt real FFT via packed complex 256.
// One block (128 thr) per (b, leaf). DIF forward, bit-reversed combine.
// ==============================================================================
__global__ void __launch_bounds__(128) rfft_leaves_kernel()
{
    const int idx = blockIdx.x;               // 0..16383
    const int b = idx >> 6, leaf = idx & 63;
    const int tid = threadIdx.x;
    __shared__ float2 sZ[256];
    __shared__ float2 stw[128];
    __shared__ float2 sw5[256];

    stw[tid] = g_twf[tid];
    sw5[tid] = g_w512f[tid];
    sw5[tid + 128] = g_w512f[tid + 128];

    const float2* xr = (const float2*)(g_nodes + ((size_t)(b * MAXN + leaf)) * HID);
    sZ[tid] = xr[tid];
    sZ[tid + 128] = xr[tid + 128];
    __syncthreads();

    // DIF radix-2, 8 stages: natural in -> bit-reversed out
#pragma unroll
    for (int s = 0; s < 8; s++) {
        const int half = 128 >> s;
        const int j = tid & (half - 1);
        const int g = tid >> (7 - s) >> 0;    // tid / half
        const int p0 = ((tid / half) << (8 - s) >> 0) * 0 + ( (tid / half) * (half * 2) + j );
        const int p1 = p0 + half;
        float2 w = stw[j << s];
        float2 u = sZ[p0], v = sZ[p1];
        sZ[p0] = make_float2(u.x + v.x, u.y + v.y);
        float dx = u.x - v.x, dy = u.y - v.y;
        sZ[p1] = make_float2(dx * w.x - dy * w.y, dx * w.y + dy * w.x);
        (void)g;
        __syncthreads();
    }

    // combine to rfft X[0..256], store to g_spec
    float* spec = g_spec + (size_t)(b * MAXN + leaf) * SPST;
#pragma unroll
    for (int h = 0; h < 2; h++) {
        int k = tid + h * 128;
        int kb = __brev((unsigned)k) >> 24;
        int km = __brev((unsigned)((256 - k) & 255)) >> 24;
        float2 Zk = sZ[kb], Zm = sZ[km];
        float er = 0.5f * (Zk.x + Zm.x);
        float ei = 0.5f * (Zk.y - Zm.y);
        float orr = 0.5f * (Zk.y + Zm.y);
        float oii = -0.5f * (Zk.x - Zm.x);
        float2 w = sw5[k];
        float2 X = make_float2(er + w.x * orr - w.y * oii,
                               ei + w.x * oii + w.y * orr);
        *(float2*)(spec + 2 * k) = X;
    }
    if (tid == 0)
        *(float2*)(spec + 512) = make_float2(sZ[0].x - sZ[0].y, 0.f);
}

// ==============================================================================
// Chain (spectral only): one block per batch, 63 sequential steps.
// C = conj(F_l)*G_r; Parseval norm; spec[p] = C/(||c||+eps). No time domain.
// ==============================================================================
__global__ void __launch_bounds__(128) chain_spec_kernel(const int* __restrict__ cinfo)
{
    const int b = blockIdx.x;
    const int tid = threadIdx.x;
    __shared__ float2 sF[257];
    __shared__ __align__(16) float2 sG[2][260];
    __shared__ float ws[4];
    __shared__ int sInfo[NSTEP * 4];

    for (int i = tid; i < NSTEP * 4; i += 128) sInfo[i] = cinfo[(size_t)b * NSTEP * 4 + i];
    __syncthreads();

    const size_t nbase = (size_t)b * MAXN;
    // init F from leaf l0
    {
        int l0 = sInfo[2];
        const float2* fr = (const float2*)(g_spec + (nbase + l0) * SPST);
        sF[tid] = fr[tid];
        sF[tid + 128] = fr[tid + 128];
        if (tid == 0) sF[256] = fr[256];
    }
    int prev_p = sInfo[2];

    // prefetch G for step 0
    {
        const float* src = g_spec + (nbase + sInfo[3]) * SPST;
        uint32_t dst = smem_u32(&sG[0][0]);
        cpasync16(dst + tid * 16, src + tid * 4);
        if (tid < 2) cpasync16(dst + (128 + tid) * 16, src + (128 + tid) * 4);
        asm volatile("cp.async.commit_group;" ::: "memory");
    }

    for (int k = 0; k < NSTEP; k++) {
        const int t = sInfo[k*4 + 0];
        const int p = sInfo[k*4 + 1];
        const int l = sInfo[k*4 + 2];
        const int r = sInfo[k*4 + 3];
        (void)r;
        const int cb = k & 1;

        bool issued = false;
        if (k + 1 < NSTEP) {
            const float* src = g_spec + (nbase + sInfo[(k+1)*4 + 3]) * SPST;
            uint32_t dst = smem_u32(&sG[cb ^ 1][0]);
            cpasync16(dst + tid * 16, src + tid * 4);
            if (tid < 2) cpasync16(dst + (128 + tid) * 16, src + (128 + tid) * 4);
            asm volatile("cp.async.commit_group;" ::: "memory");
            issued = true;
        }
        if (issued) asm volatile("cp.async.wait_group 1;" ::: "memory");
        else        asm volatile("cp.async.wait_group 0;" ::: "memory");
        __syncthreads();

        if (l != prev_p) {   // generic fallback (step 0 handled by preload)
            const float2* fr = (const float2*)(g_spec + (nbase + l) * SPST);
            sF[tid] = fr[tid];
            sF[tid + 128] = fr[tid + 128];
            if (tid == 0) sF[256] = fr[256];
        }

        float* specP = g_spec + (nbase + p) * SPST;

        if (t == 2) {
            float2 F0 = sF[tid],       G0 = sG[cb][tid];
            float2 F1 = sF[tid + 128], G1 = sG[cb][tid + 128];
            float2 c0 = make_float2(F0.x*G0.x + F0.y*G0.y, F0.x*G0.y - F0.y*G0.x);
            float2 c1 = make_float2(F1.x*G1.x + F1.y*G1.y, F1.x*G1.y - F1.y*G1.x);
            float w0 = (tid == 0) ? 1.f : 2.f;
            float part = w0 * (c0.x*c0.x + c0.y*c0.y) + 2.f * (c1.x*c1.x + c1.y*c1.y);
            float2 c2 = make_float2(0.f, 0.f);
            if (tid == 0) {
                float2 F2 = sF[256], G2 = sG[cb][256];
                c2 = make_float2(F2.x*G2.x + F2.y*G2.y, F2.x*G2.y - F2.y*G2.x);
                part += c2.x*c2.x + c2.y*c2.y;
            }
#pragma unroll
            for (int o = 16; o; o >>= 1) part += __shfl_xor_sync(0xffffffffu, part, o);
            if ((tid & 31) == 0) ws[tid >> 5] = part;
            __syncthreads();
            float tot = ws[0] + ws[1] + ws[2] + ws[3];
            float s = 1.f / (sqrtf(tot * (1.f / 512.f)) + 1e-6f);

            float2 f0 = make_float2(s * c0.x, s * c0.y);
            float2 f1 = make_float2(s * c1.x, s * c1.y);
            sF[tid] = f0; sF[tid + 128] = f1;
            *(float2*)(specP + 2 * tid) = f0;
            *(float2*)(specP + 2 * (tid + 128)) = f1;
            if (tid == 0) {
                float2 f2 = make_float2(s * c2.x, s * c2.y);
                sF[256] = f2;
                *(float2*)(specP + 512) = f2;
            }
        } else if (t == 1) {
            *(float2*)(specP + 2 * tid) = sF[tid];
            *(float2*)(specP + 2 * (tid + 128)) = sF[tid + 128];
            if (tid == 0) *(float2*)(specP + 512) = sF[256];
        } else {
            float2 z = make_float2(0.f, 0.f);
            sF[tid] = z; sF[tid + 128] = z;
            *(float2*)(specP + 2 * tid) = z;
            *(float2*)(specP + 2 * (tid + 128)) = z;
            if (tid == 0) { sF[256] = z; *(float2*)(specP + 512) = z; }
        }
        prev_p = p;
        __syncthreads();
    }
}

// ==============================================================================
// irfft of the 63 internal nodes per batch -> g_nodes. One block per (b, i).
// Inverse 512-pt real FFT via complex 256 DIT (bit-reversed in, natural out).
// ==============================================================================
__global__ void __launch_bounds__(128) irfft_nodes_kernel()
{
    const int idx = blockIdx.x;               // 0..16127
    const int b = idx / NSTEP, i = idx - b * NSTEP;
    const int node = 64 + i;
    const int tid = threadIdx.x;
    __shared__ float2 sX[257];
    __shared__ float2 sZ[256];
    __shared__ float2 stw[128];
    __shared__ float2 sw5[256];

    stw[tid] = g_twi[tid];
    sw5[tid] = g_w512i[tid];
    sw5[tid + 128] = g_w512i[tid + 128];

    const float2* sp = (const float2*)(g_spec + (size_t)(b * MAXN + node) * SPST);
    sX[tid] = sp[tid];
    sX[tid + 128] = sp[tid + 128];
    if (tid == 0) sX[256] = sp[256];
    __syncthreads();

    const float inv512 = 1.f / 512.f;
#pragma unroll
    for (int h = 0; h < 2; h++) {
        int k = tid + h * 128;
        float2 A = sX[k], B = sX[256 - k];
        float er = A.x + B.x;
        float ei = A.y - B.y;
        float dr = A.x - B.x;
        float di = A.y + B.y;
        float2 w = sw5[k];
        float qr = w.x * dr - w.y * di;
        float qi = w.x * di + w.y * dr;
        float2 Z = make_float2(inv512 * (er - qi), inv512 * (ei + qr));
        sZ[__brev((unsigned)k) >> 24] = Z;
    }
    __syncthreads();

    // DIT radix-2, 8 stages: bit-reversed in -> natural out
#pragma unroll
    for (int s = 0; s < 8; s++) {
        const int half = 1 << s;
        const int j = tid & (half - 1);
        const int p0 = ((tid >> s) << (s + 1)) | j;
        const int p1 = p0 + half;
        float2 w = stw[j << (7 - s)];
        float2 u = sZ[p0], v = sZ[p1];
        float tx = v.x * w.x - v.y * w.y;
        float ty = v.x * w.y + v.y * w.x;
        sZ[p0] = make_float2(u.x + tx, u.y + ty);
        sZ[p1] = make_float2(u.x - tx, u.y - ty);
        __syncthreads();
    }

    float2* xr = (float2*)(g_nodes + ((size_t)(b * MAXN + node)) * HID);
    xr[tid] = sZ[tid];                  // x[2n]=Re z, x[2n+1]=Im z
    xr[tid + 128] = sZ[tid + 128];
}

// ==============================================================================
extern "C" void kernel_launch(void* const* d_in, const int* in_sizes, int n_in,
                              void* d_out, int out_size)
{
    const float* seq  = (const float*)d_in[0];   // (256,64,1024)
    const float* W1   = (const float*)d_in[1];   // (512,512)
    const float* W2   = (const float*)d_in[2];   // (512,512)
    const float* LW   = (const float*)d_in[3];   // (511,512)
    const float* LB   = (const float*)d_in[4];   // (511,)
    const int*   opos = (const int*)d_in[7];     // (256,64,2)
    const int*   cinf = (const int*)d_in[8];     // (256,63,4)
    float* out = (float*)d_out;                  // (256,127,511)

    bf16 *ae1, *be1, *ae2, *be2; float *comb, *nodes;
    cudaGetSymbolAddress((void**)&ae1, g_ae1);
    cudaGetSymbolAddress((void**)&be1, g_be1);
    cudaGetSymbolAddress((void**)&ae2, g_ae2);
    cudaGetSymbolAddress((void**)&be2, g_be2);
    cudaGetSymbolAddress((void**)&comb, g_comb);
    cudaGetSymbolAddress((void**)&nodes, g_nodes);

    init_tables_kernel<<<1, 256>>>();

    // --- GEMM1: comb = relu(seq @ [W1;W2]);  M=16384, N=512, K'=3072 ---
    prep_b1_kernel<<<(HID * EMB) / 256, 256>>>(W1, W2);
    prep_a_kernel<<<(BSZ * SEQ * EMB) / 256, 256>>>(seq, ae1, EMB);
    {
        dim3 g(HID / BN, BSZ * SEQ / BM);
        mm_hmma_kernel<0><<<g, 256>>>(ae1, be1, nullptr, comb, 3 * EMB, HID);
    }

    normalize_scatter_kernel<<<BSZ * SEQ, 128>>>(opos);

    // --- spectral chain ---
    rfft_leaves_kernel<<<BSZ * SEQ, 128>>>();
    chain_spec_kernel<<<BSZ, 128>>>(cinf);
    irfft_nodes_kernel<<<BSZ * NSTEP, 128>>>();

    // --- GEMM2: out = nodes @ LW^T + LB;  M=32512, N=511(pad 512), K'=1536 ---
    prep_b2_kernel<<<(512 * HID) / 256, 256>>>(LW);
    prep_a_kernel<<<(BSZ * MAXN * HID) / 256, 256>>>(nodes, ae2, HID);
    {
        dim3 g(512 / BN, BSZ * MAXN / BM);
        mm_hmma_kernel<1><<<g, 256>>>(ae2, be2, LB, out, 3 * HID, NCAT);
    }
}

// round 6
// speedup vs baseline: 2.6312x; 1.2565x over previous
#include <cuda_runtime.h>
#include <cuda_bf16.h>
#include <cstdint>

// Problem constants (fixed by setup_inputs)
#define BSZ 256
#define SEQ 64
#define EMB 1024
#define HID 512
#define MAXN 127           // 2*S-1
#define NSTEP 63           // S-1
#define NCAT 511
#define SPST 520           // spec row stride (floats): 257 complex padded

typedef unsigned long long ull;
typedef __nv_bfloat16 bf16;

// ---------------- helpers ------------------------------------------------------
__device__ __forceinline__ uint32_t smem_u32(const void* p) {
    uint32_t a;
    asm("{ .reg .u64 t; cvta.to.shared.u64 t, %1; cvt.u32.u64 %0, t; }" : "=r"(a) : "l"(p));
    return a;
}
__device__ __forceinline__ void cpasync16(uint32_t dst, const void* src) {
    asm volatile("cp.async.cg.shared.global [%0], [%1], 16;" :: "r"(dst), "l"(src) : "memory");
}
__device__ __forceinline__ void ldsm4(uint32_t &d0, uint32_t &d1, uint32_t &d2, uint32_t &d3,
                                      uint32_t addr) {
    asm volatile("ldmatrix.sync.aligned.m8n8.x4.shared.b16 {%0,%1,%2,%3}, [%4];"
                 : "=r"(d0), "=r"(d1), "=r"(d2), "=r"(d3) : "r"(addr));
}
__device__ __forceinline__ void mma16816(float* c, const uint32_t* a, uint32_t b0, uint32_t b1) {
    asm volatile("mma.sync.aligned.m16n8k16.row.col.f32.bf16.bf16.f32 "
                 "{%0,%1,%2,%3}, {%4,%5,%6,%7}, {%8,%9}, {%0,%1,%2,%3};"
                 : "+f"(c[0]), "+f"(c[1]), "+f"(c[2]), "+f"(c[3])
                 : "r"(a[0]), "r"(a[1]), "r"(a[2]), "r"(a[3]), "r"(b0), "r"(b1));
}
__device__ __forceinline__ void sts128(uint32_t addr, uint4 v) {
    asm volatile("st.shared.v4.b32 [%0], {%1,%2,%3,%4};"
                 :: "r"(addr), "r"(v.x), "r"(v.y), "r"(v.z), "r"(v.w) : "memory");
}
__device__ __forceinline__ uint32_t bf2hi(float a, float b) {
    __nv_bfloat162 t = __float22bfloat162_rn(make_float2(a, b));
    return *(uint32_t*)&t;
}
// split 8 floats into hi/lo bf16x2 quads
__device__ __forceinline__ void split8(float4 u, float4 v, uint4 &hi, uint4 &lo) {
    hi.x = bf2hi(u.x, u.y); hi.y = bf2hi(u.z, u.w);
    hi.z = bf2hi(v.x, v.y); hi.w = bf2hi(v.z, v.w);
    __nv_bfloat162 h;
    h = *(__nv_bfloat162*)&hi.x; float2 f0 = __bfloat1622float2(h);
    h = *(__nv_bfloat162*)&hi.y; float2 f1 = __bfloat1622float2(h);
    h = *(__nv_bfloat162*)&hi.z; float2 f2 = __bfloat1622float2(h);
    h = *(__nv_bfloat162*)&hi.w; float2 f3 = __bfloat1622float2(h);
    lo.x = bf2hi(u.x - f0.x, u.y - f0.y);
    lo.y = bf2hi(u.z - f1.x, u.w - f1.y);
    lo.z = bf2hi(v.x - f2.x, v.y - f2.y);
    lo.w = bf2hi(v.z - f3.x, v.w - f3.y);
}

// ---------------- scratch (device globals: allocation-free) -------------------
__device__ float g_comb[(size_t)BSZ * SEQ * HID];                 // relu(GEMM1) fp32
__device__ __align__(16) float g_spec[(size_t)BSZ * MAXN * SPST]; // node spectra
__device__ bf16 g_a2h[(size_t)BSZ * MAXN * HID];                  // GEMM2 A hi
__device__ bf16 g_a2l[(size_t)BSZ * MAXN * HID];                  // GEMM2 A lo
__device__ bf16 g_b1h[(size_t)HID * EMB], g_b1l[(size_t)HID * EMB];   // W^T hi/lo
__device__ bf16 g_b2h[(size_t)512 * HID], g_b2l[(size_t)512 * HID];   // LW hi/lo (pad)
__device__ float2 g_twf[128], g_twi[128], g_w512f[256], g_w512i[256];

// ==============================================================================
__global__ void init_tables_kernel()
{
    int t = threadIdx.x;
    const float PI2 = 6.283185307179586f;
    if (t < 128) {
        float th = PI2 * t / 256.0f;
        float s, c; sincosf(th, &s, &c);
        g_twf[t] = make_float2(c, -s);
        g_twi[t] = make_float2(c,  s);
    }
    float ph = PI2 * t / 512.0f;
    float s, c; sincosf(ph, &s, &c);
    g_w512f[t] = make_float2(c, -s);
    g_w512i[t] = make_float2(c,  s);
}

__global__ void prep_b1_kernel(const float* __restrict__ W1, const float* __restrict__ W2)
{
    int id = blockIdx.x * 256 + threadIdx.x;              // over 512*1024
    int n = id >> 10, k = id & 1023;
    float v = (k < HID) ? W1[(size_t)k * HID + n] : W2[(size_t)(k - HID) * HID + n];
    bf16 h = __float2bfloat16(v);
    g_b1h[id] = h;
    g_b1l[id] = __float2bfloat16(v - __bfloat162float(h));
}

__global__ void prep_b2_kernel(const float* __restrict__ LW)
{
    int id = blockIdx.x * 256 + threadIdx.x;              // over 512*512
    int n = id >> 9, k = id & 511;
    float v = (n < NCAT) ? LW[(size_t)n * HID + k] : 0.f;
    bf16 h = __float2bfloat16(v);
    g_b2h[id] = h;
    g_b2l[id] = __float2bfloat16(v - __bfloat162float(h));
}

// ==============================================================================
// HMMA GEMM with fused fp32->bf16 hi/lo split (AMODE=0) or pre-split A (AMODE=1).
// D = A@B^T as ah*bh + al*bh + ah*bl, 3 MMA passes per base K-chunk of 32.
// Block 128x128, 8 warps (4m x 2n), 2-stage dynamic smem (32KB/stage).
// EPI=0: relu -> out(ld=512).  EPI=1: +bias, n<NCAT guard.
// Stage layout: Ah@0, Al@8K, Bh@16K, Bl@24K; rows 64B, 16B-chunk XOR swizzle.
// ==============================================================================
#define BM 128
#define BN 128
#define STG 32768

template<int AMODE, int EPI>
__global__ void __launch_bounds__(256, 2) mm_hmma2_kernel(
    const float* __restrict__ Af, const bf16* __restrict__ Ah, const bf16* __restrict__ Al,
    const bf16* __restrict__ Bh, const bf16* __restrict__ Bl,
    const float* __restrict__ bias, float* __restrict__ out, int K, int ldo)
{
    extern __shared__ __align__(16) char smem[];
    const uint32_t sb = smem_u32(smem);

    const int tid  = threadIdx.x;
    const int lane = tid & 31;
    const int wid  = tid >> 5;
    const int wm   = (wid & 3) * 32;
    const int wn   = (wid >> 2) * 64;
    const int n0   = blockIdx.x * BN;
    const int m0   = blockIdx.y * BM;

    float acc[2][8][4];
#pragma unroll
    for (int mt = 0; mt < 2; mt++)
#pragma unroll
        for (int nt = 0; nt < 8; nt++)
#pragma unroll
            for (int i = 0; i < 4; i++) acc[mt][nt][i] = 0.f;

    // loader constants
    const int brow = tid >> 2, bc = tid & 3;                  // B/A-async: 2 chunks each
    const int brow2 = (tid + 256) >> 2, bc2 = (tid + 256) & 3;
    const uint32_t bsw1 = brow * 64 + ((bc ^ ((brow >> 1) & 3)) << 4);
    const uint32_t bsw2 = brow2 * 64 + ((bc2 ^ ((brow2 >> 1) & 3)) << 4);
    const int arow = tid >> 1, ahalf = tid & 1;               // AMODE0 ldg
    const uint32_t asw0 = arow * 64 + (((ahalf * 2 + 0) ^ ((arow >> 1) & 3)) << 4);
    const uint32_t asw1 = arow * 64 + (((ahalf * 2 + 1) ^ ((arow >> 1) & 3)) << 4);

    auto loadB = [&](int kt, uint32_t st) {
        cpasync16(st + 16384 + bsw1, Bh + (size_t)(n0 + brow) * K + kt + bc * 8);
        cpasync16(st + 24576 + bsw1, Bl + (size_t)(n0 + brow) * K + kt + bc * 8);
        cpasync16(st + 16384 + bsw2, Bh + (size_t)(n0 + brow2) * K + kt + bc2 * 8);
        cpasync16(st + 24576 + bsw2, Bl + (size_t)(n0 + brow2) * K + kt + bc2 * 8);
    };
    auto loadAasync = [&](int kt, uint32_t st) {
        cpasync16(st + 0    + bsw1, Ah + (size_t)(m0 + brow) * K + kt + bc * 8);
        cpasync16(st + 8192 + bsw1, Al + (size_t)(m0 + brow) * K + kt + bc * 8);
        cpasync16(st + 0    + bsw2, Ah + (size_t)(m0 + brow2) * K + kt + bc2 * 8);
        cpasync16(st + 8192 + bsw2, Al + (size_t)(m0 + brow2) * K + kt + bc2 * 8);
    };

    float4 pr[4];
    auto ldgA = [&](int kt) {
        const float4* src = (const float4*)(Af + (size_t)(m0 + arow) * K + kt + ahalf * 16);
        pr[0] = src[0]; pr[1] = src[1]; pr[2] = src[2]; pr[3] = src[3];
    };
    auto cvtsts = [&](uint32_t st) {
        uint4 hi, lo;
        split8(pr[0], pr[1], hi, lo);
        sts128(st + 0 + asw0, hi);
        sts128(st + 8192 + asw0, lo);
        split8(pr[2], pr[3], hi, lo);
        sts128(st + 0 + asw1, hi);
        sts128(st + 8192 + asw1, lo);
    };

    // prologue: fill stage 0
    loadB(0, sb);
    if (AMODE == 1) loadAasync(0, sb);
    asm volatile("cp.async.commit_group;" ::: "memory");
    if (AMODE == 0) { ldgA(0); cvtsts(sb); }
    asm volatile("cp.async.wait_group 0;" ::: "memory");
    __syncthreads();

    // ldmatrix constants
    const int rA  = wm + (lane & 15);
    const int hA  = lane >> 4;
    const int sAx = (rA >> 1) & 3;
    const int rB  = wn + (lane & 7) + ((lane >> 4) << 3);
    const int hB  = (lane >> 3) & 1;
    const int sBx = (rB >> 1) & 3;

    const int C = K / 32;
    for (int c = 0; c < C; c++) {
        const uint32_t st  = sb + (c & 1) * STG;
        const uint32_t nx  = sb + ((c + 1) & 1) * STG;
        if (c + 1 < C) {
            loadB((c + 1) * 32, nx);
            if (AMODE == 1) loadAasync((c + 1) * 32, nx);
            asm volatile("cp.async.commit_group;" ::: "memory");
            if (AMODE == 0) ldgA((c + 1) * 32);
        }

#pragma unroll
        for (int ks = 0; ks < 2; ks++) {
            const int chA = ((ks * 2 + hA) ^ sAx) << 4;
            const int chB = ((ks * 2 + hB) ^ sBx) << 4;
            uint32_t ah[2][4], al[2][4], bh[4][4], bl[4][4];
#pragma unroll
            for (int mt = 0; mt < 2; mt++)
                ldsm4(ah[mt][0], ah[mt][1], ah[mt][2], ah[mt][3],
                      st + 0 + (rA + mt * 16) * 64 + chA);
#pragma unroll
            for (int g = 0; g < 4; g++)
                ldsm4(bh[g][0], bh[g][1], bh[g][2], bh[g][3],
                      st + 16384 + (rB + g * 16) * 64 + chB);
#pragma unroll
            for (int mt = 0; mt < 2; mt++)
#pragma unroll
                for (int nt = 0; nt < 8; nt++)
                    mma16816(acc[mt][nt], ah[mt],
                             bh[nt >> 1][(nt & 1) * 2], bh[nt >> 1][(nt & 1) * 2 + 1]);
#pragma unroll
            for (int mt = 0; mt < 2; mt++)
                ldsm4(al[mt][0], al[mt][1], al[mt][2], al[mt][3],
                      st + 8192 + (rA + mt * 16) * 64 + chA);
#pragma unroll
            for (int mt = 0; mt < 2; mt++)
#pragma unroll
                for (int nt = 0; nt < 8; nt++)
                    mma16816(acc[mt][nt], al[mt],
                             bh[nt >> 1][(nt & 1) * 2], bh[nt >> 1][(nt & 1) * 2 + 1]);
#pragma unroll
            for (int g = 0; g < 4; g++)
                ldsm4(bl[g][0], bl[g][1], bl[g][2], bl[g][3],
                      st + 24576 + (rB + g * 16) * 64 + chB);
#pragma unroll
            for (int mt = 0; mt < 2; mt++)
#pragma unroll
                for (int nt = 0; nt < 8; nt++)
                    mma16816(acc[mt][nt], ah[mt],
                             bl[nt >> 1][(nt & 1) * 2], bl[nt >> 1][(nt & 1) * 2 + 1]);
        }
        __syncthreads();
        if (c + 1 < C) {
            if (AMODE == 0) cvtsts(nx);
            asm volatile("cp.async.wait_group 0;" ::: "memory");
            __syncthreads();
        }
    }

    // epilogue
#pragma unroll
    for (int mt = 0; mt < 2; mt++) {
        const int mrow = m0 + wm + mt * 16 + (lane >> 2);
#pragma unroll
        for (int nt = 0; nt < 8; nt++) {
            const int ncol = n0 + wn + nt * 8 + 2 * (lane & 3);
            float* cc = acc[mt][nt];
            if (EPI == 0) {
                float2 v0 = make_float2(fmaxf(cc[0], 0.f), fmaxf(cc[1], 0.f));
                float2 v1 = make_float2(fmaxf(cc[2], 0.f), fmaxf(cc[3], 0.f));
                *(float2*)(out + (size_t)mrow * ldo + ncol) = v0;
                *(float2*)(out + (size_t)(mrow + 8) * ldo + ncol) = v1;
            } else {
                if (ncol < NCAT) {
                    float bv = bias[ncol];
                    out[(size_t)mrow * ldo + ncol] = cc[0] + bv;
                    out[(size_t)(mrow + 8) * ldo + ncol] = cc[2] + bv;
                }
                if (ncol + 1 < NCAT) {
                    float bv = bias[ncol + 1];
                    out[(size_t)mrow * ldo + ncol + 1] = cc[1] + bv;
                    out[(size_t)(mrow + 8) * ldo + ncol + 1] = cc[3] + bv;
                }
            }
        }
    }
}

// ==============================================================================
// Leaf kernel: normalize comb row, emit GEMM2 A bf16 hi/lo row, rfft -> g_spec.
// One block (128 thr) per (b,s).
// ==============================================================================
__global__ void __launch_bounds__(128) leaf_kernel(const int* __restrict__ opos)
{
    const int row = blockIdx.x;          // 0..16383
    const int b = row >> 6;
    const int dst = opos[(row << 1) + 0];
    const int src = opos[(row << 1) + 1];
    const int tid = threadIdx.x;

    __shared__ float2 sZ[256];
    __shared__ float2 stw[128];
    __shared__ float2 sw5[256];
    __shared__ float ws[4];

    stw[tid] = g_twf[tid];
    sw5[tid] = g_w512f[tid];
    sw5[tid + 128] = g_w512f[tid + 128];

    const float4* cp = (const float4*)(g_comb + ((size_t)(b * SEQ + src)) * HID);
    float4 v = cp[tid];
    float ss = v.x*v.x + v.y*v.y + v.z*v.z + v.w*v.w;
#pragma unroll
    for (int o = 16; o; o >>= 1) ss += __shfl_xor_sync(0xffffffffu, ss, o);
    if ((tid & 31) == 0) ws[tid >> 5] = ss;
    __syncthreads();
    float sc = 1.f / (sqrtf(ws[0] + ws[1] + ws[2] + ws[3]) + 1e-6f);
    v = make_float4(v.x*sc, v.y*sc, v.z*sc, v.w*sc);

    // emit GEMM2 A row (bf16 hi/lo)
    const size_t nrow = (size_t)(b * MAXN + dst);
    {
        uint32_t* rh = (uint32_t*)(g_a2h + nrow * HID);
        uint32_t* rl = (uint32_t*)(g_a2l + nrow * HID);
        uint32_t h0 = bf2hi(v.x, v.y), h1 = bf2hi(v.z, v.w);
        __nv_bfloat162 t;
        t = *(__nv_bfloat162*)&h0; float2 f0 = __bfloat1622float2(t);
        t = *(__nv_bfloat162*)&h1; float2 f1 = __bfloat1622float2(t);
        rh[2*tid] = h0; rh[2*tid+1] = h1;
        rl[2*tid]   = bf2hi(v.x - f0.x, v.y - f0.y);
        rl[2*tid+1] = bf2hi(v.z - f1.x, v.w - f1.y);
    }

    // pack into complex z[n] = x[2n] + i x[2n+1]
    sZ[2*tid]     = make_float2(v.x, v.y);
    sZ[2*tid + 1] = make_float2(v.z, v.w);
    __syncthreads();

    // DIF radix-2, 8 stages (natural -> bit-reversed)
#pragma unroll
    for (int s = 0; s < 8; s++) {
        const int half = 128 >> s;
        const int j = tid & (half - 1);
        const int p0 = (tid / half) * (half * 2) + j;
        const int p1 = p0 + half;
        float2 w = stw[j << s];
        float2 u = sZ[p0], vv = sZ[p1];
        sZ[p0] = make_float2(u.x + vv.x, u.y + vv.y);
        float dx = u.x - vv.x, dy = u.y - vv.y;
        sZ[p1] = make_float2(dx * w.x - dy * w.y, dx * w.y + dy * w.x);
        __syncthreads();
    }

    float* spec = g_spec + nrow * SPST;
#pragma unroll
    for (int h = 0; h < 2; h++) {
        int k = tid + h * 128;
        int kb = __brev((unsigned)k) >> 24;
        int km = __brev((unsigned)((256 - k) & 255)) >> 24;
        float2 Zk = sZ[kb], Zm = sZ[km];
        float er = 0.5f * (Zk.x + Zm.x);
        float ei = 0.5f * (Zk.y - Zm.y);
        float orr = 0.5f * (Zk.y + Zm.y);
        float oii = -0.5f * (Zk.x - Zm.x);
        float2 w = sw5[k];
        float2 X = make_float2(er + w.x * orr - w.y * oii,
                               ei + w.x * oii + w.y * orr);
        *(float2*)(spec + 2 * k) = X;
    }
    if (tid == 0)
        *(float2*)(spec + 512) = make_float2(sZ[0].x - sZ[0].y, 0.f);
}

// ==============================================================================
// Chain (spectral): one block per batch, 63 sequential steps. Unchanged (R4).
// ==============================================================================
__global__ void __launch_bounds__(128) chain_spec_kernel(const int* __restrict__ cinfo)
{
    const int b = blockIdx.x;
    const int tid = threadIdx.x;
    __shared__ float2 sF[257];
    __shared__ __align__(16) float2 sG[2][260];
    __shared__ float ws[4];
    __shared__ int sInfo[NSTEP * 4];

    for (int i = tid; i < NSTEP * 4; i += 128) sInfo[i] = cinfo[(size_t)b * NSTEP * 4 + i];
    __syncthreads();

    const size_t nbase = (size_t)b * MAXN;
    {
        int l0 = sInfo[2];
        const float2* fr = (const float2*)(g_spec + (nbase + l0) * SPST);
        sF[tid] = fr[tid];
        sF[tid + 128] = fr[tid + 128];
        if (tid == 0) sF[256] = fr[256];
    }
    int prev_p = sInfo[2];

    {
        const float* src = g_spec + (nbase + sInfo[3]) * SPST;
        uint32_t dst = smem_u32(&sG[0][0]);
        cpasync16(dst + tid * 16, src + tid * 4);
        if (tid < 2) cpasync16(dst + (128 + tid) * 16, src + (128 + tid) * 4);
        asm volatile("cp.async.commit_group;" ::: "memory");
    }

    for (int k = 0; k < NSTEP; k++) {
        const int t = sInfo[k*4 + 0];
        const int p = sInfo[k*4 + 1];
        const int l = sInfo[k*4 + 2];
        const int cb = k & 1;

        bool issued = false;
        if (k + 1 < NSTEP) {
            const float* src = g_spec + (nbase + sInfo[(k+1)*4 + 3]) * SPST;
            uint32_t dst = smem_u32(&sG[cb ^ 1][0]);
            cpasync16(dst + tid * 16, src + tid * 4);
            if (tid < 2) cpasync16(dst + (128 + tid) * 16, src + (128 + tid) * 4);
            asm volatile("cp.async.commit_group;" ::: "memory");
            issued = true;
        }
        if (issued) asm volatile("cp.async.wait_group 1;" ::: "memory");
        else        asm volatile("cp.async.wait_group 0;" ::: "memory");
        __syncthreads();

        if (l != prev_p) {
            const float2* fr = (const float2*)(g_spec + (nbase + l) * SPST);
            sF[tid] = fr[tid];
            sF[tid + 128] = fr[tid + 128];
            if (tid == 0) sF[256] = fr[256];
        }

        float* specP = g_spec + (nbase + p) * SPST;

        if (t == 2) {
            float2 F0 = sF[tid],       G0 = sG[cb][tid];
            float2 F1 = sF[tid + 128], G1 = sG[cb][tid + 128];
            float2 c0 = make_float2(F0.x*G0.x + F0.y*G0.y, F0.x*G0.y - F0.y*G0.x);
            float2 c1 = make_float2(F1.x*G1.x + F1.y*G1.y, F1.x*G1.y - F1.y*G1.x);
            float w0 = (tid == 0) ? 1.f : 2.f;
            float part = w0 * (c0.x*c0.x + c0.y*c0.y) + 2.f * (c1.x*c1.x + c1.y*c1.y);
            float2 c2 = make_float2(0.f, 0.f);
            if (tid == 0) {
                float2 F2 = sF[256], G2 = sG[cb][256];
                c2 = make_float2(F2.x*G2.x + F2.y*G2.y, F2.x*G2.y - F2.y*G2.x);
                part += c2.x*c2.x + c2.y*c2.y;
            }
#pragma unroll
            for (int o = 16; o; o >>= 1) part += __shfl_xor_sync(0xffffffffu, part, o);
            if ((tid & 31) == 0) ws[tid >> 5] = part;
            __syncthreads();
            float tot = ws[0] + ws[1] + ws[2] + ws[3];
            float s = 1.f / (sqrtf(tot * (1.f / 512.f)) + 1e-6f);

            float2 f0 = make_float2(s * c0.x, s * c0.y);
            float2 f1 = make_float2(s * c1.x, s * c1.y);
            sF[tid] = f0; sF[tid + 128] = f1;
            *(float2*)(specP + 2 * tid) = f0;
            *(float2*)(specP + 2 * (tid + 128)) = f1;
            if (tid == 0) {
                float2 f2 = make_float2(s * c2.x, s * c2.y);
                sF[256] = f2;
                *(float2*)(specP + 512) = f2;
            }
        } else if (t == 1) {
            *(float2*)(specP + 2 * tid) = sF[tid];
            *(float2*)(specP + 2 * (tid + 128)) = sF[tid + 128];
            if (tid == 0) *(float2*)(specP + 512) = sF[256];
        } else {
            float2 z = make_float2(0.f, 0.f);
            sF[tid] = z; sF[tid + 128] = z;
            *(float2*)(specP + 2 * tid) = z;
            *(float2*)(specP + 2 * (tid + 128)) = z;
            if (tid == 0) { sF[256] = z; *(float2*)(specP + 512) = z; }
        }
        prev_p = p;
        __syncthreads();
    }
}

// ==============================================================================
// irfft of the 63 internal nodes per batch -> GEMM2 A bf16 hi/lo rows.
// ==============================================================================
__global__ void __launch_bounds__(128) irfft_nodes_kernel()
{
    const int idx = blockIdx.x;               // 0..16127
    const int b = idx / NSTEP, i = idx - b * NSTEP;
    const int node = 64 + i;
    const int tid = threadIdx.x;
    __shared__ float2 sX[257];
    __shared__ float2 sZ[256];
    __shared__ float2 stw[128];
    __shared__ float2 sw5[256];

    stw[tid] = g_twi[tid];
    sw5[tid] = g_w512i[tid];
    sw5[tid + 128] = g_w512i[tid + 128];

    const size_t nrow = (size_t)(b * MAXN + node);
    const float2* sp = (const float2*)(g_spec + nrow * SPST);
    sX[tid] = sp[tid];
    sX[tid + 128] = sp[tid + 128];
    if (tid == 0) sX[256] = sp[256];
    __syncthreads();

    const float inv512 = 1.f / 512.f;
#pragma unroll
    for (int h = 0; h < 2; h++) {
        int k = tid + h * 128;
        float2 A = sX[k], B = sX[256 - k];
        float er = A.x + B.x;
        float ei = A.y - B.y;
        float dr = A.x - B.x;
        float di = A.y + B.y;
        float2 w = sw5[k];
        float qr = w.x * dr - w.y * di;
        float qi = w.x * di + w.y * dr;
        float2 Z = make_float2(inv512 * (er - qi), inv512 * (ei + qr));
        sZ[__brev((unsigned)k) >> 24] = Z;
    }
    __syncthreads();

#pragma unroll
    for (int s = 0; s < 8; s++) {
        const int half = 1 << s;
        const int j = tid & (half - 1);
        const int p0 = ((tid >> s) << (s + 1)) | j;
        const int p1 = p0 + half;
        float2 w = stw[j << (7 - s)];
        float2 u = sZ[p0], v = sZ[p1];
        float tx = v.x * w.x - v.y * w.y;
        float ty = v.x * w.y + v.y * w.x;
        sZ[p0] = make_float2(u.x + tx, u.y + ty);
        sZ[p1] = make_float2(u.x - tx, u.y - ty);
        __syncthreads();
    }

    uint32_t* rh = (uint32_t*)(g_a2h + nrow * HID);
    uint32_t* rl = (uint32_t*)(g_a2l + nrow * HID);
#pragma unroll
    for (int h = 0; h < 2; h++) {
        int k = tid + h * 128;
        float2 z = sZ[k];                   // x[2k] = z.x, x[2k+1] = z.y
        uint32_t hv = bf2hi(z.x, z.y);
        __nv_bfloat162 t = *(__nv_bfloat162*)&hv;
        float2 f = __bfloat1622float2(t);
        rh[k] = hv;
        rl[k] = bf2hi(z.x - f.x, z.y - f.y);
    }
}

// ==============================================================================
extern "C" void kernel_launch(void* const* d_in, const int* in_sizes, int n_in,
                              void* d_out, int out_size)
{
    const float* seq  = (const float*)d_in[0];   // (256,64,1024)
    const float* W1   = (const float*)d_in[1];   // (512,512)
    const float* W2   = (const float*)d_in[2];   // (512,512)
    const float* LW   = (const float*)d_in[3];   // (511,512)
    const float* LB   = (const float*)d_in[4];   // (511,)
    const int*   opos = (const int*)d_in[7];     // (256,64,2)
    const int*   cinf = (const int*)d_in[8];     // (256,63,4)
    float* out = (float*)d_out;                  // (256,127,511)

    float* comb; bf16 *a2h, *a2l, *b1h, *b1l, *b2h, *b2l;
    cudaGetSymbolAddress((void**)&comb, g_comb);
    cudaGetSymbolAddress((void**)&a2h, g_a2h);
    cudaGetSymbolAddress((void**)&a2l, g_a2l);
    cudaGetSymbolAddress((void**)&b1h, g_b1h);
    cudaGetSymbolAddress((void**)&b1l, g_b1l);
    cudaGetSymbolAddress((void**)&b2h, g_b2h);
    cudaGetSymbolAddress((void**)&b2l, g_b2l);

    cudaFuncSetAttribute(mm_hmma2_kernel<0, 0>,
                         cudaFuncAttributeMaxDynamicSharedMemorySize, 2 * STG);
    cudaFuncSetAttribute(mm_hmma2_kernel<1, 1>,
                         cudaFuncAttributeMaxDynamicSharedMemorySize, 2 * STG);

    init_tables_kernel<<<1, 256>>>();
    prep_b1_kernel<<<(HID * EMB) / 256, 256>>>(W1, W2);
    prep_b2_kernel<<<(512 * HID) / 256, 256>>>(LW);

    // GEMM1: comb = relu(seq @ [W1;W2]); fused fp32->bf16 split in loader
    {
        dim3 g(HID / BN, BSZ * SEQ / BM);         // (4, 128)
        mm_hmma2_kernel<0, 0><<<g, 256, 2 * STG>>>(
            seq, nullptr, nullptr, b1h, b1l, nullptr, comb, EMB, HID);
    }

    leaf_kernel<<<BSZ * SEQ, 128>>>(opos);
    chain_spec_kernel<<<BSZ, 128>>>(cinf);
    irfft_nodes_kernel<<<BSZ * NSTEP, 128>>>();

    // GEMM2: out = nodes @ LW^T + LB; pre-split bf16 A
    {
        dim3 g(512 / BN, BSZ * MAXN / BM);        // (4, 254)
        mm_hmma2_kernel<1, 1><<<g, 256, 2 * STG>>>(
            nullptr, a2h, a2l, b2h, b2l, LB, out, HID, NCAT);
    }
}

// round 7
// speedup vs baseline: 2.6596x; 1.0108x over previous
#include <cuda_runtime.h>
#include <cuda_bf16.h>
#include <cstdint>

// Problem constants (fixed by setup_inputs)
#define BSZ 256
#define SEQ 64
#define EMB 1024
#define HID 512
#define MAXN 127           // 2*S-1
#define NSTEP 63           // S-1
#define NCAT 511
#define SPST 520           // spec row stride (floats): 257 complex padded

typedef unsigned long long ull;
typedef __nv_bfloat16 bf16;

// ---------------- helpers ------------------------------------------------------
__device__ __forceinline__ uint32_t smem_u32(const void* p) {
    uint32_t a;
    asm("{ .reg .u64 t; cvta.to.shared.u64 t, %1; cvt.u32.u64 %0, t; }" : "=r"(a) : "l"(p));
    return a;
}
__device__ __forceinline__ void cpasync16(uint32_t dst, const void* src) {
    asm volatile("cp.async.cg.shared.global [%0], [%1], 16;" :: "r"(dst), "l"(src) : "memory");
}
__device__ __forceinline__ void ldsm4(uint32_t &d0, uint32_t &d1, uint32_t &d2, uint32_t &d3,
                                      uint32_t addr) {
    asm volatile("ldmatrix.sync.aligned.m8n8.x4.shared.b16 {%0,%1,%2,%3}, [%4];"
                 : "=r"(d0), "=r"(d1), "=r"(d2), "=r"(d3) : "r"(addr));
}
__device__ __forceinline__ void mma16816(float* c, const uint32_t* a, uint32_t b0, uint32_t b1) {
    asm volatile("mma.sync.aligned.m16n8k16.row.col.f32.bf16.bf16.f32 "
                 "{%0,%1,%2,%3}, {%4,%5,%6,%7}, {%8,%9}, {%0,%1,%2,%3};"
                 : "+f"(c[0]), "+f"(c[1]), "+f"(c[2]), "+f"(c[3])
                 : "r"(a[0]), "r"(a[1]), "r"(a[2]), "r"(a[3]), "r"(b0), "r"(b1));
}
__device__ __forceinline__ void sts128(uint32_t addr, uint4 v) {
    asm volatile("st.shared.v4.b32 [%0], {%1,%2,%3,%4};"
                 :: "r"(addr), "r"(v.x), "r"(v.y), "r"(v.z), "r"(v.w) : "memory");
}
__device__ __forceinline__ uint32_t bf2hi(float a, float b) {
    __nv_bfloat162 t = __float22bfloat162_rn(make_float2(a, b));
    return *(uint32_t*)&t;
}
__device__ __forceinline__ void split8(float4 u, float4 v, uint4 &hi, uint4 &lo) {
    hi.x = bf2hi(u.x, u.y); hi.y = bf2hi(u.z, u.w);
    hi.z = bf2hi(v.x, v.y); hi.w = bf2hi(v.z, v.w);
    __nv_bfloat162 h;
    h = *(__nv_bfloat162*)&hi.x; float2 f0 = __bfloat1622float2(h);
    h = *(__nv_bfloat162*)&hi.y; float2 f1 = __bfloat1622float2(h);
    h = *(__nv_bfloat162*)&hi.z; float2 f2 = __bfloat1622float2(h);
    h = *(__nv_bfloat162*)&hi.w; float2 f3 = __bfloat1622float2(h);
    lo.x = bf2hi(u.x - f0.x, u.y - f0.y);
    lo.y = bf2hi(u.z - f1.x, u.w - f1.y);
    lo.z = bf2hi(v.x - f2.x, v.y - f2.y);
    lo.w = bf2hi(v.z - f3.x, v.w - f3.y);
}

// ---------------- scratch (device globals: allocation-free) -------------------
__device__ float g_comb[(size_t)BSZ * SEQ * HID];                 // relu(GEMM1) fp32
__device__ __align__(16) float g_spec[(size_t)BSZ * MAXN * SPST]; // node spectra
__device__ bf16 g_a2h[(size_t)BSZ * MAXN * HID];                  // GEMM2 A hi
__device__ bf16 g_a2l[(size_t)BSZ * MAXN * HID];                  // GEMM2 A lo
__device__ bf16 g_b1h[(size_t)HID * EMB], g_b1l[(size_t)HID * EMB];   // W^T hi/lo
__device__ bf16 g_b2h[(size_t)512 * HID], g_b2l[(size_t)512 * HID];   // LW hi/lo (pad)
__device__ float2 g_twf[128], g_twi[128], g_w512f[256], g_w512i[256];

// ==============================================================================
__global__ void init_tables_kernel()
{
    int t = threadIdx.x;
    const float PI2 = 6.283185307179586f;
    if (t < 128) {
        float th = PI2 * t / 256.0f;
        float s, c; sincosf(th, &s, &c);
        g_twf[t] = make_float2(c, -s);
        g_twi[t] = make_float2(c,  s);
    }
    float ph = PI2 * t / 512.0f;
    float s, c; sincosf(ph, &s, &c);
    g_w512f[t] = make_float2(c, -s);
    g_w512i[t] = make_float2(c,  s);
}

// coalesced tiled transpose+split: W1/W2 [k][n] -> g_b1{h,l}[n][k']
__global__ void prep_b1_kernel(const float* __restrict__ W1, const float* __restrict__ W2)
{
    __shared__ float tile[32][33];
    const int kp0 = blockIdx.x * 32, n0 = blockIdx.y * 32;
    const int tx = threadIdx.x, ty = threadIdx.y;   // 32 x 8
#pragma unroll
    for (int i = 0; i < 32; i += 8) {
        int kp = kp0 + ty + i;
        const float* W = (kp < HID) ? (W1 + (size_t)kp * HID) : (W2 + (size_t)(kp - HID) * HID);
        tile[ty + i][tx] = W[n0 + tx];
    }
    __syncthreads();
#pragma unroll
    for (int i = 0; i < 32; i += 8) {
        int n = n0 + ty + i;
        float v = tile[tx][ty + i];
        bf16 h = __float2bfloat16(v);
        size_t o = (size_t)n * EMB + kp0 + tx;
        g_b1h[o] = h;
        g_b1l[o] = __float2bfloat16(v - __bfloat162float(h));
    }
}

__global__ void prep_b2_kernel(const float* __restrict__ LW)
{
    int id = blockIdx.x * 256 + threadIdx.x;              // over 512*512
    int n = id >> 9, k = id & 511;
    float v = (n < NCAT) ? LW[(size_t)n * HID + k] : 0.f;
    bf16 h = __float2bfloat16(v);
    g_b2h[id] = h;
    g_b2l[id] = __float2bfloat16(v - __bfloat162float(h));
}

// ==============================================================================
// HMMA GEMM, 3-stage cp.async ring, ONE __syncthreads per K-chunk.
// D = ah*bh + al*bh + ah*bl (3 MMA passes, shared fragments).
// AMODE=0: A fp32, fused hi/lo split in loader. AMODE=1: pre-split bf16 A.
// Stage (32KB): Ah@0, Al@8K, Bh@16K, Bl@24K; rows 64B, 16B-chunk XOR swizzle.
// ==============================================================================
#define BM 128
#define BN 128
#define STG 32768
#define NSTG 3

template<int AMODE, int EPI>
__global__ void __launch_bounds__(256, 2) mm_hmma3_kernel(
    const float* __restrict__ Af, const bf16* __restrict__ Ah, const bf16* __restrict__ Al,
    const bf16* __restrict__ Bh, const bf16* __restrict__ Bl,
    const float* __restrict__ bias, float* __restrict__ out, int K, int ldo)
{
    extern __shared__ __align__(16) char smem[];
    const uint32_t sb = smem_u32(smem);

    const int tid  = threadIdx.x;
    const int lane = tid & 31;
    const int wid  = tid >> 5;
    const int wm   = (wid & 3) * 32;
    const int wn   = (wid >> 2) * 64;
    const int n0   = blockIdx.x * BN;
    const int m0   = blockIdx.y * BM;

    float acc[2][8][4];
#pragma unroll
    for (int mt = 0; mt < 2; mt++)
#pragma unroll
        for (int nt = 0; nt < 8; nt++)
#pragma unroll
            for (int i = 0; i < 4; i++) acc[mt][nt][i] = 0.f;

    // loader constants
    const int brow = tid >> 2, bc = tid & 3;
    const int brow2 = (tid + 256) >> 2, bc2 = (tid + 256) & 3;
    const uint32_t bsw1 = brow * 64 + ((bc ^ ((brow >> 1) & 3)) << 4);
    const uint32_t bsw2 = brow2 * 64 + ((bc2 ^ ((brow2 >> 1) & 3)) << 4);
    const int arow = tid >> 1, ahalf = tid & 1;
    const uint32_t asw0 = arow * 64 + (((ahalf * 2 + 0) ^ ((arow >> 1) & 3)) << 4);
    const uint32_t asw1 = arow * 64 + (((ahalf * 2 + 1) ^ ((arow >> 1) & 3)) << 4);

    auto loadB = [&](int kt, uint32_t st) {
        cpasync16(st + 16384 + bsw1, Bh + (size_t)(n0 + brow) * K + kt + bc * 8);
        cpasync16(st + 24576 + bsw1, Bl + (size_t)(n0 + brow) * K + kt + bc * 8);
        cpasync16(st + 16384 + bsw2, Bh + (size_t)(n0 + brow2) * K + kt + bc2 * 8);
        cpasync16(st + 24576 + bsw2, Bl + (size_t)(n0 + brow2) * K + kt + bc2 * 8);
    };
    auto loadAasync = [&](int kt, uint32_t st) {
        cpasync16(st + 0    + bsw1, Ah + (size_t)(m0 + brow) * K + kt + bc * 8);
        cpasync16(st + 8192 + bsw1, Al + (size_t)(m0 + brow) * K + kt + bc * 8);
        cpasync16(st + 0    + bsw2, Ah + (size_t)(m0 + brow2) * K + kt + bc2 * 8);
        cpasync16(st + 8192 + bsw2, Al + (size_t)(m0 + brow2) * K + kt + bc2 * 8);
    };

    float4 pr[4];
    auto ldgA = [&](int kt) {
        const float4* src = (const float4*)(Af + (size_t)(m0 + arow) * K + kt + ahalf * 16);
        pr[0] = src[0]; pr[1] = src[1]; pr[2] = src[2]; pr[3] = src[3];
    };
    auto cvtsts = [&](uint32_t st) {
        uint4 hi, lo;
        split8(pr[0], pr[1], hi, lo);
        sts128(st + 0 + asw0, hi);
        sts128(st + 8192 + asw0, lo);
        split8(pr[2], pr[3], hi, lo);
        sts128(st + 0 + asw1, hi);
        sts128(st + 8192 + asw1, lo);
    };

    const int C = K / 32;   // >= 16 always here

    // ---- prologue: stages 0 and 1 in flight, pr holds chunk 2 (AMODE0) ----
    if (AMODE == 0) {
        ldgA(0);  cvtsts(sb + 0 * STG);
        ldgA(32); cvtsts(sb + 1 * STG);
        ldgA(64);
    }
    loadB(0, sb + 0 * STG);
    if (AMODE == 1) loadAasync(0, sb + 0 * STG);
    asm volatile("cp.async.commit_group;" ::: "memory");
    loadB(32, sb + 1 * STG);
    if (AMODE == 1) loadAasync(32, sb + 1 * STG);
    asm volatile("cp.async.commit_group;" ::: "memory");

    // ldmatrix constants
    const int rA  = wm + (lane & 15);
    const int hA  = lane >> 4;
    const int sAx = (rA >> 1) & 3;
    const int rB  = wn + (lane & 7) + ((lane >> 4) << 3);
    const int hB  = (lane >> 3) & 1;
    const int sBx = (rB >> 1) & 3;

    int s_cur = 0, s_nxt = 2;       // stage indices mod 3
    for (int c = 0; c < C; c++) {
        asm volatile("cp.async.wait_group 1;" ::: "memory");   // stage c landed
        __syncthreads();

        const uint32_t st = sb + s_cur * STG;
        const uint32_t nx = sb + s_nxt * STG;
        if (c + 2 < C) {
            loadB((c + 2) * 32, nx);
            if (AMODE == 1) loadAasync((c + 2) * 32, nx);
            if (AMODE == 0) {
                cvtsts(nx);                       // chunk c+2 from pr
                if (c + 3 < C) ldgA((c + 3) * 32);
            }
        }
        asm volatile("cp.async.commit_group;" ::: "memory");   // (possibly empty)

#pragma unroll
        for (int ks = 0; ks < 2; ks++) {
            const int chA = ((ks * 2 + hA) ^ sAx) << 4;
            const int chB = ((ks * 2 + hB) ^ sBx) << 4;
            uint32_t ah[2][4], al[2][4], bh[4][4], bl[4][4];
#pragma unroll
            for (int mt = 0; mt < 2; mt++)
                ldsm4(ah[mt][0], ah[mt][1], ah[mt][2], ah[mt][3],
                      st + 0 + (rA + mt * 16) * 64 + chA);
#pragma unroll
            for (int g = 0; g < 4; g++)
                ldsm4(bh[g][0], bh[g][1], bh[g][2], bh[g][3],
                      st + 16384 + (rB + g * 16) * 64 + chB);
#pragma unroll
            for (int mt = 0; mt < 2; mt++)
#pragma unroll
                for (int nt = 0; nt < 8; nt++)
                    mma16816(acc[mt][nt], ah[mt],
                             bh[nt >> 1][(nt & 1) * 2], bh[nt >> 1][(nt & 1) * 2 + 1]);
#pragma unroll
            for (int mt = 0; mt < 2; mt++)
                ldsm4(al[mt][0], al[mt][1], al[mt][2], al[mt][3],
                      st + 8192 + (rA + mt * 16) * 64 + chA);
#pragma unroll
            for (int mt = 0; mt < 2; mt++)
#pragma unroll
                for (int nt = 0; nt < 8; nt++)
                    mma16816(acc[mt][nt], al[mt],
                             bh[nt >> 1][(nt & 1) * 2], bh[nt >> 1][(nt & 1) * 2 + 1]);
#pragma unroll
            for (int g = 0; g < 4; g++)
                ldsm4(bl[g][0], bl[g][1], bl[g][2], bl[g][3],
                      st + 24576 + (rB + g * 16) * 64 + chB);
#pragma unroll
            for (int mt = 0; mt < 2; mt++)
#pragma unroll
                for (int nt = 0; nt < 8; nt++)
                    mma16816(acc[mt][nt], ah[mt],
                             bl[nt >> 1][(nt & 1) * 2], bl[nt >> 1][(nt & 1) * 2 + 1]);
        }
        s_cur = (s_cur == 2) ? 0 : s_cur + 1;
        s_nxt = (s_nxt == 2) ? 0 : s_nxt + 1;
    }

    // epilogue
#pragma unroll
    for (int mt = 0; mt < 2; mt++) {
        const int mrow = m0 + wm + mt * 16 + (lane >> 2);
#pragma unroll
        for (int nt = 0; nt < 8; nt++) {
            const int ncol = n0 + wn + nt * 8 + 2 * (lane & 3);
            float* cc = acc[mt][nt];
            if (EPI == 0) {
                float2 v0 = make_float2(fmaxf(cc[0], 0.f), fmaxf(cc[1], 0.f));
                float2 v1 = make_float2(fmaxf(cc[2], 0.f), fmaxf(cc[3], 0.f));
                *(float2*)(out + (size_t)mrow * ldo + ncol) = v0;
                *(float2*)(out + (size_t)(mrow + 8) * ldo + ncol) = v1;
            } else {
                if (ncol < NCAT) {
                    float bv = bias[ncol];
                    out[(size_t)mrow * ldo + ncol] = cc[0] + bv;
                    out[(size_t)(mrow + 8) * ldo + ncol] = cc[2] + bv;
                }
                if (ncol + 1 < NCAT) {
                    float bv = bias[ncol + 1];
                    out[(size_t)mrow * ldo + ncol + 1] = cc[1] + bv;
                    out[(size_t)(mrow + 8) * ldo + ncol + 1] = cc[3] + bv;
                }
            }
        }
    }
}

// ==============================================================================
// Leaf kernel: normalize comb row, emit GEMM2 A bf16 hi/lo row, rfft -> g_spec.
// ==============================================================================
__global__ void __launch_bounds__(128) leaf_kernel(const int* __restrict__ opos)
{
    const int row = blockIdx.x;          // 0..16383
    const int b = row >> 6;
    const int dst = opos[(row << 1) + 0];
    const int src = opos[(row << 1) + 1];
    const int tid = threadIdx.x;

    __shared__ float2 sZ[256];
    __shared__ float2 stw[128];
    __shared__ float2 sw5[256];
    __shared__ float ws[4];

    stw[tid] = g_twf[tid];
    sw5[tid] = g_w512f[tid];
    sw5[tid + 128] = g_w512f[tid + 128];

    const float4* cp = (const float4*)(g_comb + ((size_t)(b * SEQ + src)) * HID);
    float4 v = cp[tid];
    float ss = v.x*v.x + v.y*v.y + v.z*v.z + v.w*v.w;
#pragma unroll
    for (int o = 16; o; o >>= 1) ss += __shfl_xor_sync(0xffffffffu, ss, o);
    if ((tid & 31) == 0) ws[tid >> 5] = ss;
    __syncthreads();
    float sc = 1.f / (sqrtf(ws[0] + ws[1] + ws[2] + ws[3]) + 1e-6f);
    v = make_float4(v.x*sc, v.y*sc, v.z*sc, v.w*sc);

    const size_t nrow = (size_t)(b * MAXN + dst);
    {
        uint32_t* rh = (uint32_t*)(g_a2h + nrow * HID);
        uint32_t* rl = (uint32_t*)(g_a2l + nrow * HID);
        uint32_t h0 = bf2hi(v.x, v.y), h1 = bf2hi(v.z, v.w);
        __nv_bfloat162 t;
        t = *(__nv_bfloat162*)&h0; float2 f0 = __bfloat1622float2(t);
        t = *(__nv_bfloat162*)&h1; float2 f1 = __bfloat1622float2(t);
        rh[2*tid] = h0; rh[2*tid+1] = h1;
        rl[2*tid]   = bf2hi(v.x - f0.x, v.y - f0.y);
        rl[2*tid+1] = bf2hi(v.z - f1.x, v.w - f1.y);
    }

    sZ[2*tid]     = make_float2(v.x, v.y);
    sZ[2*tid + 1] = make_float2(v.z, v.w);
    __syncthreads();

#pragma unroll
    for (int s = 0; s < 8; s++) {
        const int half = 128 >> s;
        const int j = tid & (half - 1);
        const int p0 = (tid / half) * (half * 2) + j;
        const int p1 = p0 + half;
        float2 w = stw[j << s];
        float2 u = sZ[p0], vv = sZ[p1];
        sZ[p0] = make_float2(u.x + vv.x, u.y + vv.y);
        float dx = u.x - vv.x, dy = u.y - vv.y;
        sZ[p1] = make_float2(dx * w.x - dy * w.y, dx * w.y + dy * w.x);
        __syncthreads();
    }

    float* spec = g_spec + nrow * SPST;
#pragma unroll
    for (int h = 0; h < 2; h++) {
        int k = tid + h * 128;
        int kb = __brev((unsigned)k) >> 24;
        int km = __brev((unsigned)((256 - k) & 255)) >> 24;
        float2 Zk = sZ[kb], Zm = sZ[km];
        float er = 0.5f * (Zk.x + Zm.x);
        float ei = 0.5f * (Zk.y - Zm.y);
        float orr = 0.5f * (Zk.y + Zm.y);
        float oii = -0.5f * (Zk.x - Zm.x);
        float2 w = sw5[k];
        float2 X = make_float2(er + w.x * orr - w.y * oii,
                               ei + w.x * oii + w.y * orr);
        *(float2*)(spec + 2 * k) = X;
    }
    if (tid == 0)
        *(float2*)(spec + 512) = make_float2(sZ[0].x - sZ[0].y, 0.f);
}

// ==============================================================================
// Chain (spectral): one block per batch, 63 sequential steps.
// ==============================================================================
__global__ void __launch_bounds__(128) chain_spec_kernel(const int* __restrict__ cinfo)
{
    const int b = blockIdx.x;
    const int tid = threadIdx.x;
    __shared__ float2 sF[257];
    __shared__ __align__(16) float2 sG[2][260];
    __shared__ float ws[4];
    __shared__ int sInfo[NSTEP * 4];

    for (int i = tid; i < NSTEP * 4; i += 128) sInfo[i] = cinfo[(size_t)b * NSTEP * 4 + i];
    __syncthreads();

    const size_t nbase = (size_t)b * MAXN;
    {
        int l0 = sInfo[2];
        const float2* fr = (const float2*)(g_spec + (nbase + l0) * SPST);
        sF[tid] = fr[tid];
        sF[tid + 128] = fr[tid + 128];
        if (tid == 0) sF[256] = fr[256];
    }
    int prev_p = sInfo[2];

    {
        const float* src = g_spec + (nbase + sInfo[3]) * SPST;
        uint32_t dst = smem_u32(&sG[0][0]);
        cpasync16(dst + tid * 16, src + tid * 4);
        if (tid < 2) cpasync16(dst + (128 + tid) * 16, src + (128 + tid) * 4);
        asm volatile("cp.async.commit_group;" ::: "memory");
    }

    for (int k = 0; k < NSTEP; k++) {
        const int t = sInfo[k*4 + 0];
        const int p = sInfo[k*4 + 1];
        const int l = sInfo[k*4 + 2];
        const int cb = k & 1;

        bool issued = false;
        if (k + 1 < NSTEP) {
            const float* src = g_spec + (nbase + sInfo[(k+1)*4 + 3]) * SPST;
            uint32_t dst = smem_u32(&sG[cb ^ 1][0]);
            cpasync16(dst + tid * 16, src + tid * 4);
            if (tid < 2) cpasync16(dst + (128 + tid) * 16, src + (128 + tid) * 4);
            asm volatile("cp.async.commit_group;" ::: "memory");
            issued = true;
        }
        if (issued) asm volatile("cp.async.wait_group 1;" ::: "memory");
        else        asm volatile("cp.async.wait_group 0;" ::: "memory");
        __syncthreads();

        if (l != prev_p) {
            const float2* fr = (const float2*)(g_spec + (nbase + l) * SPST);
            sF[tid] = fr[tid];
            sF[tid + 128] = fr[tid + 128];
            if (tid == 0) sF[256] = fr[256];
        }

        float* specP = g_spec + (nbase + p) * SPST;

        if (t == 2) {
            float2 F0 = sF[tid],       G0 = sG[cb][tid];
            float2 F1 = sF[tid + 128], G1 = sG[cb][tid + 128];
            float2 c0 = make_float2(F0.x*G0.x + F0.y*G0.y, F0.x*G0.y - F0.y*G0.x);
            float2 c1 = make_float2(F1.x*G1.x + F1.y*G1.y, F1.x*G1.y - F1.y*G1.x);
            float w0 = (tid == 0) ? 1.f : 2.f;
            float part = w0 * (c0.x*c0.x + c0.y*c0.y) + 2.f * (c1.x*c1.x + c1.y*c1.y);
            float2 c2 = make_float2(0.f, 0.f);
            if (tid == 0) {
                float2 F2 = sF[256], G2 = sG[cb][256];
                c2 = make_float2(F2.x*G2.x + F2.y*G2.y, F2.x*G2.y - F2.y*G2.x);
                part += c2.x*c2.x + c2.y*c2.y;
            }
#pragma unroll
            for (int o = 16; o; o >>= 1) part += __shfl_xor_sync(0xffffffffu, part, o);
            if ((tid & 31) == 0) ws[tid >> 5] = part;
            __syncthreads();
            float tot = ws[0] + ws[1] + ws[2] + ws[3];
            float s = 1.f / (sqrtf(tot * (1.f / 512.f)) + 1e-6f);

            float2 f0 = make_float2(s * c0.x, s * c0.y);
            float2 f1 = make_float2(s * c1.x, s * c1.y);
            sF[tid] = f0; sF[tid + 128] = f1;
            *(float2*)(specP + 2 * tid) = f0;
            *(float2*)(specP + 2 * (tid + 128)) = f1;
            if (tid == 0) {
                float2 f2 = make_float2(s * c2.x, s * c2.y);
                sF[256] = f2;
                *(float2*)(specP + 512) = f2;
            }
        } else if (t == 1) {
            *(float2*)(specP + 2 * tid) = sF[tid];
            *(float2*)(specP + 2 * (tid + 128)) = sF[tid + 128];
            if (tid == 0) *(float2*)(specP + 512) = sF[256];
        } else {
            float2 z = make_float2(0.f, 0.f);
            sF[tid] = z; sF[tid + 128] = z;
            *(float2*)(specP + 2 * tid) = z;
            *(float2*)(specP + 2 * (tid + 128)) = z;
            if (tid == 0) { sF[256] = z; *(float2*)(specP + 512) = z; }
        }
        prev_p = p;
        __syncthreads();
    }
}

// ==============================================================================
// irfft of the 63 internal nodes per batch -> GEMM2 A bf16 hi/lo rows.
// ==============================================================================
__global__ void __launch_bounds__(128) irfft_nodes_kernel()
{
    const int idx = blockIdx.x;               // 0..16127
    const int b = idx / NSTEP, i = idx - b * NSTEP;
    const int node = 64 + i;
    const int tid = threadIdx.x;
    __shared__ float2 sX[257];
    __shared__ float2 sZ[256];
    __shared__ float2 stw[128];
    __shared__ float2 sw5[256];

    stw[tid] = g_twi[tid];
    sw5[tid] = g_w512i[tid];
    sw5[tid + 128] = g_w512i[tid + 128];

    const size_t nrow = (size_t)(b * MAXN + node);
    const float2* sp = (const float2*)(g_spec + nrow * SPST);
    sX[tid] = sp[tid];
    sX[tid + 128] = sp[tid + 128];
    if (tid == 0) sX[256] = sp[256];
    __syncthreads();

    const float inv512 = 1.f / 512.f;
#pragma unroll
    for (int h = 0; h < 2; h++) {
        int k = tid + h * 128;
        float2 A = sX[k], B = sX[256 - k];
        float er = A.x + B.x;
        float ei = A.y - B.y;
        float dr = A.x - B.x;
        float di = A.y + B.y;
        float2 w = sw5[k];
        float qr = w.x * dr - w.y * di;
        float qi = w.x * di + w.y * dr;
        float2 Z = make_float2(inv512 * (er - qi), inv512 * (ei + qr));
        sZ[__brev((unsigned)k) >> 24] = Z;
    }
    __syncthreads();

#pragma unroll
    for (int s = 0; s < 8; s++) {
        const int half = 1 << s;
        const int j = tid & (half - 1);
        const int p0 = ((tid >> s) << (s + 1)) | j;
        const int p1 = p0 + half;
        float2 w = stw[j << (7 - s)];
        float2 u = sZ[p0], v = sZ[p1];
        float tx = v.x * w.x - v.y * w.y;
        float ty = v.x * w.y + v.y * w.x;
        sZ[p0] = make_float2(u.x + tx, u.y + ty);
        sZ[p1] = make_float2(u.x - tx, u.y - ty);
        __syncthreads();
    }

    uint32_t* rh = (uint32_t*)(g_a2h + nrow * HID);
    uint32_t* rl = (uint32_t*)(g_a2l + nrow * HID);
#pragma unroll
    for (int h = 0; h < 2; h++) {
        int k = tid + h * 128;
        float2 z = sZ[k];
        uint32_t hv = bf2hi(z.x, z.y);
        __nv_bfloat162 t = *(__nv_bfloat162*)&hv;
        float2 f = __bfloat1622float2(t);
        rh[k] = hv;
        rl[k] = bf2hi(z.x - f.x, z.y - f.y);
    }
}

// ==============================================================================
extern "C" void kernel_launch(void* const* d_in, const int* in_sizes, int n_in,
                              void* d_out, int out_size)
{
    const float* seq  = (const float*)d_in[0];   // (256,64,1024)
    const float* W1   = (const float*)d_in[1];   // (512,512)
    const float* W2   = (const float*)d_in[2];   // (512,512)
    const float* LW   = (const float*)d_in[3];   // (511,512)
    const float* LB   = (const float*)d_in[4];   // (511,)
    const int*   opos = (const int*)d_in[7];     // (256,64,2)
    const int*   cinf = (const int*)d_in[8];     // (256,63,4)
    float* out = (float*)d_out;                  // (256,127,511)

    float* comb; bf16 *a2h, *a2l, *b1h, *b1l, *b2h, *b2l;
    cudaGetSymbolAddress((void**)&comb, g_comb);
    cudaGetSymbolAddress((void**)&a2h, g_a2h);
    cudaGetSymbolAddress((void**)&a2l, g_a2l);
    cudaGetSymbolAddress((void**)&b1h, g_b1h);
    cudaGetSymbolAddress((void**)&b1l, g_b1l);
    cudaGetSymbolAddress((void**)&b2h, g_b2h);
    cudaGetSymbolAddress((void**)&b2l, g_b2l);

    cudaFuncSetAttribute(mm_hmma3_kernel<0, 0>,
                         cudaFuncAttributeMaxDynamicSharedMemorySize, NSTG * STG);
    cudaFuncSetAttribute(mm_hmma3_kernel<1, 1>,
                         cudaFuncAttributeMaxDynamicSharedMemorySize, NSTG * STG);

    init_tables_kernel<<<1, 256>>>();
    {
        dim3 b(32, 8);
        dim3 g(EMB / 32, HID / 32);
        prep_b1_kernel<<<g, b>>>(W1, W2);
    }
    prep_b2_kernel<<<(512 * HID) / 256, 256>>>(LW);

    // GEMM1: comb = relu(seq @ [W1;W2]); fused fp32->bf16 split in loader
    {
        dim3 g(HID / BN, BSZ * SEQ / BM);         // (4, 128)
        mm_hmma3_kernel<0, 0><<<g, 256, NSTG * STG>>>(
            seq, nullptr, nullptr, b1h, b1l, nullptr, comb, EMB, HID);
    }

    leaf_kernel<<<BSZ * SEQ, 128>>>(opos);
    chain_spec_kernel<<<BSZ, 128>>>(cinf);
    irfft_nodes_kernel<<<BSZ * NSTEP, 128>>>();

    // GEMM2: out = nodes @ LW^T + LB; pre-split bf16 A
    {
        dim3 g(512 / BN, BSZ * MAXN / BM);        // (4, 254)
        mm_hmma3_kernel<1, 1><<<g, 256, NSTG * STG>>>(
            nullptr, a2h, a2l, b2h, b2l, LB, out, HID, NCAT);
    }
}

// round 8
// speedup vs baseline: 3.3147x; 1.2463x over previous
#include <cuda_runtime.h>
#include <cuda_fp16.h>
#include <cstdint>

// Problem constants (fixed by setup_inputs)
#define BSZ 256
#define SEQ 64
#define EMB 1024
#define HID 512
#define MAXN 127           // 2*S-1
#define NSTEP 63           // S-1
#define NCAT 511
#define SPST 520           // spec row stride (floats): 257 complex padded

typedef unsigned long long ull;

// ---------------- helpers ------------------------------------------------------
__device__ __forceinline__ uint32_t smem_u32(const void* p) {
    uint32_t a;
    asm("{ .reg .u64 t; cvta.to.shared.u64 t, %1; cvt.u32.u64 %0, t; }" : "=r"(a) : "l"(p));
    return a;
}
__device__ __forceinline__ void cpasync16(uint32_t dst, const void* src) {
    asm volatile("cp.async.cg.shared.global [%0], [%1], 16;" :: "r"(dst), "l"(src) : "memory");
}
__device__ __forceinline__ void ldsm4(uint32_t &d0, uint32_t &d1, uint32_t &d2, uint32_t &d3,
                                      uint32_t addr) {
    asm volatile("ldmatrix.sync.aligned.m8n8.x4.shared.b16 {%0,%1,%2,%3}, [%4];"
                 : "=r"(d0), "=r"(d1), "=r"(d2), "=r"(d3) : "r"(addr));
}
__device__ __forceinline__ void mma16816h(float* c, const uint32_t* a, uint32_t b0, uint32_t b1) {
    asm volatile("mma.sync.aligned.m16n8k16.row.col.f32.f16.f16.f32 "
                 "{%0,%1,%2,%3}, {%4,%5,%6,%7}, {%8,%9}, {%0,%1,%2,%3};"
                 : "+f"(c[0]), "+f"(c[1]), "+f"(c[2]), "+f"(c[3])
                 : "r"(a[0]), "r"(a[1]), "r"(a[2]), "r"(a[3]), "r"(b0), "r"(b1));
}
__device__ __forceinline__ void sts128(uint32_t addr, uint4 v) {
    asm volatile("st.shared.v4.b32 [%0], {%1,%2,%3,%4};"
                 :: "r"(addr), "r"(v.x), "r"(v.y), "r"(v.z), "r"(v.w) : "memory");
}
__device__ __forceinline__ uint32_t f2h2(float a, float b) {
    __half2 t = __float22half2_rn(make_float2(a, b));
    return *(uint32_t*)&t;
}
// split 8 floats into fp16 hi/lo quads
__device__ __forceinline__ void split8h(float4 u, float4 v, uint4 &hi, uint4 &lo) {
    hi.x = f2h2(u.x, u.y); hi.y = f2h2(u.z, u.w);
    hi.z = f2h2(v.x, v.y); hi.w = f2h2(v.z, v.w);
    __half2 h;
    h = *(__half2*)&hi.x; float2 f0 = __half22float2(h);
    h = *(__half2*)&hi.y; float2 f1 = __half22float2(h);
    h = *(__half2*)&hi.z; float2 f2 = __half22float2(h);
    h = *(__half2*)&hi.w; float2 f3 = __half22float2(h);
    lo.x = f2h2(u.x - f0.x, u.y - f0.y);
    lo.y = f2h2(u.z - f1.x, u.w - f1.y);
    lo.z = f2h2(v.x - f2.x, v.y - f2.y);
    lo.w = f2h2(v.z - f3.x, v.w - f3.y);
}

// ---------------- scratch (device globals: allocation-free) -------------------
__device__ float g_comb[(size_t)BSZ * SEQ * HID];                 // relu(GEMM1) fp32
__device__ __align__(16) float g_spec[(size_t)BSZ * MAXN * SPST]; // node spectra
__device__ __half g_a2h[(size_t)BSZ * MAXN * HID];                // GEMM2 A hi
__device__ __half g_a2l[(size_t)BSZ * MAXN * HID];                // GEMM2 A lo
__device__ __half g_b1h[(size_t)HID * EMB];                       // W^T fp16 [n][k]
__device__ __half g_b2h[(size_t)512 * HID];                       // LW fp16 (pad n=512)
__device__ float2 g_twf[128], g_twi[128], g_w512f[256], g_w512i[256];

// ==============================================================================
__global__ void init_tables_kernel()
{
    int t = threadIdx.x;
    const float PI2 = 6.283185307179586f;
    if (t < 128) {
        float th = PI2 * t / 256.0f;
        float s, c; sincosf(th, &s, &c);
        g_twf[t] = make_float2(c, -s);
        g_twi[t] = make_float2(c,  s);
    }
    float ph = PI2 * t / 512.0f;
    float s, c; sincosf(ph, &s, &c);
    g_w512f[t] = make_float2(c, -s);
    g_w512i[t] = make_float2(c,  s);
}

// coalesced tiled transpose: W1/W2 [k][n] -> g_b1h[n][k] fp16
__global__ void prep_b1_kernel(const float* __restrict__ W1, const float* __restrict__ W2)
{
    __shared__ float tile[32][33];
    const int kp0 = blockIdx.x * 32, n0 = blockIdx.y * 32;
    const int tx = threadIdx.x, ty = threadIdx.y;   // 32 x 8
#pragma unroll
    for (int i = 0; i < 32; i += 8) {
        int kp = kp0 + ty + i;
        const float* W = (kp < HID) ? (W1 + (size_t)kp * HID) : (W2 + (size_t)(kp - HID) * HID);
        tile[ty + i][tx] = W[n0 + tx];
    }
    __syncthreads();
#pragma unroll
    for (int i = 0; i < 32; i += 8) {
        int n = n0 + ty + i;
        g_b1h[(size_t)n * EMB + kp0 + tx] = __float2half_rn(tile[tx][ty + i]);
    }
}

__global__ void prep_b2_kernel(const float* __restrict__ LW)
{
    int id = blockIdx.x * 256 + threadIdx.x;              // over 512*512
    int n = id >> 9, k = id & 511;
    float v = (n < NCAT) ? LW[(size_t)n * HID + k] : 0.f;
    g_b2h[id] = __float2half_rn(v);
}

// ==============================================================================
// HMMA fp16 GEMM: D = ah*bh + al*bh (2 MMA passes, A split fp16 hi/lo, B fp16).
// 3-stage cp.async ring, one __syncthreads per K-chunk of 32.
// AMODE=0: A fp32 with fused split. AMODE=1: pre-split fp16 A.
// Stage (24KB): Ah@0, Al@8K, Bh@16K; rows 64B, 16B-chunk XOR swizzle.
// ==============================================================================
#define BM 128
#define BN 128
#define STG 24576
#define NSTG 3

template<int AMODE, int EPI>
__global__ void __launch_bounds__(256, 2) mm_fp16_kernel(
    const float* __restrict__ Af, const __half* __restrict__ Ah, const __half* __restrict__ Al,
    const __half* __restrict__ Bh,
    const float* __restrict__ bias, float* __restrict__ out, int K, int ldo)
{
    extern __shared__ __align__(16) char smem[];
    const uint32_t sb = smem_u32(smem);

    const int tid  = threadIdx.x;
    const int lane = tid & 31;
    const int wid  = tid >> 5;
    const int wm   = (wid & 3) * 32;
    const int wn   = (wid >> 2) * 64;
    const int n0   = blockIdx.x * BN;
    const int m0   = blockIdx.y * BM;

    float acc[2][8][4];
#pragma unroll
    for (int mt = 0; mt < 2; mt++)
#pragma unroll
        for (int nt = 0; nt < 8; nt++)
#pragma unroll
            for (int i = 0; i < 4; i++) acc[mt][nt][i] = 0.f;

    // loader constants
    const int brow = tid >> 2, bc = tid & 3;
    const int brow2 = (tid + 256) >> 2, bc2 = (tid + 256) & 3;
    const uint32_t bsw1 = brow * 64 + ((bc ^ ((brow >> 1) & 3)) << 4);
    const uint32_t bsw2 = brow2 * 64 + ((bc2 ^ ((brow2 >> 1) & 3)) << 4);
    const int arow = tid >> 1, ahalf = tid & 1;
    const uint32_t asw0 = arow * 64 + (((ahalf * 2 + 0) ^ ((arow >> 1) & 3)) << 4);
    const uint32_t asw1 = arow * 64 + (((ahalf * 2 + 1) ^ ((arow >> 1) & 3)) << 4);

    auto loadB = [&](int kt, uint32_t st) {
        cpasync16(st + 16384 + bsw1, Bh + (size_t)(n0 + brow) * K + kt + bc * 8);
        cpasync16(st + 16384 + bsw2, Bh + (size_t)(n0 + brow2) * K + kt + bc2 * 8);
    };
    auto loadAasync = [&](int kt, uint32_t st) {
        cpasync16(st + 0    + bsw1, Ah + (size_t)(m0 + brow) * K + kt + bc * 8);
        cpasync16(st + 8192 + bsw1, Al + (size_t)(m0 + brow) * K + kt + bc * 8);
        cpasync16(st + 0    + bsw2, Ah + (size_t)(m0 + brow2) * K + kt + bc2 * 8);
        cpasync16(st + 8192 + bsw2, Al + (size_t)(m0 + brow2) * K + kt + bc2 * 8);
    };

    float4 pr[4];
    auto ldgA = [&](int kt) {
        const float4* src = (const float4*)(Af + (size_t)(m0 + arow) * K + kt + ahalf * 16);
        pr[0] = src[0]; pr[1] = src[1]; pr[2] = src[2]; pr[3] = src[3];
    };
    auto cvtsts = [&](uint32_t st) {
        uint4 hi, lo;
        split8h(pr[0], pr[1], hi, lo);
        sts128(st + 0 + asw0, hi);
        sts128(st + 8192 + asw0, lo);
        split8h(pr[2], pr[3], hi, lo);
        sts128(st + 0 + asw1, hi);
        sts128(st + 8192 + asw1, lo);
    };

    const int C = K / 32;   // >= 16 here

    // ---- prologue: stages 0,1 in flight; pr holds chunk 2 (AMODE0) ----
    if (AMODE == 0) {
        ldgA(0);  cvtsts(sb + 0 * STG);
        ldgA(32); cvtsts(sb + 1 * STG);
        ldgA(64);
    }
    loadB(0, sb + 0 * STG);
    if (AMODE == 1) loadAasync(0, sb + 0 * STG);
    asm volatile("cp.async.commit_group;" ::: "memory");
    loadB(32, sb + 1 * STG);
    if (AMODE == 1) loadAasync(32, sb + 1 * STG);
    asm volatile("cp.async.commit_group;" ::: "memory");

    // ldmatrix constants
    const int rA  = wm + (lane & 15);
    const int hA  = lane >> 4;
    const int sAx = (rA >> 1) & 3;
    const int rB  = wn + (lane & 7) + ((lane >> 4) << 3);
    const int hB  = (lane >> 3) & 1;
    const int sBx = (rB >> 1) & 3;

    int s_cur = 0, s_nxt = 2;
    for (int c = 0; c < C; c++) {
        asm volatile("cp.async.wait_group 1;" ::: "memory");
        __syncthreads();

        const uint32_t st = sb + s_cur * STG;
        const uint32_t nx = sb + s_nxt * STG;
        if (c + 2 < C) {
            loadB((c + 2) * 32, nx);
            if (AMODE == 1) loadAasync((c + 2) * 32, nx);
            if (AMODE == 0) {
                cvtsts(nx);
                if (c + 3 < C) ldgA((c + 3) * 32);
            }
        }
        asm volatile("cp.async.commit_group;" ::: "memory");

#pragma unroll
        for (int ks = 0; ks < 2; ks++) {
            const int chA = ((ks * 2 + hA) ^ sAx) << 4;
            const int chB = ((ks * 2 + hB) ^ sBx) << 4;
            uint32_t ah[2][4], al[2][4], bh[4][4];
#pragma unroll
            for (int mt = 0; mt < 2; mt++)
                ldsm4(ah[mt][0], ah[mt][1], ah[mt][2], ah[mt][3],
                      st + 0 + (rA + mt * 16) * 64 + chA);
#pragma unroll
            for (int g = 0; g < 4; g++)
                ldsm4(bh[g][0], bh[g][1], bh[g][2], bh[g][3],
                      st + 16384 + (rB + g * 16) * 64 + chB);
#pragma unroll
            for (int mt = 0; mt < 2; mt++)
#pragma unroll
                for (int nt = 0; nt < 8; nt++)
                    mma16816h(acc[mt][nt], ah[mt],
                              bh[nt >> 1][(nt & 1) * 2], bh[nt >> 1][(nt & 1) * 2 + 1]);
#pragma unroll
            for (int mt = 0; mt < 2; mt++)
                ldsm4(al[mt][0], al[mt][1], al[mt][2], al[mt][3],
                      st + 8192 + (rA + mt * 16) * 64 + chA);
#pragma unroll
            for (int mt = 0; mt < 2; mt++)
#pragma unroll
                for (int nt = 0; nt < 8; nt++)
                    mma16816h(acc[mt][nt], al[mt],
                              bh[nt >> 1][(nt & 1) * 2], bh[nt >> 1][(nt & 1) * 2 + 1]);
        }
        s_cur = (s_cur == 2) ? 0 : s_cur + 1;
        s_nxt = (s_nxt == 2) ? 0 : s_nxt + 1;
    }

    // epilogue
#pragma unroll
    for (int mt = 0; mt < 2; mt++) {
        const int mrow = m0 + wm + mt * 16 + (lane >> 2);
#pragma unroll
        for (int nt = 0; nt < 8; nt++) {
            const int ncol = n0 + wn + nt * 8 + 2 * (lane & 3);
            float* cc = acc[mt][nt];
            if (EPI == 0) {
                float2 v0 = make_float2(fmaxf(cc[0], 0.f), fmaxf(cc[1], 0.f));
                float2 v1 = make_float2(fmaxf(cc[2], 0.f), fmaxf(cc[3], 0.f));
                *(float2*)(out + (size_t)mrow * ldo + ncol) = v0;
                *(float2*)(out + (size_t)(mrow + 8) * ldo + ncol) = v1;
            } else {
                if (ncol < NCAT) {
                    float bv = bias[ncol];
                    out[(size_t)mrow * ldo + ncol] = cc[0] + bv;
                    out[(size_t)(mrow + 8) * ldo + ncol] = cc[2] + bv;
                }
                if (ncol + 1 < NCAT) {
                    float bv = bias[ncol + 1];
                    out[(size_t)mrow * ldo + ncol + 1] = cc[1] + bv;
                    out[(size_t)(mrow + 8) * ldo + ncol + 1] = cc[3] + bv;
                }
            }
        }
    }
}

// ==============================================================================
// Leaf kernel: normalize comb row, emit GEMM2 A fp16 hi/lo row, rfft -> g_spec.
// ==============================================================================
__global__ void __launch_bounds__(128) leaf_kernel(const int* __restrict__ opos)
{
    const int row = blockIdx.x;          // 0..16383
    const int b = row >> 6;
    const int dst = opos[(row << 1) + 0];
    const int src = opos[(row << 1) + 1];
    const int tid = threadIdx.x;

    __shared__ float2 sZ[256];
    __shared__ float2 stw[128];
    __shared__ float2 sw5[256];
    __shared__ float ws[4];

    stw[tid] = g_twf[tid];
    sw5[tid] = g_w512f[tid];
    sw5[tid + 128] = g_w512f[tid + 128];

    const float4* cp = (const float4*)(g_comb + ((size_t)(b * SEQ + src)) * HID);
    float4 v = cp[tid];
    float ss = v.x*v.x + v.y*v.y + v.z*v.z + v.w*v.w;
#pragma unroll
    for (int o = 16; o; o >>= 1) ss += __shfl_xor_sync(0xffffffffu, ss, o);
    if ((tid & 31) == 0) ws[tid >> 5] = ss;
    __syncthreads();
    float sc = 1.f / (sqrtf(ws[0] + ws[1] + ws[2] + ws[3]) + 1e-6f);
    v = make_float4(v.x*sc, v.y*sc, v.z*sc, v.w*sc);

    const size_t nrow = (size_t)(b * MAXN + dst);
    {
        uint32_t* rh = (uint32_t*)(g_a2h + nrow * HID);
        uint32_t* rl = (uint32_t*)(g_a2l + nrow * HID);
        uint32_t h0 = f2h2(v.x, v.y), h1 = f2h2(v.z, v.w);
        __half2 t;
        t = *(__half2*)&h0; float2 f0 = __half22float2(t);
        t = *(__half2*)&h1; float2 f1 = __half22float2(t);
        rh[2*tid] = h0; rh[2*tid+1] = h1;
        rl[2*tid]   = f2h2(v.x - f0.x, v.y - f0.y);
        rl[2*tid+1] = f2h2(v.z - f1.x, v.w - f1.y);
    }

    sZ[2*tid]     = make_float2(v.x, v.y);
    sZ[2*tid + 1] = make_float2(v.z, v.w);
    __syncthreads();

#pragma unroll
    for (int s = 0; s < 8; s++) {
        const int half = 128 >> s;
        const int j = tid & (half - 1);
        const int p0 = (tid / half) * (half * 2) + j;
        const int p1 = p0 + half;
        float2 w = stw[j << s];
        float2 u = sZ[p0], vv = sZ[p1];
        sZ[p0] = make_float2(u.x + vv.x, u.y + vv.y);
        float dx = u.x - vv.x, dy = u.y - vv.y;
        sZ[p1] = make_float2(dx * w.x - dy * w.y, dx * w.y + dy * w.x);
        __syncthreads();
    }

    float* spec = g_spec + nrow * SPST;
#pragma unroll
    for (int h = 0; h < 2; h++) {
        int k = tid + h * 128;
        int kb = __brev((unsigned)k) >> 24;
        int km = __brev((unsigned)((256 - k) & 255)) >> 24;
        float2 Zk = sZ[kb], Zm = sZ[km];
        float er = 0.5f * (Zk.x + Zm.x);
        float ei = 0.5f * (Zk.y - Zm.y);
        float orr = 0.5f * (Zk.y + Zm.y);
        float oii = -0.5f * (Zk.x - Zm.x);
        float2 w = sw5[k];
        float2 X = make_float2(er + w.x * orr - w.y * oii,
                               ei + w.x * oii + w.y * orr);
        *(float2*)(spec + 2 * k) = X;
    }
    if (tid == 0)
        *(float2*)(spec + 512) = make_float2(sZ[0].x - sZ[0].y, 0.f);
}

// ==============================================================================
// Chain (spectral): one block per batch, 63 sequential steps.
// ==============================================================================
__global__ void __launch_bounds__(128) chain_spec_kernel(const int* __restrict__ cinfo)
{
    const int b = blockIdx.x;
    const int tid = threadIdx.x;
    __shared__ float2 sF[257];
    __shared__ __align__(16) float2 sG[2][260];
    __shared__ float ws[4];
    __shared__ int sInfo[NSTEP * 4];

    for (int i = tid; i < NSTEP * 4; i += 128) sInfo[i] = cinfo[(size_t)b * NSTEP * 4 + i];
    __syncthreads();

    const size_t nbase = (size_t)b * MAXN;
    {
        int l0 = sInfo[2];
        const float2* fr = (const float2*)(g_spec + (nbase + l0) * SPST);
        sF[tid] = fr[tid];
        sF[tid + 128] = fr[tid + 128];
        if (tid == 0) sF[256] = fr[256];
    }
    int prev_p = sInfo[2];

    {
        const float* src = g_spec + (nbase + sInfo[3]) * SPST;
        uint32_t dst = smem_u32(&sG[0][0]);
        cpasync16(dst + tid * 16, src + tid * 4);
        if (tid < 2) cpasync16(dst + (128 + tid) * 16, src + (128 + tid) * 4);
        asm volatile("cp.async.commit_group;" ::: "memory");
    }

    for (int k = 0; k < NSTEP; k++) {
        const int t = sInfo[k*4 + 0];
        const int p = sInfo[k*4 + 1];
        const int l = sInfo[k*4 + 2];
        const int cb = k & 1;

        bool issued = false;
        if (k + 1 < NSTEP) {
            const float* src = g_spec + (nbase + sInfo[(k+1)*4 + 3]) * SPST;
            uint32_t dst = smem_u32(&sG[cb ^ 1][0]);
            cpasync16(dst + tid * 16, src + tid * 4);
            if (tid < 2) cpasync16(dst + (128 + tid) * 16, src + (128 + tid) * 4);
            asm volatile("cp.async.commit_group;" ::: "memory");
            issued = true;
        }
        if (issued) asm volatile("cp.async.wait_group 1;" ::: "memory");
        else        asm volatile("cp.async.wait_group 0;" ::: "memory");
        __syncthreads();

        if (l != prev_p) {
            const float2* fr = (const float2*)(g_spec + (nbase + l) * SPST);
            sF[tid] = fr[tid];
            sF[tid + 128] = fr[tid + 128];
            if (tid == 0) sF[256] = fr[256];
        }

        float* specP = g_spec + (nbase + p) * SPST;

        if (t == 2) {
            float2 F0 = sF[tid],       G0 = sG[cb][tid];
            float2 F1 = sF[tid + 128], G1 = sG[cb][tid + 128];
            float2 c0 = make_float2(F0.x*G0.x + F0.y*G0.y, F0.x*G0.y - F0.y*G0.x);
            float2 c1 = make_float2(F1.x*G1.x + F1.y*G1.y, F1.x*G1.y - F1.y*G1.x);
            float w0 = (tid == 0) ? 1.f : 2.f;
            float part = w0 * (c0.x*c0.x + c0.y*c0.y) + 2.f * (c1.x*c1.x + c1.y*c1.y);
            float2 c2 = make_float2(0.f, 0.f);
            if (tid == 0) {
                float2 F2 = sF[256], G2 = sG[cb][256];
                c2 = make_float2(F2.x*G2.x + F2.y*G2.y, F2.x*G2.y - F2.y*G2.x);
                part += c2.x*c2.x + c2.y*c2.y;
            }
#pragma unroll
            for (int o = 16; o; o >>= 1) part += __shfl_xor_sync(0xffffffffu, part, o);
            if ((tid & 31) == 0) ws[tid >> 5] = part;
            __syncthreads();
            float tot = ws[0] + ws[1] + ws[2] + ws[3];
            float s = 1.f / (sqrtf(tot * (1.f / 512.f)) + 1e-6f);

            float2 f0 = make_float2(s * c0.x, s * c0.y);
            float2 f1 = make_float2(s * c1.x, s * c1.y);
            sF[tid] = f0; sF[tid + 128] = f1;
            *(float2*)(specP + 2 * tid) = f0;
            *(float2*)(specP + 2 * (tid + 128)) = f1;
            if (tid == 0) {
                float2 f2 = make_float2(s * c2.x, s * c2.y);
                sF[256] = f2;
                *(float2*)(specP + 512) = f2;
            }
        } else if (t == 1) {
            *(float2*)(specP + 2 * tid) = sF[tid];
            *(float2*)(specP + 2 * (tid + 128)) = sF[tid + 128];
            if (tid == 0) *(float2*)(specP + 512) = sF[256];
        } else {
            float2 z = make_float2(0.f, 0.f);
            sF[tid] = z; sF[tid + 128] = z;
            *(float2*)(specP + 2 * tid) = z;
            *(float2*)(specP + 2 * (tid + 128)) = z;
            if (tid == 0) { sF[256] = z; *(float2*)(specP + 512) = z; }
        }
        prev_p = p;
        __syncthreads();
    }
}

// ==============================================================================
// irfft of the 63 internal nodes per batch -> GEMM2 A fp16 hi/lo rows.
// ==============================================================================
__global__ void __launch_bounds__(128) irfft_nodes_kernel()
{
    const int idx = blockIdx.x;               // 0..16127
    const int b = idx / NSTEP, i = idx - b * NSTEP;
    const int node = 64 + i;
    const int tid = threadIdx.x;
    __shared__ float2 sX[257];
    __shared__ float2 sZ[256];
    __shared__ float2 stw[128];
    __shared__ float2 sw5[256];

    stw[tid] = g_twi[tid];
    sw5[tid] = g_w512i[tid];
    sw5[tid + 128] = g_w512i[tid + 128];

    const size_t nrow = (size_t)(b * MAXN + node);
    const float2* sp = (const float2*)(g_spec + nrow * SPST);
    sX[tid] = sp[tid];
    sX[tid + 128] = sp[tid + 128];
    if (tid == 0) sX[256] = sp[256];
    __syncthreads();

    const float inv512 = 1.f / 512.f;
#pragma unroll
    for (int h = 0; h < 2; h++) {
        int k = tid + h * 128;
        float2 A = sX[k], B = sX[256 - k];
        float er = A.x + B.x;
        float ei = A.y - B.y;
        float dr = A.x - B.x;
        float di = A.y + B.y;
        float2 w = sw5[k];
        float qr = w.x * dr - w.y * di;
        float qi = w.x * di + w.y * dr;
        float2 Z = make_float2(inv512 * (er - qi), inv512 * (ei + qr));
        sZ[__brev((unsigned)k) >> 24] = Z;
    }
    __syncthreads();

#pragma unroll
    for (int s = 0; s < 8; s++) {
        const int half = 1 << s;
        const int j = tid & (half - 1);
        const int p0 = ((tid >> s) << (s + 1)) | j;
        const int p1 = p0 + half;
        float2 w = stw[j << (7 - s)];
        float2 u = sZ[p0], v = sZ[p1];
        float tx = v.x * w.x - v.y * w.y;
        float ty = v.x * w.y + v.y * w.x;
        sZ[p0] = make_float2(u.x + tx, u.y + ty);
        sZ[p1] = make_float2(u.x - tx, u.y - ty);
        __syncthreads();
    }

    uint32_t* rh = (uint32_t*)(g_a2h + nrow * HID);
    uint32_t* rl = (uint32_t*)(g_a2l + nrow * HID);
#pragma unroll
    for (int h = 0; h < 2; h++) {
        int k = tid + h * 128;
        float2 z = sZ[k];
        uint32_t hv = f2h2(z.x, z.y);
        __half2 t = *(__half2*)&hv;
        float2 f = __half22float2(t);
        rh[k] = hv;
        rl[k] = f2h2(z.x - f.x, z.y - f.y);
    }
}

// ==============================================================================
extern "C" void kernel_launch(void* const* d_in, const int* in_sizes, int n_in,
                              void* d_out, int out_size)
{
    const float* seq  = (const float*)d_in[0];   // (256,64,1024)
    const float* W1   = (const float*)d_in[1];   // (512,512)
    const float* W2   = (const float*)d_in[2];   // (512,512)
    const float* LW   = (const float*)d_in[3];   // (511,512)
    const float* LB   = (const float*)d_in[4];   // (511,)
    const int*   opos = (const int*)d_in[7];     // (256,64,2)
    const int*   cinf = (const int*)d_in[8];     // (256,63,4)
    float* out = (float*)d_out;                  // (256,127,511)

    float* comb; __half *a2h, *a2l, *b1h, *b2h;
    cudaGetSymbolAddress((void**)&comb, g_comb);
    cudaGetSymbolAddress((void**)&a2h, g_a2h);
    cudaGetSymbolAddress((void**)&a2l, g_a2l);
    cudaGetSymbolAddress((void**)&b1h, g_b1h);
    cudaGetSymbolAddress((void**)&b2h, g_b2h);

    cudaFuncSetAttribute(mm_fp16_kernel<0, 0>,
                         cudaFuncAttributeMaxDynamicSharedMemorySize, NSTG * STG);
    cudaFuncSetAttribute(mm_fp16_kernel<1, 1>,
                         cudaFuncAttributeMaxDynamicSharedMemorySize, NSTG * STG);

    init_tables_kernel<<<1, 256>>>();
    {
        dim3 b(32, 8);
        dim3 g(EMB / 32, HID / 32);
        prep_b1_kernel<<<g, b>>>(W1, W2);
    }
    prep_b2_kernel<<<(512 * HID) / 256, 256>>>(LW);

    // GEMM1: comb = relu(seq @ [W1;W2]); fused fp32->fp16 split in loader
    {
        dim3 g(HID / BN, BSZ * SEQ / BM);         // (4, 128)
        mm_fp16_kernel<0, 0><<<g, 256, NSTG * STG>>>(
            seq, nullptr, nullptr, b1h, nullptr, comb, EMB, HID);
    }

    leaf_kernel<<<BSZ * SEQ, 128>>>(opos);
    chain_spec_kernel<<<BSZ, 128>>>(cinf);
    irfft_nodes_kernel<<<BSZ * NSTEP, 128>>>();

    // GEMM2: out = nodes @ LW^T + LB; pre-split fp16 A
    {
        dim3 g(512 / BN, BSZ * MAXN / BM);        // (4, 254)
        mm_fp16_kernel<1, 1><<<g, 256, NSTG * STG>>>(
            nullptr, a2h, a2l, b2h, LB, out, HID, NCAT);
    }
}

// round 9
// speedup vs baseline: 3.4561x; 1.0427x over previous
#include <cuda_runtime.h>
#include <cuda_fp16.h>
#include <cstdint>

// Problem constants (fixed by setup_inputs)
#define BSZ 256
#define SEQ 64
#define EMB 1024
#define HID 512
#define MAXN 127           // 2*S-1
#define NSTEP 63           // S-1
#define NCAT 511
#define SPST 520           // spec row stride (floats): 257 complex padded

typedef unsigned long long ull;

// ---------------- helpers ------------------------------------------------------
__device__ __forceinline__ uint32_t smem_u32(const void* p) {
    uint32_t a;
    asm("{ .reg .u64 t; cvta.to.shared.u64 t, %1; cvt.u32.u64 %0, t; }" : "=r"(a) : "l"(p));
    return a;
}
__device__ __forceinline__ void cpasync16(uint32_t dst, const void* src) {
    asm volatile("cp.async.cg.shared.global [%0], [%1], 16;" :: "r"(dst), "l"(src) : "memory");
}
__device__ __forceinline__ void ldsm4(uint32_t &d0, uint32_t &d1, uint32_t &d2, uint32_t &d3,
                                      uint32_t addr) {
    asm volatile("ldmatrix.sync.aligned.m8n8.x4.shared.b16 {%0,%1,%2,%3}, [%4];"
                 : "=r"(d0), "=r"(d1), "=r"(d2), "=r"(d3) : "r"(addr));
}
__device__ __forceinline__ void mma16816h(float* c, const uint32_t* a, uint32_t b0, uint32_t b1) {
    asm volatile("mma.sync.aligned.m16n8k16.row.col.f32.f16.f16.f32 "
                 "{%0,%1,%2,%3}, {%4,%5,%6,%7}, {%8,%9}, {%0,%1,%2,%3};"
                 : "+f"(c[0]), "+f"(c[1]), "+f"(c[2]), "+f"(c[3])
                 : "r"(a[0]), "r"(a[1]), "r"(a[2]), "r"(a[3]), "r"(b0), "r"(b1));
}
__device__ __forceinline__ void sts128(uint32_t addr, uint4 v) {
    asm volatile("st.shared.v4.b32 [%0], {%1,%2,%3,%4};"
                 :: "r"(addr), "r"(v.x), "r"(v.y), "r"(v.z), "r"(v.w) : "memory");
}
__device__ __forceinline__ uint32_t f2h2(float a, float b) {
    __half2 t = __float22half2_rn(make_float2(a, b));
    return *(uint32_t*)&t;
}
// split 8 floats into fp16 hi/lo quads
__device__ __forceinline__ void split8h(float4 u, float4 v, uint4 &hi, uint4 &lo) {
    hi.x = f2h2(u.x, u.y); hi.y = f2h2(u.z, u.w);
    hi.z = f2h2(v.x, v.y); hi.w = f2h2(v.z, v.w);
    __half2 h;
    h = *(__half2*)&hi.x; float2 f0 = __half22float2(h);
    h = *(__half2*)&hi.y; float2 f1 = __half22float2(h);
    h = *(__half2*)&hi.z; float2 f2 = __half22float2(h);
    h = *(__half2*)&hi.w; float2 f3 = __half22float2(h);
    lo.x = f2h2(u.x - f0.x, u.y - f0.y);
    lo.y = f2h2(u.z - f1.x, u.w - f1.y);
    lo.z = f2h2(v.x - f2.x, v.y - f2.y);
    lo.w = f2h2(v.z - f3.x, v.w - f3.y);
}

// ---------------- scratch (device globals: allocation-free) -------------------
__device__ float g_comb[(size_t)BSZ * SEQ * HID];                 // relu(GEMM1) fp32
__device__ __align__(16) float g_spec[(size_t)BSZ * MAXN * SPST]; // node spectra
__device__ __half g_a2h[(size_t)BSZ * MAXN * HID];                // GEMM2 A fp16
__device__ __half g_b1h[(size_t)HID * EMB];                       // W^T fp16 [n][k]
__device__ __half g_b2h[(size_t)512 * HID];                       // LW fp16 (pad n=512)
__device__ float2 g_twf[128], g_twi[128], g_w512f[256], g_w512i[256];

// ==============================================================================
__global__ void init_tables_kernel()
{
    int t = threadIdx.x;
    const float PI2 = 6.283185307179586f;
    if (t < 128) {
        float th = PI2 * t / 256.0f;
        float s, c; sincosf(th, &s, &c);
        g_twf[t] = make_float2(c, -s);
        g_twi[t] = make_float2(c,  s);
    }
    float ph = PI2 * t / 512.0f;
    float s, c; sincosf(ph, &s, &c);
    g_w512f[t] = make_float2(c, -s);
    g_w512i[t] = make_float2(c,  s);
}

// coalesced tiled transpose: W1/W2 [k][n] -> g_b1h[n][k] fp16
__global__ void prep_b1_kernel(const float* __restrict__ W1, const float* __restrict__ W2)
{
    __shared__ float tile[32][33];
    const int kp0 = blockIdx.x * 32, n0 = blockIdx.y * 32;
    const int tx = threadIdx.x, ty = threadIdx.y;   // 32 x 8
#pragma unroll
    for (int i = 0; i < 32; i += 8) {
        int kp = kp0 + ty + i;
        const float* W = (kp < HID) ? (W1 + (size_t)kp * HID) : (W2 + (size_t)(kp - HID) * HID);
        tile[ty + i][tx] = W[n0 + tx];
    }
    __syncthreads();
#pragma unroll
    for (int i = 0; i < 32; i += 8) {
        int n = n0 + ty + i;
        g_b1h[(size_t)n * EMB + kp0 + tx] = __float2half_rn(tile[tx][ty + i]);
    }
}

__global__ void prep_b2_kernel(const float* __restrict__ LW)
{
    int id = blockIdx.x * 256 + threadIdx.x;              // over 512*512
    int n = id >> 9, k = id & 511;
    float v = (n < NCAT) ? LW[(size_t)n * HID + k] : 0.f;
    g_b2h[id] = __float2half_rn(v);
}

// ==============================================================================
// HMMA fp16 GEMM, 3-stage cp.async ring, one __syncthreads per K-chunk of 32.
// TWOP=1: D = ah*bh + al*bh (A split fp16 hi/lo).  TWOP=0: D = ah*bh.
// AMODE=0: A fp32 with fused split. AMODE=1: pre-split/rounded fp16 A.
// Stage: Ah@0 [, Al@8K], Bh@BOFF; rows 64B, 16B-chunk XOR swizzle.
// ==============================================================================
#define BM 128
#define BN 128
#define NSTG 3

template<int AMODE, int EPI, int TWOP>
__global__ void __launch_bounds__(256, 2) mm_fp16_kernel(
    const float* __restrict__ Af, const __half* __restrict__ Ah, const __half* __restrict__ Al,
    const __half* __restrict__ Bh,
    const float* __restrict__ bias, float* __restrict__ out, int K, int ldo)
{
    constexpr uint32_t BOFF  = TWOP ? 16384 : 8192;
    constexpr uint32_t STGSZ = TWOP ? 24576 : 16384;

    extern __shared__ __align__(16) char smem[];
    const uint32_t sb = smem_u32(smem);

    const int tid  = threadIdx.x;
    const int lane = tid & 31;
    const int wid  = tid >> 5;
    const int wm   = (wid & 3) * 32;
    const int wn   = (wid >> 2) * 64;
    const int n0   = blockIdx.x * BN;
    const int m0   = blockIdx.y * BM;

    float acc[2][8][4];
#pragma unroll
    for (int mt = 0; mt < 2; mt++)
#pragma unroll
        for (int nt = 0; nt < 8; nt++)
#pragma unroll
            for (int i = 0; i < 4; i++) acc[mt][nt][i] = 0.f;

    // loader constants
    const int brow = tid >> 2, bc = tid & 3;
    const int brow2 = (tid + 256) >> 2, bc2 = (tid + 256) & 3;
    const uint32_t bsw1 = brow * 64 + ((bc ^ ((brow >> 1) & 3)) << 4);
    const uint32_t bsw2 = brow2 * 64 + ((bc2 ^ ((brow2 >> 1) & 3)) << 4);
    const int arow = tid >> 1, ahalf = tid & 1;
    const uint32_t asw0 = arow * 64 + (((ahalf * 2 + 0) ^ ((arow >> 1) & 3)) << 4);
    const uint32_t asw1 = arow * 64 + (((ahalf * 2 + 1) ^ ((arow >> 1) & 3)) << 4);

    auto loadB = [&](int kt, uint32_t st) {
        cpasync16(st + BOFF + bsw1, Bh + (size_t)(n0 + brow) * K + kt + bc * 8);
        cpasync16(st + BOFF + bsw2, Bh + (size_t)(n0 + brow2) * K + kt + bc2 * 8);
    };
    auto loadAasync = [&](int kt, uint32_t st) {
        cpasync16(st + 0 + bsw1, Ah + (size_t)(m0 + brow) * K + kt + bc * 8);
        cpasync16(st + 0 + bsw2, Ah + (size_t)(m0 + brow2) * K + kt + bc2 * 8);
        if (TWOP) {
            cpasync16(st + 8192 + bsw1, Al + (size_t)(m0 + brow) * K + kt + bc * 8);
            cpasync16(st + 8192 + bsw2, Al + (size_t)(m0 + brow2) * K + kt + bc2 * 8);
        }
    };

    float4 pr[4];
    auto ldgA = [&](int kt) {
        const float4* src = (const float4*)(Af + (size_t)(m0 + arow) * K + kt + ahalf * 16);
        pr[0] = src[0]; pr[1] = src[1]; pr[2] = src[2]; pr[3] = src[3];
    };
    auto cvtsts = [&](uint32_t st) {
        uint4 hi, lo;
        split8h(pr[0], pr[1], hi, lo);
        sts128(st + 0 + asw0, hi);
        sts128(st + 8192 + asw0, lo);
        split8h(pr[2], pr[3], hi, lo);
        sts128(st + 0 + asw1, hi);
        sts128(st + 8192 + asw1, lo);
    };

    const int C = K / 32;   // >= 16 here

    // ---- prologue: stages 0,1 in flight; pr holds chunk 2 (AMODE0) ----
    if (AMODE == 0) {
        ldgA(0);  cvtsts(sb + 0 * STGSZ);
        ldgA(32); cvtsts(sb + 1 * STGSZ);
        ldgA(64);
    }
    loadB(0, sb + 0 * STGSZ);
    if (AMODE == 1) loadAasync(0, sb + 0 * STGSZ);
    asm volatile("cp.async.commit_group;" ::: "memory");
    loadB(32, sb + 1 * STGSZ);
    if (AMODE == 1) loadAasync(32, sb + 1 * STGSZ);
    asm volatile("cp.async.commit_group;" ::: "memory");

    // ldmatrix constants
    const int rA  = wm + (lane & 15);
    const int hA  = lane >> 4;
    const int sAx = (rA >> 1) & 3;
    const int rB  = wn + (lane & 7) + ((lane >> 4) << 3);
    const int hB  = (lane >> 3) & 1;
    const int sBx = (rB >> 1) & 3;

    int s_cur = 0, s_nxt = 2;
    for (int c = 0; c < C; c++) {
        asm volatile("cp.async.wait_group 1;" ::: "memory");
        __syncthreads();

        const uint32_t st = sb + s_cur * STGSZ;
        const uint32_t nx = sb + s_nxt * STGSZ;
        if (c + 2 < C) {
            loadB((c + 2) * 32, nx);
            if (AMODE == 1) loadAasync((c + 2) * 32, nx);
            if (AMODE == 0) {
                cvtsts(nx);
                if (c + 3 < C) ldgA((c + 3) * 32);
            }
        }
        asm volatile("cp.async.commit_group;" ::: "memory");

#pragma unroll
        for (int ks = 0; ks < 2; ks++) {
            const int chA = ((ks * 2 + hA) ^ sAx) << 4;
            const int chB = ((ks * 2 + hB) ^ sBx) << 4;
            uint32_t ah[2][4], al[2][4], bh[4][4];
#pragma unroll
            for (int mt = 0; mt < 2; mt++)
                ldsm4(ah[mt][0], ah[mt][1], ah[mt][2], ah[mt][3],
                      st + 0 + (rA + mt * 16) * 64 + chA);
#pragma unroll
            for (int g = 0; g < 4; g++)
                ldsm4(bh[g][0], bh[g][1], bh[g][2], bh[g][3],
                      st + BOFF + (rB + g * 16) * 64 + chB);
#pragma unroll
            for (int mt = 0; mt < 2; mt++)
#pragma unroll
                for (int nt = 0; nt < 8; nt++)
                    mma16816h(acc[mt][nt], ah[mt],
                              bh[nt >> 1][(nt & 1) * 2], bh[nt >> 1][(nt & 1) * 2 + 1]);
            if (TWOP) {
#pragma unroll
                for (int mt = 0; mt < 2; mt++)
                    ldsm4(al[mt][0], al[mt][1], al[mt][2], al[mt][3],
                          st + 8192 + (rA + mt * 16) * 64 + chA);
#pragma unroll
                for (int mt = 0; mt < 2; mt++)
#pragma unroll
                    for (int nt = 0; nt < 8; nt++)
                        mma16816h(acc[mt][nt], al[mt],
                                  bh[nt >> 1][(nt & 1) * 2], bh[nt >> 1][(nt & 1) * 2 + 1]);
            }
        }
        s_cur = (s_cur == 2) ? 0 : s_cur + 1;
        s_nxt = (s_nxt == 2) ? 0 : s_nxt + 1;
    }

    // epilogue
#pragma unroll
    for (int mt = 0; mt < 2; mt++) {
        const int mrow = m0 + wm + mt * 16 + (lane >> 2);
#pragma unroll
        for (int nt = 0; nt < 8; nt++) {
            const int ncol = n0 + wn + nt * 8 + 2 * (lane & 3);
            float* cc = acc[mt][nt];
            if (EPI == 0) {
                float2 v0 = make_float2(fmaxf(cc[0], 0.f), fmaxf(cc[1], 0.f));
                float2 v1 = make_float2(fmaxf(cc[2], 0.f), fmaxf(cc[3], 0.f));
                *(float2*)(out + (size_t)mrow * ldo + ncol) = v0;
                *(float2*)(out + (size_t)(mrow + 8) * ldo + ncol) = v1;
            } else {
                if (ncol < NCAT) {
                    float bv = bias[ncol];
                    out[(size_t)mrow * ldo + ncol] = cc[0] + bv;
                    out[(size_t)(mrow + 8) * ldo + ncol] = cc[2] + bv;
                }
                if (ncol + 1 < NCAT) {
                    float bv = bias[ncol + 1];
                    out[(size_t)mrow * ldo + ncol + 1] = cc[1] + bv;
                    out[(size_t)(mrow + 8) * ldo + ncol + 1] = cc[3] + bv;
                }
            }
        }
    }
}

// ==============================================================================
// Leaf kernel: normalize comb row, emit GEMM2 A fp16 row, rfft -> g_spec.
// ==============================================================================
__global__ void __launch_bounds__(128) leaf_kernel(const int* __restrict__ opos)
{
    const int row = blockIdx.x;          // 0..16383
    const int b = row >> 6;
    const int dst = opos[(row << 1) + 0];
    const int src = opos[(row << 1) + 1];
    const int tid = threadIdx.x;

    __shared__ float2 sZ[256];
    __shared__ float2 stw[128];
    __shared__ float2 sw5[256];
    __shared__ float ws[4];

    stw[tid] = g_twf[tid];
    sw5[tid] = g_w512f[tid];
    sw5[tid + 128] = g_w512f[tid + 128];

    const float4* cp = (const float4*)(g_comb + ((size_t)(b * SEQ + src)) * HID);
    float4 v = cp[tid];
    float ss = v.x*v.x + v.y*v.y + v.z*v.z + v.w*v.w;
#pragma unroll
    for (int o = 16; o; o >>= 1) ss += __shfl_xor_sync(0xffffffffu, ss, o);
    if ((tid & 31) == 0) ws[tid >> 5] = ss;
    __syncthreads();
    float sc = 1.f / (sqrtf(ws[0] + ws[1] + ws[2] + ws[3]) + 1e-6f);
    v = make_float4(v.x*sc, v.y*sc, v.z*sc, v.w*sc);

    const size_t nrow = (size_t)(b * MAXN + dst);
    {
        uint32_t* rh = (uint32_t*)(g_a2h + nrow * HID);
        rh[2*tid]     = f2h2(v.x, v.y);
        rh[2*tid + 1] = f2h2(v.z, v.w);
    }

    sZ[2*tid]     = make_float2(v.x, v.y);
    sZ[2*tid + 1] = make_float2(v.z, v.w);
    __syncthreads();

#pragma unroll
    for (int s = 0; s < 8; s++) {
        const int half = 128 >> s;
        const int j = tid & (half - 1);
        const int p0 = (tid / half) * (half * 2) + j;
        const int p1 = p0 + half;
        float2 w = stw[j << s];
        float2 u = sZ[p0], vv = sZ[p1];
        sZ[p0] = make_float2(u.x + vv.x, u.y + vv.y);
        float dx = u.x - vv.x, dy = u.y - vv.y;
        sZ[p1] = make_float2(dx * w.x - dy * w.y, dx * w.y + dy * w.x);
        __syncthreads();
    }

    float* spec = g_spec + nrow * SPST;
#pragma unroll
    for (int h = 0; h < 2; h++) {
        int k = tid + h * 128;
        int kb = __brev((unsigned)k) >> 24;
        int km = __brev((unsigned)((256 - k) & 255)) >> 24;
        float2 Zk = sZ[kb], Zm = sZ[km];
        float er = 0.5f * (Zk.x + Zm.x);
        float ei = 0.5f * (Zk.y - Zm.y);
        float orr = 0.5f * (Zk.y + Zm.y);
        float oii = -0.5f * (Zk.x - Zm.x);
        float2 w = sw5[k];
        float2 X = make_float2(er + w.x * orr - w.y * oii,
                               ei + w.x * oii + w.y * orr);
        *(float2*)(spec + 2 * k) = X;
    }
    if (tid == 0)
        *(float2*)(spec + 512) = make_float2(sZ[0].x - sZ[0].y, 0.f);
}

// ==============================================================================
// Chain (spectral): one block per batch. All 64 leaf spectra cached in smem;
// F carried in registers. Gmem fallback only for non-leaf operands.
// Dynamic smem: [0,133120) leaf cache; +133120 ws[4]; +133136 sInfo[252].
// ==============================================================================
#define CHAIN_SMEM (64 * 2080 + 16 + NSTEP * 4 * 4)

__global__ void __launch_bounds__(128) chain_spec_kernel(const int* __restrict__ cinfo)
{
    extern __shared__ __align__(16) char csm[];
    float2* cache = (float2*)csm;                       // 64 rows x 260 float2
    float*  ws    = (float*)(csm + 64 * 2080);          // 4 floats
    int*    sInfo = (int*)(csm + 64 * 2080 + 16);       // 252 ints

    const int b = blockIdx.x;
    const int tid = threadIdx.x;
    const size_t nbase = (size_t)b * MAXN;

    for (int i = tid; i < NSTEP * 4; i += 128) sInfo[i] = cinfo[(size_t)b * NSTEP * 4 + i];

    // preload all 64 leaf spectra (contiguous 133120 B)
    {
        const float* src = g_spec + nbase * SPST;
        uint32_t dst = smem_u32(cache);
        for (int i = tid; i < 8320; i += 128) cpasync16(dst + i * 16, src + i * 4);
        asm volatile("cp.async.commit_group;" ::: "memory");
        asm volatile("cp.async.wait_group 0;" ::: "memory");
    }
    __syncthreads();

    float2 F0 = make_float2(0.f, 0.f), F1 = F0, F2 = F0;   // F2 valid on tid 0
    int prev_p = -1;

    for (int k = 0; k < NSTEP; k++) {
        const int t = sInfo[k*4 + 0];
        const int p = sInfo[k*4 + 1];
        const int l = sInfo[k*4 + 2];
        const int r = sInfo[k*4 + 3];

        if (l != prev_p) {
            if (l < 64) {
                F0 = cache[l * 260 + tid];
                F1 = cache[l * 260 + tid + 128];
                if (tid == 0) F2 = cache[l * 260 + 256];
            } else {
                const float2* fr = (const float2*)(g_spec + (nbase + l) * SPST);
                F0 = fr[tid]; F1 = fr[tid + 128];
                if (tid == 0) F2 = fr[256];
            }
        }
        float2 G0, G1, G2 = make_float2(0.f, 0.f);
        if (r < 64) {
            G0 = cache[r * 260 + tid];
            G1 = cache[r * 260 + tid + 128];
            if (tid == 0) G2 = cache[r * 260 + 256];
        } else {
            const float2* gr = (const float2*)(g_spec + (nbase + r) * SPST);
            G0 = gr[tid]; G1 = gr[tid + 128];
            if (tid == 0) G2 = gr[256];
        }

        float* specP = g_spec + (nbase + p) * SPST;

        if (t == 2) {
            float2 c0 = make_float2(F0.x*G0.x + F0.y*G0.y, F0.x*G0.y - F0.y*G0.x);
            float2 c1 = make_float2(F1.x*G1.x + F1.y*G1.y, F1.x*G1.y - F1.y*G1.x);
            float w0 = (tid == 0) ? 1.f : 2.f;
            float part = w0 * (c0.x*c0.x + c0.y*c0.y) + 2.f * (c1.x*c1.x + c1.y*c1.y);
            float2 c2 = make_float2(0.f, 0.f);
            if (tid == 0) {
                c2 = make_float2(F2.x*G2.x + F2.y*G2.y, F2.x*G2.y - F2.y*G2.x);
                part += c2.x*c2.x + c2.y*c2.y;
            }
#pragma unroll
            for (int o = 16; o; o >>= 1) part += __shfl_xor_sync(0xffffffffu, part, o);
            if ((tid & 31) == 0) ws[tid >> 5] = part;
            __syncthreads();
            float s = 1.f / (sqrtf((ws[0] + ws[1] + ws[2] + ws[3]) * (1.f / 512.f)) + 1e-6f);

            F0 = make_float2(s * c0.x, s * c0.y);
            F1 = make_float2(s * c1.x, s * c1.y);
            *(float2*)(specP + 2 * tid) = F0;
            *(float2*)(specP + 2 * (tid + 128)) = F1;
            if (tid == 0) {
                F2 = make_float2(s * c2.x, s * c2.y);
                *(float2*)(specP + 512) = F2;
            }
        } else if (t == 1) {
            *(float2*)(specP + 2 * tid) = F0;
            *(float2*)(specP + 2 * (tid + 128)) = F1;
            if (tid == 0) *(float2*)(specP + 512) = F2;
        } else {
            float2 z = make_float2(0.f, 0.f);
            F0 = z; F1 = z; F2 = z;
            *(float2*)(specP + 2 * tid) = z;
            *(float2*)(specP + 2 * (tid + 128)) = z;
            if (tid == 0) *(float2*)(specP + 512) = z;
        }
        prev_p = p;
        __syncthreads();   // orders specP stores + ws reuse across steps
    }
}

// ==============================================================================
// irfft of the 63 internal nodes per batch -> GEMM2 A fp16 rows.
// ==============================================================================
__global__ void __launch_bounds__(128) irfft_nodes_kernel()
{
    const int idx = blockIdx.x;               // 0..16127
    const int b = idx / NSTEP, i = idx - b * NSTEP;
    const int node = 64 + i;
    const int tid = threadIdx.x;
    __shared__ float2 sX[257];
    __shared__ float2 sZ[256];
    __shared__ float2 stw[128];
    __shared__ float2 sw5[256];

    stw[tid] = g_twi[tid];
    sw5[tid] = g_w512i[tid];
    sw5[tid + 128] = g_w512i[tid + 128];

    const size_t nrow = (size_t)(b * MAXN + node);
    const float2* sp = (const float2*)(g_spec + nrow * SPST);
    sX[tid] = sp[tid];
    sX[tid + 128] = sp[tid + 128];
    if (tid == 0) sX[256] = sp[256];
    __syncthreads();

    const float inv512 = 1.f / 512.f;
#pragma unroll
    for (int h = 0; h < 2; h++) {
        int k = tid + h * 128;
        float2 A = sX[k], B = sX[256 - k];
        float er = A.x + B.x;
        float ei = A.y - B.y;
        float dr = A.x - B.x;
        float di = A.y + B.y;
        float2 w = sw5[k];
        float qr = w.x * dr - w.y * di;
        float qi = w.x * di + w.y * dr;
        float2 Z = make_float2(inv512 * (er - qi), inv512 * (ei + qr));
        sZ[__brev((unsigned)k) >> 24] = Z;
    }
    __syncthreads();

#pragma unroll
    for (int s = 0; s < 8; s++) {
        const int half = 1 << s;
        const int j = tid & (half - 1);
        const int p0 = ((tid >> s) << (s + 1)) | j;
        const int p1 = p0 + half;
        float2 w = stw[j << (7 - s)];
        float2 u = sZ[p0], v = sZ[p1];
        float tx = v.x * w.x - v.y * w.y;
        float ty = v.x * w.y + v.y * w.x;
        sZ[p0] = make_float2(u.x + tx, u.y + ty);
        sZ[p1] = make_float2(u.x - tx, u.y - ty);
        __syncthreads();
    }

    uint32_t* rh = (uint32_t*)(g_a2h + nrow * HID);
#pragma unroll
    for (int h = 0; h < 2; h++) {
        int k = tid + h * 128;
        float2 z = sZ[k];
        rh[k] = f2h2(z.x, z.y);
    }
}

// ==============================================================================
extern "C" void kernel_launch(void* const* d_in, const int* in_sizes, int n_in,
                              void* d_out, int out_size)
{
    const float* seq  = (const float*)d_in[0];   // (256,64,1024)
    const float* W1   = (const float*)d_in[1];   // (512,512)
    const float* W2   = (const float*)d_in[2];   // (512,512)
    const float* LW   = (const float*)d_in[3];   // (511,512)
    const float* LB   = (const float*)d_in[4];   // (511,)
    const int*   opos = (const int*)d_in[7];     // (256,64,2)
    const int*   cinf = (const int*)d_in[8];     // (256,63,4)
    float* out = (float*)d_out;                  // (256,127,511)

    float* comb; __half *a2h, *b1h, *b2h;
    cudaGetSymbolAddress((void**)&comb, g_comb);
    cudaGetSymbolAddress((void**)&a2h, g_a2h);
    cudaGetSymbolAddress((void**)&b1h, g_b1h);
    cudaGetSymbolAddress((void**)&b2h, g_b2h);

    cudaFuncSetAttribute(mm_fp16_kernel<0, 0, 1>,
                         cudaFuncAttributeMaxDynamicSharedMemorySize, NSTG * 24576);
    cudaFuncSetAttribute(mm_fp16_kernel<1, 1, 0>,
                         cudaFuncAttributeMaxDynamicSharedMemorySize, NSTG * 16384);
    cudaFuncSetAttribute(chain_spec_kernel,
                         cudaFuncAttributeMaxDynamicSharedMemorySize, CHAIN_SMEM);

    init_tables_kernel<<<1, 256>>>();
    {
        dim3 b(32, 8);
        dim3 g(EMB / 32, HID / 32);
        prep_b1_kernel<<<g, b>>>(W1, W2);
    }
    prep_b2_kernel<<<(512 * HID) / 256, 256>>>(LW);

    // GEMM1: comb = relu(seq @ [W1;W2]); 2-pass fp16, fused fp32->fp16 split
    {
        dim3 g(HID / BN, BSZ * SEQ / BM);         // (4, 128)
        mm_fp16_kernel<0, 0, 1><<<g, 256, NSTG * 24576>>>(
            seq, nullptr, nullptr, b1h, nullptr, comb, EMB, HID);
    }

    leaf_kernel<<<BSZ * SEQ, 128>>>(opos);
    chain_spec_kernel<<<BSZ, 128, CHAIN_SMEM>>>(cinf);
    irfft_nodes_kernel<<<BSZ * NSTEP, 128>>>();

    // GEMM2: out = nodes @ LW^T + LB; single-pass fp16
    {
        dim3 g(512 / BN, BSZ * MAXN / BM);        // (4, 254)
        mm_fp16_kernel<1, 1, 0><<<g, 256, NSTG * 16384>>>(
            nullptr, a2h, nullptr, b2h, LB, out, HID, NCAT);
    }
}

// round 10
// speedup vs baseline: 3.7619x; 1.0885x over previous
#include <cuda_runtime.h>
#include <cuda_fp16.h>
#include <cstdint>

// Problem constants (fixed by setup_inputs)
#define BSZ 256
#define SEQ 64
#define EMB 1024
#define HID 512
#define MAXN 127           // 2*S-1
#define NSTEP 63           // S-1
#define NCAT 511
#define SPST 520           // spec row stride (floats): 257 complex padded

typedef unsigned long long ull;

// ---------------- helpers ------------------------------------------------------
__device__ __forceinline__ uint32_t smem_u32(const void* p) {
    uint32_t a;
    asm("{ .reg .u64 t; cvta.to.shared.u64 t, %1; cvt.u32.u64 %0, t; }" : "=r"(a) : "l"(p));
    return a;
}
__device__ __forceinline__ void cpasync16(uint32_t dst, const void* src) {
    asm volatile("cp.async.cg.shared.global [%0], [%1], 16;" :: "r"(dst), "l"(src) : "memory");
}
__device__ __forceinline__ void ldsm4(uint32_t &d0, uint32_t &d1, uint32_t &d2, uint32_t &d3,
                                      uint32_t addr) {
    asm volatile("ldmatrix.sync.aligned.m8n8.x4.shared.b16 {%0,%1,%2,%3}, [%4];"
                 : "=r"(d0), "=r"(d1), "=r"(d2), "=r"(d3) : "r"(addr));
}
__device__ __forceinline__ void mma16816h(float* c, const uint32_t* a, uint32_t b0, uint32_t b1) {
    asm volatile("mma.sync.aligned.m16n8k16.row.col.f32.f16.f16.f32 "
                 "{%0,%1,%2,%3}, {%4,%5,%6,%7}, {%8,%9}, {%0,%1,%2,%3};"
                 : "+f"(c[0]), "+f"(c[1]), "+f"(c[2]), "+f"(c[3])
                 : "r"(a[0]), "r"(a[1]), "r"(a[2]), "r"(a[3]), "r"(b0), "r"(b1));
}
__device__ __forceinline__ void sts128(uint32_t addr, uint4 v) {
    asm volatile("st.shared.v4.b32 [%0], {%1,%2,%3,%4};"
                 :: "r"(addr), "r"(v.x), "r"(v.y), "r"(v.z), "r"(v.w) : "memory");
}
__device__ __forceinline__ uint32_t f2h2(float a, float b) {
    __half2 t = __float22half2_rn(make_float2(a, b));
    return *(uint32_t*)&t;
}
// round 8 floats to fp16 hi quads (and lo when needed)
__device__ __forceinline__ void split8h(float4 u, float4 v, uint4 &hi, uint4 &lo) {
    hi.x = f2h2(u.x, u.y); hi.y = f2h2(u.z, u.w);
    hi.z = f2h2(v.x, v.y); hi.w = f2h2(v.z, v.w);
    __half2 h;
    h = *(__half2*)&hi.x; float2 f0 = __half22float2(h);
    h = *(__half2*)&hi.y; float2 f1 = __half22float2(h);
    h = *(__half2*)&hi.z; float2 f2 = __half22float2(h);
    h = *(__half2*)&hi.w; float2 f3 = __half22float2(h);
    lo.x = f2h2(u.x - f0.x, u.y - f0.y);
    lo.y = f2h2(u.z - f1.x, u.w - f1.y);
    lo.z = f2h2(v.x - f2.x, v.y - f2.y);
    lo.w = f2h2(v.z - f3.x, v.w - f3.y);
}
__device__ __forceinline__ void round8h(float4 u, float4 v, uint4 &hi) {
    hi.x = f2h2(u.x, u.y); hi.y = f2h2(u.z, u.w);
    hi.z = f2h2(v.x, v.y); hi.w = f2h2(v.z, v.w);
}

// ---------------- scratch (device globals: allocation-free) -------------------
__device__ float g_comb[(size_t)BSZ * SEQ * HID];                 // relu(GEMM1) fp32
__device__ __align__(16) float g_spec[(size_t)BSZ * MAXN * SPST]; // node spectra
__device__ __half g_a2h[(size_t)BSZ * MAXN * HID];                // GEMM2 A fp16
__device__ __half g_b1h[(size_t)HID * EMB];                       // W^T fp16 [n][k]
__device__ __half g_b2h[(size_t)512 * HID];                       // LW fp16 (pad n=512)
__device__ float2 g_twf[128], g_twi[128], g_w512f[256], g_w512i[256];

// ==============================================================================
__global__ void init_tables_kernel()
{
    int t = threadIdx.x;
    const float PI2 = 6.283185307179586f;
    if (t < 128) {
        float th = PI2 * t / 256.0f;
        float s, c; sincosf(th, &s, &c);
        g_twf[t] = make_float2(c, -s);
        g_twi[t] = make_float2(c,  s);
    }
    float ph = PI2 * t / 512.0f;
    float s, c; sincosf(ph, &s, &c);
    g_w512f[t] = make_float2(c, -s);
    g_w512i[t] = make_float2(c,  s);
}

// coalesced tiled transpose: W1/W2 [k][n] -> g_b1h[n][k] fp16
__global__ void prep_b1_kernel(const float* __restrict__ W1, const float* __restrict__ W2)
{
    __shared__ float tile[32][33];
    const int kp0 = blockIdx.x * 32, n0 = blockIdx.y * 32;
    const int tx = threadIdx.x, ty = threadIdx.y;   // 32 x 8
#pragma unroll
    for (int i = 0; i < 32; i += 8) {
        int kp = kp0 + ty + i;
        const float* W = (kp < HID) ? (W1 + (size_t)kp * HID) : (W2 + (size_t)(kp - HID) * HID);
        tile[ty + i][tx] = W[n0 + tx];
    }
    __syncthreads();
#pragma unroll
    for (int i = 0; i < 32; i += 8) {
        int n = n0 + ty + i;
        g_b1h[(size_t)n * EMB + kp0 + tx] = __float2half_rn(tile[tx][ty + i]);
    }
}

__global__ void prep_b2_kernel(const float* __restrict__ LW)
{
    int id = blockIdx.x * 256 + threadIdx.x;              // over 512*512
    int n = id >> 9, k = id & 511;
    float v = (n < NCAT) ? LW[(size_t)n * HID + k] : 0.f;
    g_b2h[id] = __float2half_rn(v);
}

// ==============================================================================
// HMMA fp16 GEMM, 3-stage cp.async ring, one __syncthreads per K-chunk of 32.
// TWOP=1: D = ah*bh + al*bh (A split fp16 hi/lo).  TWOP=0: D = ah*bh.
// AMODE=0: A fp32 with fused round/split. AMODE=1: pre-rounded fp16 A.
// Stage: Ah@0 [, Al@8K], Bh@BOFF; rows 64B, 16B-chunk XOR swizzle.
// ==============================================================================
#define BM 128
#define BN 128
#define NSTG 3

template<int AMODE, int EPI, int TWOP>
__global__ void __launch_bounds__(256, 2) mm_fp16_kernel(
    const float* __restrict__ Af, const __half* __restrict__ Ah, const __half* __restrict__ Al,
    const __half* __restrict__ Bh,
    const float* __restrict__ bias, float* __restrict__ out, int K, int ldo)
{
    constexpr uint32_t BOFF  = TWOP ? 16384 : 8192;
    constexpr uint32_t STGSZ = TWOP ? 24576 : 16384;

    extern __shared__ __align__(16) char smem[];
    const uint32_t sb = smem_u32(smem);

    const int tid  = threadIdx.x;
    const int lane = tid & 31;
    const int wid  = tid >> 5;
    const int wm   = (wid & 3) * 32;
    const int wn   = (wid >> 2) * 64;
    const int n0   = blockIdx.x * BN;
    const int m0   = blockIdx.y * BM;

    float acc[2][8][4];
#pragma unroll
    for (int mt = 0; mt < 2; mt++)
#pragma unroll
        for (int nt = 0; nt < 8; nt++)
#pragma unroll
            for (int i = 0; i < 4; i++) acc[mt][nt][i] = 0.f;

    // loader constants
    const int brow = tid >> 2, bc = tid & 3;
    const int brow2 = (tid + 256) >> 2, bc2 = (tid + 256) & 3;
    const uint32_t bsw1 = brow * 64 + ((bc ^ ((brow >> 1) & 3)) << 4);
    const uint32_t bsw2 = brow2 * 64 + ((bc2 ^ ((brow2 >> 1) & 3)) << 4);
    const int arow = tid >> 1, ahalf = tid & 1;
    const uint32_t asw0 = arow * 64 + (((ahalf * 2 + 0) ^ ((arow >> 1) & 3)) << 4);
    const uint32_t asw1 = arow * 64 + (((ahalf * 2 + 1) ^ ((arow >> 1) & 3)) << 4);

    auto loadB = [&](int kt, uint32_t st) {
        cpasync16(st + BOFF + bsw1, Bh + (size_t)(n0 + brow) * K + kt + bc * 8);
        cpasync16(st + BOFF + bsw2, Bh + (size_t)(n0 + brow2) * K + kt + bc2 * 8);
    };
    auto loadAasync = [&](int kt, uint32_t st) {
        cpasync16(st + 0 + bsw1, Ah + (size_t)(m0 + brow) * K + kt + bc * 8);
        cpasync16(st + 0 + bsw2, Ah + (size_t)(m0 + brow2) * K + kt + bc2 * 8);
        if (TWOP) {
            cpasync16(st + 8192 + bsw1, Al + (size_t)(m0 + brow) * K + kt + bc * 8);
            cpasync16(st + 8192 + bsw2, Al + (size_t)(m0 + brow2) * K + kt + bc2 * 8);
        }
    };

    float4 pr[4];
    auto ldgA = [&](int kt) {
        const float4* src = (const float4*)(Af + (size_t)(m0 + arow) * K + kt + ahalf * 16);
        pr[0] = src[0]; pr[1] = src[1]; pr[2] = src[2]; pr[3] = src[3];
    };
    auto cvtsts = [&](uint32_t st) {
        if (TWOP) {
            uint4 hi, lo;
            split8h(pr[0], pr[1], hi, lo);
            sts128(st + 0 + asw0, hi);
            sts128(st + 8192 + asw0, lo);
            split8h(pr[2], pr[3], hi, lo);
            sts128(st + 0 + asw1, hi);
            sts128(st + 8192 + asw1, lo);
        } else {
            uint4 hi;
            round8h(pr[0], pr[1], hi);
            sts128(st + 0 + asw0, hi);
            round8h(pr[2], pr[3], hi);
            sts128(st + 0 + asw1, hi);
        }
    };

    const int C = K / 32;   // >= 16 here

    // ---- prologue: stages 0,1 in flight; pr holds chunk 2 (AMODE0) ----
    if (AMODE == 0) {
        ldgA(0);  cvtsts(sb + 0 * STGSZ);
        ldgA(32); cvtsts(sb + 1 * STGSZ);
        ldgA(64);
    }
    loadB(0, sb + 0 * STGSZ);
    if (AMODE == 1) loadAasync(0, sb + 0 * STGSZ);
    asm volatile("cp.async.commit_group;" ::: "memory");
    loadB(32, sb + 1 * STGSZ);
    if (AMODE == 1) loadAasync(32, sb + 1 * STGSZ);
    asm volatile("cp.async.commit_group;" ::: "memory");

    // ldmatrix constants
    const int rA  = wm + (lane & 15);
    const int hA  = lane >> 4;
    const int sAx = (rA >> 1) & 3;
    const int rB  = wn + (lane & 7) + ((lane >> 4) << 3);
    const int hB  = (lane >> 3) & 1;
    const int sBx = (rB >> 1) & 3;

    int s_cur = 0, s_nxt = 2;
    for (int c = 0; c < C; c++) {
        asm volatile("cp.async.wait_group 1;" ::: "memory");
        __syncthreads();

        const uint32_t st = sb + s_cur * STGSZ;
        const uint32_t nx = sb + s_nxt * STGSZ;
        if (c + 2 < C) {
            loadB((c + 2) * 32, nx);
            if (AMODE == 1) loadAasync((c + 2) * 32, nx);
            if (AMODE == 0) {
                cvtsts(nx);
                if (c + 3 < C) ldgA((c + 3) * 32);
            }
        }
        asm volatile("cp.async.commit_group;" ::: "memory");

#pragma unroll
        for (int ks = 0; ks < 2; ks++) {
            const int chA = ((ks * 2 + hA) ^ sAx) << 4;
            const int chB = ((ks * 2 + hB) ^ sBx) << 4;
            uint32_t ah[2][4], al[2][4], bh[4][4];
#pragma unroll
            for (int mt = 0; mt < 2; mt++)
                ldsm4(ah[mt][0], ah[mt][1], ah[mt][2], ah[mt][3],
                      st + 0 + (rA + mt * 16) * 64 + chA);
#pragma unroll
            for (int g = 0; g < 4; g++)
                ldsm4(bh[g][0], bh[g][1], bh[g][2], bh[g][3],
                      st + BOFF + (rB + g * 16) * 64 + chB);
#pragma unroll
            for (int mt = 0; mt < 2; mt++)
#pragma unroll
                for (int nt = 0; nt < 8; nt++)
                    mma16816h(acc[mt][nt], ah[mt],
                              bh[nt >> 1][(nt & 1) * 2], bh[nt >> 1][(nt & 1) * 2 + 1]);
            if (TWOP) {
#pragma unroll
                for (int mt = 0; mt < 2; mt++)
                    ldsm4(al[mt][0], al[mt][1], al[mt][2], al[mt][3],
                          st + 8192 + (rA + mt * 16) * 64 + chA);
#pragma unroll
                for (int mt = 0; mt < 2; mt++)
#pragma unroll
                    for (int nt = 0; nt < 8; nt++)
                        mma16816h(acc[mt][nt], al[mt],
                                  bh[nt >> 1][(nt & 1) * 2], bh[nt >> 1][(nt & 1) * 2 + 1]);
            }
        }
        s_cur = (s_cur == 2) ? 0 : s_cur + 1;
        s_nxt = (s_nxt == 2) ? 0 : s_nxt + 1;
    }

    // epilogue
#pragma unroll
    for (int mt = 0; mt < 2; mt++) {
        const int mrow = m0 + wm + mt * 16 + (lane >> 2);
#pragma unroll
        for (int nt = 0; nt < 8; nt++) {
            const int ncol = n0 + wn + nt * 8 + 2 * (lane & 3);
            float* cc = acc[mt][nt];
            if (EPI == 0) {
                float2 v0 = make_float2(fmaxf(cc[0], 0.f), fmaxf(cc[1], 0.f));
                float2 v1 = make_float2(fmaxf(cc[2], 0.f), fmaxf(cc[3], 0.f));
                *(float2*)(out + (size_t)mrow * ldo + ncol) = v0;
                *(float2*)(out + (size_t)(mrow + 8) * ldo + ncol) = v1;
            } else {
                if (ncol < NCAT) {
                    float bv = bias[ncol];
                    out[(size_t)mrow * ldo + ncol] = cc[0] + bv;
                    out[(size_t)(mrow + 8) * ldo + ncol] = cc[2] + bv;
                }
                if (ncol + 1 < NCAT) {
                    float bv = bias[ncol + 1];
                    out[(size_t)mrow * ldo + ncol + 1] = cc[1] + bv;
                    out[(size_t)(mrow + 8) * ldo + ncol + 1] = cc[3] + bv;
                }
            }
        }
    }
}

// ==============================================================================
// Leaf kernel: normalize comb row, emit GEMM2 A fp16 row, rfft -> g_spec.
// ==============================================================================
__global__ void __launch_bounds__(128) leaf_kernel(const int* __restrict__ opos)
{
    const int row = blockIdx.x;          // 0..16383
    const int b = row >> 6;
    const int dst = opos[(row << 1) + 0];
    const int src = opos[(row << 1) + 1];
    const int tid = threadIdx.x;

    __shared__ float2 sZ[256];
    __shared__ float2 stw[128];
    __shared__ float2 sw5[256];
    __shared__ float ws[4];

    stw[tid] = g_twf[tid];
    sw5[tid] = g_w512f[tid];
    sw5[tid + 128] = g_w512f[tid + 128];

    const float4* cp = (const float4*)(g_comb + ((size_t)(b * SEQ + src)) * HID);
    float4 v = cp[tid];
    float ss = v.x*v.x + v.y*v.y + v.z*v.z + v.w*v.w;
#pragma unroll
    for (int o = 16; o; o >>= 1) ss += __shfl_xor_sync(0xffffffffu, ss, o);
    if ((tid & 31) == 0) ws[tid >> 5] = ss;
    __syncthreads();
    float sc = 1.f / (sqrtf(ws[0] + ws[1] + ws[2] + ws[3]) + 1e-6f);
    v = make_float4(v.x*sc, v.y*sc, v.z*sc, v.w*sc);

    const size_t nrow = (size_t)(b * MAXN + dst);
    {
        uint32_t* rh = (uint32_t*)(g_a2h + nrow * HID);
        rh[2*tid]     = f2h2(v.x, v.y);
        rh[2*tid + 1] = f2h2(v.z, v.w);
    }

    sZ[2*tid]     = make_float2(v.x, v.y);
    sZ[2*tid + 1] = make_float2(v.z, v.w);
    __syncthreads();

#pragma unroll
    for (int s = 0; s < 8; s++) {
        const int half = 128 >> s;
        const int j = tid & (half - 1);
        const int p0 = (tid / half) * (half * 2) + j;
        const int p1 = p0 + half;
        float2 w = stw[j << s];
        float2 u = sZ[p0], vv = sZ[p1];
        sZ[p0] = make_float2(u.x + vv.x, u.y + vv.y);
        float dx = u.x - vv.x, dy = u.y - vv.y;
        sZ[p1] = make_float2(dx * w.x - dy * w.y, dx * w.y + dy * w.x);
        __syncthreads();
    }

    float* spec = g_spec + nrow * SPST;
#pragma unroll
    for (int h = 0; h < 2; h++) {
        int k = tid + h * 128;
        int kb = __brev((unsigned)k) >> 24;
        int km = __brev((unsigned)((256 - k) & 255)) >> 24;
        float2 Zk = sZ[kb], Zm = sZ[km];
        float er = 0.5f * (Zk.x + Zm.x);
        float ei = 0.5f * (Zk.y - Zm.y);
        float orr = 0.5f * (Zk.y + Zm.y);
        float oii = -0.5f * (Zk.x - Zm.x);
        float2 w = sw5[k];
        float2 X = make_float2(er + w.x * orr - w.y * oii,
                               ei + w.x * oii + w.y * orr);
        *(float2*)(spec + 2 * k) = X;
    }
    if (tid == 0)
        *(float2*)(spec + 512) = make_float2(sZ[0].x - sZ[0].y, 0.f);
}

// ==============================================================================
// Chain (spectral): one block per batch. All 64 leaf spectra cached in smem;
// F carried in registers. Gmem fallback only for non-leaf operands.
// ==============================================================================
#define CHAIN_SMEM (64 * 2080 + 16 + NSTEP * 4 * 4)

__global__ void __launch_bounds__(128) chain_spec_kernel(const int* __restrict__ cinfo)
{
    extern __shared__ __align__(16) char csm[];
    float2* cache = (float2*)csm;                       // 64 rows x 260 float2
    float*  ws    = (float*)(csm + 64 * 2080);          // 4 floats
    int*    sInfo = (int*)(csm + 64 * 2080 + 16);       // 252 ints

    const int b = blockIdx.x;
    const int tid = threadIdx.x;
    const size_t nbase = (size_t)b * MAXN;

    for (int i = tid; i < NSTEP * 4; i += 128) sInfo[i] = cinfo[(size_t)b * NSTEP * 4 + i];

    // preload all 64 leaf spectra (contiguous 133120 B)
    {
        const float* src = g_spec + nbase * SPST;
        uint32_t dst = smem_u32(cache);
        for (int i = tid; i < 8320; i += 128) cpasync16(dst + i * 16, src + i * 4);
        asm volatile("cp.async.commit_group;" ::: "memory");
        asm volatile("cp.async.wait_group 0;" ::: "memory");
    }
    __syncthreads();

    float2 F0 = make_float2(0.f, 0.f), F1 = F0, F2 = F0;   // F2 valid on tid 0
    int prev_p = -1;

    for (int k = 0; k < NSTEP; k++) {
        const int t = sInfo[k*4 + 0];
        const int p = sInfo[k*4 + 1];
        const int l = sInfo[k*4 + 2];
        const int r = sInfo[k*4 + 3];

        if (l != prev_p) {
            if (l < 64) {
                F0 = cache[l * 260 + tid];
                F1 = cache[l * 260 + tid + 128];
                if (tid == 0) F2 = cache[l * 260 + 256];
            } else {
                const float2* fr = (const float2*)(g_spec + (nbase + l) * SPST);
                F0 = fr[tid]; F1 = fr[tid + 128];
                if (tid == 0) F2 = fr[256];
            }
        }
        float2 G0, G1, G2 = make_float2(0.f, 0.f);
        if (r < 64) {
            G0 = cache[r * 260 + tid];
            G1 = cache[r * 260 + tid + 128];
            if (tid == 0) G2 = cache[r * 260 + 256];
        } else {
            const float2* gr = (const float2*)(g_spec + (nbase + r) * SPST);
            G0 = gr[tid]; G1 = gr[tid + 128];
            if (tid == 0) G2 = gr[256];
        }

        float* specP = g_spec + (nbase + p) * SPST;

        if (t == 2) {
            float2 c0 = make_float2(F0.x*G0.x + F0.y*G0.y, F0.x*G0.y - F0.y*G0.x);
            float2 c1 = make_float2(F1.x*G1.x + F1.y*G1.y, F1.x*G1.y - F1.y*G1.x);
            float w0 = (tid == 0) ? 1.f : 2.f;
            float part = w0 * (c0.x*c0.x + c0.y*c0.y) + 2.f * (c1.x*c1.x + c1.y*c1.y);
            float2 c2 = make_float2(0.f, 0.f);
            if (tid == 0) {
                c2 = make_float2(F2.x*G2.x + F2.y*G2.y, F2.x*G2.y - F2.y*G2.x);
                part += c2.x*c2.x + c2.y*c2.y;
            }
#pragma unroll
            for (int o = 16; o; o >>= 1) part += __shfl_xor_sync(0xffffffffu, part, o);
            if ((tid & 31) == 0) ws[tid >> 5] = part;
            __syncthreads();
            float s = 1.f / (sqrtf((ws[0] + ws[1] + ws[2] + ws[3]) * (1.f / 512.f)) + 1e-6f);

            F0 = make_float2(s * c0.x, s * c0.y);
            F1 = make_float2(s * c1.x, s * c1.y);
            *(float2*)(specP + 2 * tid) = F0;
            *(float2*)(specP + 2 * (tid + 128)) = F1;
            if (tid == 0) {
                F2 = make_float2(s * c2.x, s * c2.y);
                *(float2*)(specP + 512) = F2;
            }
        } else if (t == 1) {
            *(float2*)(specP + 2 * tid) = F0;
            *(float2*)(specP + 2 * (tid + 128)) = F1;
            if (tid == 0) *(float2*)(specP + 512) = F2;
        } else {
            float2 z = make_float2(0.f, 0.f);
            F0 = z; F1 = z; F2 = z;
            *(float2*)(specP + 2 * tid) = z;
            *(float2*)(specP + 2 * (tid + 128)) = z;
            if (tid == 0) *(float2*)(specP + 512) = z;
        }
        prev_p = p;
        __syncthreads();
    }
}

// ==============================================================================
// irfft of the 63 internal nodes per batch -> GEMM2 A fp16 rows.
// ==============================================================================
__global__ void __launch_bounds__(128) irfft_nodes_kernel()
{
    const int idx = blockIdx.x;               // 0..16127
    const int b = idx / NSTEP, i = idx - b * NSTEP;
    const int node = 64 + i;
    const int tid = threadIdx.x;
    __shared__ float2 sX[257];
    __shared__ float2 sZ[256];
    __shared__ float2 stw[128];
    __shared__ float2 sw5[256];

    stw[tid] = g_twi[tid];
    sw5[tid] = g_w512i[tid];
    sw5[tid + 128] = g_w512i[tid + 128];

    const size_t nrow = (size_t)(b * MAXN + node);
    const float2* sp = (const float2*)(g_spec + nrow * SPST);
    sX[tid] = sp[tid];
    sX[tid + 128] = sp[tid + 128];
    if (tid == 0) sX[256] = sp[256];
    __syncthreads();

    const float inv512 = 1.f / 512.f;
#pragma unroll
    for (int h = 0; h < 2; h++) {
        int k = tid + h * 128;
        float2 A = sX[k], B = sX[256 - k];
        float er = A.x + B.x;
        float ei = A.y - B.y;
        float dr = A.x - B.x;
        float di = A.y + B.y;
        float2 w = sw5[k];
        float qr = w.x * dr - w.y * di;
        float qi = w.x * di + w.y * dr;
        float2 Z = make_float2(inv512 * (er - qi), inv512 * (ei + qr));
        sZ[__brev((unsigned)k) >> 24] = Z;
    }
    __syncthreads();

#pragma unroll
    for (int s = 0; s < 8; s++) {
        const int half = 1 << s;
        const int j = tid & (half - 1);
        const int p0 = ((tid >> s) << (s + 1)) | j;
        const int p1 = p0 + half;
        float2 w = stw[j << (7 - s)];
        float2 u = sZ[p0], v = sZ[p1];
        float tx = v.x * w.x - v.y * w.y;
        float ty = v.x * w.y + v.y * w.x;
        sZ[p0] = make_float2(u.x + tx, u.y + ty);
        sZ[p1] = make_float2(u.x - tx, u.y - ty);
        __syncthreads();
    }

    uint32_t* rh = (uint32_t*)(g_a2h + nrow * HID);
#pragma unroll
    for (int h = 0; h < 2; h++) {
        int k = tid + h * 128;
        float2 z = sZ[k];
        rh[k] = f2h2(z.x, z.y);
    }
}

// ==============================================================================
extern "C" void kernel_launch(void* const* d_in, const int* in_sizes, int n_in,
                              void* d_out, int out_size)
{
    const float* seq  = (const float*)d_in[0];   // (256,64,1024)
    const float* W1   = (const float*)d_in[1];   // (512,512)
    const float* W2   = (const float*)d_in[2];   // (512,512)
    const float* LW   = (const float*)d_in[3];   // (511,512)
    const float* LB   = (const float*)d_in[4];   // (511,)
    const int*   opos = (const int*)d_in[7];     // (256,64,2)
    const int*   cinf = (const int*)d_in[8];     // (256,63,4)
    float* out = (float*)d_out;                  // (256,127,511)

    float* comb; __half *a2h, *b1h, *b2h;
    cudaGetSymbolAddress((void**)&comb, g_comb);
    cudaGetSymbolAddress((void**)&a2h, g_a2h);
    cudaGetSymbolAddress((void**)&b1h, g_b1h);
    cudaGetSymbolAddress((void**)&b2h, g_b2h);

    cudaFuncSetAttribute(mm_fp16_kernel<0, 0, 0>,
                         cudaFuncAttributeMaxDynamicSharedMemorySize, NSTG * 16384);
    cudaFuncSetAttribute(mm_fp16_kernel<1, 1, 0>,
                         cudaFuncAttributeMaxDynamicSharedMemorySize, NSTG * 16384);
    cudaFuncSetAttribute(chain_spec_kernel,
                         cudaFuncAttributeMaxDynamicSharedMemorySize, CHAIN_SMEM);

    init_tables_kernel<<<1, 256>>>();
    {
        dim3 b(32, 8);
        dim3 g(EMB / 32, HID / 32);
        prep_b1_kernel<<<g, b>>>(W1, W2);
    }
    prep_b2_kernel<<<(512 * HID) / 256, 256>>>(LW);

    // GEMM1: comb = relu(seq @ [W1;W2]); single-pass fp16, fused round in loader
    {
        dim3 g(HID / BN, BSZ * SEQ / BM);         // (4, 128)
        mm_fp16_kernel<0, 0, 0><<<g, 256, NSTG * 16384>>>(
            seq, nullptr, nullptr, b1h, nullptr, comb, EMB, HID);
    }

    leaf_kernel<<<BSZ * SEQ, 128>>>(opos);
    chain_spec_kernel<<<BSZ, 128, CHAIN_SMEM>>>(cinf);
    irfft_nodes_kernel<<<BSZ * NSTEP, 128>>>();

    // GEMM2: out = nodes @ LW^T + LB; single-pass fp16
    {
        dim3 g(512 / BN, BSZ * MAXN / BM);        // (4, 254)
        mm_fp16_kernel<1, 1, 0><<<g, 256, NSTG * 16384>>>(
            nullptr, a2h, nullptr, b2h, LB, out, HID, NCAT);
    }
}

// round 11
// speedup vs baseline: 3.8367x; 1.0199x over previous
#include <cuda_runtime.h>
#include <cuda_fp16.h>
#include <cstdint>

// Problem constants (fixed by setup_inputs)
#define BSZ 256
#define SEQ 64
#define EMB 1024
#define HID 512
#define MAXN 127           // 2*S-1
#define NSTEP 63           // S-1
#define NCAT 511
#define SPST 520           // spec row stride (floats): 257 complex padded

typedef unsigned long long ull;

// ---------------- helpers ------------------------------------------------------
__device__ __forceinline__ uint32_t smem_u32(const void* p) {
    uint32_t a;
    asm("{ .reg .u64 t; cvta.to.shared.u64 t, %1; cvt.u32.u64 %0, t; }" : "=r"(a) : "l"(p));
    return a;
}
__device__ __forceinline__ void cpasync16(uint32_t dst, const void* src) {
    asm volatile("cp.async.cg.shared.global [%0], [%1], 16;" :: "r"(dst), "l"(src) : "memory");
}
__device__ __forceinline__ void ldsm4(uint32_t &d0, uint32_t &d1, uint32_t &d2, uint32_t &d3,
                                      uint32_t addr) {
    asm volatile("ldmatrix.sync.aligned.m8n8.x4.shared.b16 {%0,%1,%2,%3}, [%4];"
                 : "=r"(d0), "=r"(d1), "=r"(d2), "=r"(d3) : "r"(addr));
}
__device__ __forceinline__ void mma16816h(float* c, const uint32_t* a, uint32_t b0, uint32_t b1) {
    asm volatile("mma.sync.aligned.m16n8k16.row.col.f32.f16.f16.f32 "
                 "{%0,%1,%2,%3}, {%4,%5,%6,%7}, {%8,%9}, {%0,%1,%2,%3};"
                 : "+f"(c[0]), "+f"(c[1]), "+f"(c[2]), "+f"(c[3])
                 : "r"(a[0]), "r"(a[1]), "r"(a[2]), "r"(a[3]), "r"(b0), "r"(b1));
}
__device__ __forceinline__ uint32_t f2h2(float a, float b) {
    __half2 t = __float22half2_rn(make_float2(a, b));
    return *(uint32_t*)&t;
}

// ---------------- scratch (device globals: allocation-free) -------------------
__device__ float g_comb[(size_t)BSZ * SEQ * HID];                 // relu(GEMM1) fp32
__device__ __align__(16) float g_spec[(size_t)BSZ * MAXN * SPST]; // node spectra
__device__ __half g_a1h[(size_t)BSZ * SEQ * EMB];                 // seq fp16
__device__ __half g_a2h[(size_t)BSZ * MAXN * HID];                // GEMM2 A fp16
__device__ __half g_b1h[(size_t)HID * EMB];                       // W^T fp16 [n][k]
__device__ __half g_b2h[(size_t)512 * HID];                       // LW fp16 (pad n=512)
__device__ float2 g_twf[128], g_twi[128], g_w512f[256], g_w512i[256];

// ==============================================================================
__global__ void init_tables_kernel()
{
    int t = threadIdx.x;
    const float PI2 = 6.283185307179586f;
    if (t < 128) {
        float th = PI2 * t / 256.0f;
        float s, c; sincosf(th, &s, &c);
        g_twf[t] = make_float2(c, -s);
        g_twi[t] = make_float2(c,  s);
    }
    float ph = PI2 * t / 512.0f;
    float s, c; sincosf(ph, &s, &c);
    g_w512f[t] = make_float2(c, -s);
    g_w512i[t] = make_float2(c,  s);
}

// seq fp32 -> fp16 (streaming convert)
__global__ void prep_a1_kernel(const float* __restrict__ seq)
{
    size_t idx = (size_t)blockIdx.x * 256 + threadIdx.x;   // float4 index
    float4 v = ((const float4*)seq)[idx];
    uint2 o;
    o.x = f2h2(v.x, v.y);
    o.y = f2h2(v.z, v.w);
    ((uint2*)g_a1h)[idx] = o;
}

// coalesced tiled transpose: W1/W2 [k][n] -> g_b1h[n][k] fp16
__global__ void prep_b1_kernel(const float* __restrict__ W1, const float* __restrict__ W2)
{
    __shared__ float tile[32][33];
    const int kp0 = blockIdx.x * 32, n0 = blockIdx.y * 32;
    const int tx = threadIdx.x, ty = threadIdx.y;   // 32 x 8
#pragma unroll
    for (int i = 0; i < 32; i += 8) {
        int kp = kp0 + ty + i;
        const float* W = (kp < HID) ? (W1 + (size_t)kp * HID) : (W2 + (size_t)(kp - HID) * HID);
        tile[ty + i][tx] = W[n0 + tx];
    }
    __syncthreads();
#pragma unroll
    for (int i = 0; i < 32; i += 8) {
        int n = n0 + ty + i;
        g_b1h[(size_t)n * EMB + kp0 + tx] = __float2half_rn(tile[tx][ty + i]);
    }
}

__global__ void prep_b2_kernel(const float* __restrict__ LW)
{
    int id = blockIdx.x * 256 + threadIdx.x;              // over 512*512
    int n = id >> 9, k = id & 511;
    float v = (n < NCAT) ? LW[(size_t)n * HID + k] : 0.f;
    g_b2h[id] = __float2half_rn(v);
}

// ==============================================================================
// HMMA fp16 GEMM: D = A@B^T (both fp16), 128 threads, warps 2m x 2n, 64x64 tiles.
// 3-stage cp.async ring, one __syncthreads per K-chunk of 32.
// Stage (16KB): A@0, B@8K; rows 64B, 16B-chunk XOR swizzle.
// EPI=0: relu -> out. EPI=1: +bias, n<NCAT guard.
// ==============================================================================
#define BM 128
#define BN 128
#define STGSZ 16384
#define NSTG 3

template<int EPI>
__global__ void __launch_bounds__(128, 2) mm_fp16_kernel(
    const __half* __restrict__ Ah, const __half* __restrict__ Bh,
    const float* __restrict__ bias, float* __restrict__ out, int K, int ldo)
{
    extern __shared__ __align__(16) char smem[];
    const uint32_t sb = smem_u32(smem);

    const int tid  = threadIdx.x;
    const int lane = tid & 31;
    const int wid  = tid >> 5;           // 0..3
    const int wm   = (wid & 1) * 64;
    const int wn   = (wid >> 1) * 64;
    const int n0   = blockIdx.x * BN;
    const int m0   = blockIdx.y * BM;

    float acc[4][8][4];
#pragma unroll
    for (int mt = 0; mt < 4; mt++)
#pragma unroll
        for (int nt = 0; nt < 8; nt++)
#pragma unroll
            for (int i = 0; i < 4; i++) acc[mt][nt][i] = 0.f;

    // loader: 128 threads x 4 chunks cover one 8KB tile (512 x 16B)
    int lrow[4]; uint32_t lsw[4];
#pragma unroll
    for (int i = 0; i < 4; i++) {
        int idx = tid + i * 128;
        int row = idx >> 2, cc = idx & 3;
        lrow[i] = row;
        lsw[i] = row * 64 + ((cc ^ ((row >> 1) & 3)) << 4) + (cc * 0);
    }
    int lcc[4];
#pragma unroll
    for (int i = 0; i < 4; i++) lcc[i] = (tid + i * 128) & 3;

    auto loadTile = [&](int kt, uint32_t st) {
#pragma unroll
        for (int i = 0; i < 4; i++) {
            cpasync16(st + lsw[i],        Ah + (size_t)(m0 + lrow[i]) * K + kt + lcc[i] * 8);
            cpasync16(st + 8192 + lsw[i], Bh + (size_t)(n0 + lrow[i]) * K + kt + lcc[i] * 8);
        }
    };

    const int C = K / 32;

    loadTile(0, sb + 0 * STGSZ);
    asm volatile("cp.async.commit_group;" ::: "memory");
    loadTile(32, sb + 1 * STGSZ);
    asm volatile("cp.async.commit_group;" ::: "memory");

    // ldmatrix constants
    const int rA  = wm + (lane & 15);
    const int hA  = lane >> 4;
    const int sAx = (rA >> 1) & 3;
    const int rB  = wn + (lane & 7) + ((lane >> 4) << 3);
    const int hB  = (lane >> 3) & 1;
    const int sBx = (rB >> 1) & 3;

    int s_cur = 0, s_nxt = 2;
    for (int c = 0; c < C; c++) {
        asm volatile("cp.async.wait_group 1;" ::: "memory");
        __syncthreads();

        const uint32_t st = sb + s_cur * STGSZ;
        const uint32_t nx = sb + s_nxt * STGSZ;
        if (c + 2 < C) loadTile((c + 2) * 32, nx);
        asm volatile("cp.async.commit_group;" ::: "memory");

#pragma unroll
        for (int ks = 0; ks < 2; ks++) {
            const int chA = ((ks * 2 + hA) ^ sAx) << 4;
            const int chB = ((ks * 2 + hB) ^ sBx) << 4;
            uint32_t ah[4][4], bh[4][4];
#pragma unroll
            for (int mt = 0; mt < 4; mt++)
                ldsm4(ah[mt][0], ah[mt][1], ah[mt][2], ah[mt][3],
                      st + (rA + mt * 16) * 64 + chA);
#pragma unroll
            for (int g = 0; g < 4; g++)
                ldsm4(bh[g][0], bh[g][1], bh[g][2], bh[g][3],
                      st + 8192 + (rB + g * 16) * 64 + chB);
#pragma unroll
            for (int mt = 0; mt < 4; mt++)
#pragma unroll
                for (int nt = 0; nt < 8; nt++)
                    mma16816h(acc[mt][nt], ah[mt],
                              bh[nt >> 1][(nt & 1) * 2], bh[nt >> 1][(nt & 1) * 2 + 1]);
        }
        s_cur = (s_cur == 2) ? 0 : s_cur + 1;
        s_nxt = (s_nxt == 2) ? 0 : s_nxt + 1;
    }

    // epilogue
#pragma unroll
    for (int mt = 0; mt < 4; mt++) {
        const int mrow = m0 + wm + mt * 16 + (lane >> 2);
#pragma unroll
        for (int nt = 0; nt < 8; nt++) {
            const int ncol = n0 + wn + nt * 8 + 2 * (lane & 3);
            float* cc = acc[mt][nt];
            if (EPI == 0) {
                float2 v0 = make_float2(fmaxf(cc[0], 0.f), fmaxf(cc[1], 0.f));
                float2 v1 = make_float2(fmaxf(cc[2], 0.f), fmaxf(cc[3], 0.f));
                *(float2*)(out + (size_t)mrow * ldo + ncol) = v0;
                *(float2*)(out + (size_t)(mrow + 8) * ldo + ncol) = v1;
            } else {
                if (ncol < NCAT) {
                    float bv = bias[ncol];
                    out[(size_t)mrow * ldo + ncol] = cc[0] + bv;
                    out[(size_t)(mrow + 8) * ldo + ncol] = cc[2] + bv;
                }
                if (ncol + 1 < NCAT) {
                    float bv = bias[ncol + 1];
                    out[(size_t)mrow * ldo + ncol + 1] = cc[1] + bv;
                    out[(size_t)(mrow + 8) * ldo + ncol + 1] = cc[3] + bv;
                }
            }
        }
    }
}

// ==============================================================================
// Leaf kernel: normalize comb row, emit GEMM2 A fp16 row, rfft -> g_spec.
// ==============================================================================
__global__ void __launch_bounds__(128) leaf_kernel(const int* __restrict__ opos)
{
    const int row = blockIdx.x;          // 0..16383
    const int b = row >> 6;
    const int dst = opos[(row << 1) + 0];
    const int src = opos[(row << 1) + 1];
    const int tid = threadIdx.x;

    __shared__ float2 sZ[256];
    __shared__ float2 stw[128];
    __shared__ float2 sw5[256];
    __shared__ float ws[4];

    stw[tid] = g_twf[tid];
    sw5[tid] = g_w512f[tid];
    sw5[tid + 128] = g_w512f[tid + 128];

    const float4* cp = (const float4*)(g_comb + ((size_t)(b * SEQ + src)) * HID);
    float4 v = cp[tid];
    float ss = v.x*v.x + v.y*v.y + v.z*v.z + v.w*v.w;
#pragma unroll
    for (int o = 16; o; o >>= 1) ss += __shfl_xor_sync(0xffffffffu, ss, o);
    if ((tid & 31) == 0) ws[tid >> 5] = ss;
    __syncthreads();
    float sc = 1.f / (sqrtf(ws[0] + ws[1] + ws[2] + ws[3]) + 1e-6f);
    v = make_float4(v.x*sc, v.y*sc, v.z*sc, v.w*sc);

    const size_t nrow = (size_t)(b * MAXN + dst);
    {
        uint32_t* rh = (uint32_t*)(g_a2h + nrow * HID);
        rh[2*tid]     = f2h2(v.x, v.y);
        rh[2*tid + 1] = f2h2(v.z, v.w);
    }

    sZ[2*tid]     = make_float2(v.x, v.y);
    sZ[2*tid + 1] = make_float2(v.z, v.w);
    __syncthreads();

#pragma unroll
    for (int s = 0; s < 8; s++) {
        const int half = 128 >> s;
        const int j = tid & (half - 1);
        const int p0 = (tid / half) * (half * 2) + j;
        const int p1 = p0 + half;
        float2 w = stw[j << s];
        float2 u = sZ[p0], vv = sZ[p1];
        sZ[p0] = make_float2(u.x + vv.x, u.y + vv.y);
        float dx = u.x - vv.x, dy = u.y - vv.y;
        sZ[p1] = make_float2(dx * w.x - dy * w.y, dx * w.y + dy * w.x);
        __syncthreads();
    }

    float* spec = g_spec + nrow * SPST;
#pragma unroll
    for (int h = 0; h < 2; h++) {
        int k = tid + h * 128;
        int kb = __brev((unsigned)k) >> 24;
        int km = __brev((unsigned)((256 - k) & 255)) >> 24;
        float2 Zk = sZ[kb], Zm = sZ[km];
        float er = 0.5f * (Zk.x + Zm.x);
        float ei = 0.5f * (Zk.y - Zm.y);
        float orr = 0.5f * (Zk.y + Zm.y);
        float oii = -0.5f * (Zk.x - Zm.x);
        float2 w = sw5[k];
        float2 X = make_float2(er + w.x * orr - w.y * oii,
                               ei + w.x * oii + w.y * orr);
        *(float2*)(spec + 2 * k) = X;
    }
    if (tid == 0)
        *(float2*)(spec + 512) = make_float2(sZ[0].x - sZ[0].y, 0.f);
}

// ==============================================================================
// Chain (spectral): one block per batch. All 64 leaf spectra cached in smem;
// F carried in registers. Gmem fallback only for non-leaf operands.
// ==============================================================================
#define CHAIN_SMEM (64 * 2080 + 16 + NSTEP * 4 * 4)

__global__ void __launch_bounds__(128) chain_spec_kernel(const int* __restrict__ cinfo)
{
    extern __shared__ __align__(16) char csm[];
    float2* cache = (float2*)csm;                       // 64 rows x 260 float2
    float*  ws    = (float*)(csm + 64 * 2080);          // 4 floats
    int*    sInfo = (int*)(csm + 64 * 2080 + 16);       // 252 ints

    const int b = blockIdx.x;
    const int tid = threadIdx.x;
    const size_t nbase = (size_t)b * MAXN;

    for (int i = tid; i < NSTEP * 4; i += 128) sInfo[i] = cinfo[(size_t)b * NSTEP * 4 + i];

    // preload all 64 leaf spectra (contiguous 133120 B)
    {
        const float* src = g_spec + nbase * SPST;
        uint32_t dst = smem_u32(cache);
        for (int i = tid; i < 8320; i += 128) cpasync16(dst + i * 16, src + i * 4);
        asm volatile("cp.async.commit_group;" ::: "memory");
        asm volatile("cp.async.wait_group 0;" ::: "memory");
    }
    __syncthreads();

    float2 F0 = make_float2(0.f, 0.f), F1 = F0, F2 = F0;   // F2 valid on tid 0
    int prev_p = -1;

    for (int k = 0; k < NSTEP; k++) {
        const int t = sInfo[k*4 + 0];
        const int p = sInfo[k*4 + 1];
        const int l = sInfo[k*4 + 2];
        const int r = sInfo[k*4 + 3];

        if (l != prev_p) {
            if (l < 64) {
                F0 = cache[l * 260 + tid];
                F1 = cache[l * 260 + tid + 128];
                if (tid == 0) F2 = cache[l * 260 + 256];
            } else {
                const float2* fr = (const float2*)(g_spec + (nbase + l) * SPST);
                F0 = fr[tid]; F1 = fr[tid + 128];
                if (tid == 0) F2 = fr[256];
            }
        }
        float2 G0, G1, G2 = make_float2(0.f, 0.f);
        if (r < 64) {
            G0 = cache[r * 260 + tid];
            G1 = cache[r * 260 + tid + 128];
            if (tid == 0) G2 = cache[r * 260 + 256];
        } else {
            const float2* gr = (const float2*)(g_spec + (nbase + r) * SPST);
            G0 = gr[tid]; G1 = gr[tid + 128];
            if (tid == 0) G2 = gr[256];
        }

        float* specP = g_spec + (nbase + p) * SPST;

        if (t == 2) {
            float2 c0 = make_float2(F0.x*G0.x + F0.y*G0.y, F0.x*G0.y - F0.y*G0.x);
            float2 c1 = make_float2(F1.x*G1.x + F1.y*G1.y, F1.x*G1.y - F1.y*G1.x);
            float w0 = (tid == 0) ? 1.f : 2.f;
            float part = w0 * (c0.x*c0.x + c0.y*c0.y) + 2.f * (c1.x*c1.x + c1.y*c1.y);
            float2 c2 = make_float2(0.f, 0.f);
            if (tid == 0) {
                c2 = make_float2(F2.x*G2.x + F2.y*G2.y, F2.x*G2.y - F2.y*G2.x);
                part += c2.x*c2.x + c2.y*c2.y;
            }
#pragma unroll
            for (int o = 16; o; o >>= 1) part += __shfl_xor_sync(0xffffffffu, part, o);
            if ((tid & 31) == 0) ws[tid >> 5] = part;
            __syncthreads();
            float s = 1.f / (sqrtf((ws[0] + ws[1] + ws[2] + ws[3]) * (1.f / 512.f)) + 1e-6f);

            F0 = make_float2(s * c0.x, s * c0.y);
            F1 = make_float2(s * c1.x, s * c1.y);
            *(float2*)(specP + 2 * tid) = F0;
            *(float2*)(specP + 2 * (tid + 128)) = F1;
            if (tid == 0) {
                F2 = make_float2(s * c2.x, s * c2.y);
                *(float2*)(specP + 512) = F2;
            }
        } else if (t == 1) {
            *(float2*)(specP + 2 * tid) = F0;
            *(float2*)(specP + 2 * (tid + 128)) = F1;
            if (tid == 0) *(float2*)(specP + 512) = F2;
        } else {
            float2 z = make_float2(0.f, 0.f);
            F0 = z; F1 = z; F2 = z;
            *(float2*)(specP + 2 * tid) = z;
            *(float2*)(specP + 2 * (tid + 128)) = z;
            if (tid == 0) *(float2*)(specP + 512) = z;
        }
        prev_p = p;
        __syncthreads();
    }
}

// ==============================================================================
// irfft of the 63 internal nodes per batch -> GEMM2 A fp16 rows.
// ==============================================================================
__global__ void __launch_bounds__(128) irfft_nodes_kernel()
{
    const int idx = blockIdx.x;               // 0..16127
    const int b = idx / NSTEP, i = idx - b * NSTEP;
    const int node = 64 + i;
    const int tid = threadIdx.x;
    __shared__ float2 sX[257];
    __shared__ float2 sZ[256];
    __shared__ float2 stw[128];
    __shared__ float2 sw5[256];

    stw[tid] = g_twi[tid];
    sw5[tid] = g_w512i[tid];
    sw5[tid + 128] = g_w512i[tid + 128];

    const size_t nrow = (size_t)(b * MAXN + node);
    const float2* sp = (const float2*)(g_spec + nrow * SPST);
    sX[tid] = sp[tid];
    sX[tid + 128] = sp[tid + 128];
    if (tid == 0) sX[256] = sp[256];
    __syncthreads();

    const float inv512 = 1.f / 512.f;
#pragma unroll
    for (int h = 0; h < 2; h++) {
        int k = tid + h * 128;
        float2 A = sX[k], B = sX[256 - k];
        float er = A.x + B.x;
        float ei = A.y - B.y;
        float dr = A.x - B.x;
        float di = A.y + B.y;
        float2 w = sw5[k];
        float qr = w.x * dr - w.y * di;
        float qi = w.x * di + w.y * dr;
        float2 Z = make_float2(inv512 * (er - qi), inv512 * (ei + qr));
        sZ[__brev((unsigned)k) >> 24] = Z;
    }
    __syncthreads();

#pragma unroll
    for (int s = 0; s < 8; s++) {
        const int half = 1 << s;
        const int j = tid & (half - 1);
        const int p0 = ((tid >> s) << (s + 1)) | j;
        const int p1 = p0 + half;
        float2 w = stw[j << (7 - s)];
        float2 u = sZ[p0], v = sZ[p1];
        float tx = v.x * w.x - v.y * w.y;
        float ty = v.x * w.y + v.y * w.x;
        sZ[p0] = make_float2(u.x + tx, u.y + ty);
        sZ[p1] = make_float2(u.x - tx, u.y - ty);
        __syncthreads();
    }

    uint32_t* rh = (uint32_t*)(g_a2h + nrow * HID);
#pragma unroll
    for (int h = 0; h < 2; h++) {
        int k = tid + h * 128;
        float2 z = sZ[k];
        rh[k] = f2h2(z.x, z.y);
    }
}

// ==============================================================================
extern "C" void kernel_launch(void* const* d_in, const int* in_sizes, int n_in,
                              void* d_out, int out_size)
{
    const float* seq  = (const float*)d_in[0];   // (256,64,1024)
    const float* W1   = (const float*)d_in[1];   // (512,512)
    const float* W2   = (const float*)d_in[2];   // (512,512)
    const float* LW   = (const float*)d_in[3];   // (511,512)
    const float* LB   = (const float*)d_in[4];   // (511,)
    const int*   opos = (const int*)d_in[7];     // (256,64,2)
    const int*   cinf = (const int*)d_in[8];     // (256,63,4)
    float* out = (float*)d_out;                  // (256,127,511)

    float* comb; __half *a1h, *a2h, *b1h, *b2h;
    cudaGetSymbolAddress((void**)&comb, g_comb);
    cudaGetSymbolAddress((void**)&a1h, g_a1h);
    cudaGetSymbolAddress((void**)&a2h, g_a2h);
    cudaGetSymbolAddress((void**)&b1h, g_b1h);
    cudaGetSymbolAddress((void**)&b2h, g_b2h);

    cudaFuncSetAttribute(mm_fp16_kernel<0>,
                         cudaFuncAttributeMaxDynamicSharedMemorySize, NSTG * STGSZ);
    cudaFuncSetAttribute(mm_fp16_kernel<1>,
                         cudaFuncAttributeMaxDynamicSharedMemorySize, NSTG * STGSZ);
    cudaFuncSetAttribute(chain_spec_kernel,
                         cudaFuncAttributeMaxDynamicSharedMemorySize, CHAIN_SMEM);

    init_tables_kernel<<<1, 256>>>();
    prep_a1_kernel<<<(BSZ * SEQ * EMB / 4) / 256, 256>>>(seq);
    {
        dim3 b(32, 8);
        dim3 g(EMB / 32, HID / 32);
        prep_b1_kernel<<<g, b>>>(W1, W2);
    }
    prep_b2_kernel<<<(512 * HID) / 256, 256>>>(LW);

    // GEMM1: comb = relu(seq @ [W1;W2]); fp16 single-pass
    {
        dim3 g(HID / BN, BSZ * SEQ / BM);         // (4, 128)
        mm_fp16_kernel<0><<<g, 128, NSTG * STGSZ>>>(a1h, b1h, nullptr, comb, EMB, HID);
    }

    leaf_kernel<<<BSZ * SEQ, 128>>>(opos);
    chain_spec_kernel<<<BSZ, 128, CHAIN_SMEM>>>(cinf);
    irfft_nodes_kernel<<<BSZ * NSTEP, 128>>>();

    // GEMM2: out = nodes @ LW^T + LB; fp16 single-pass
    {
        dim3 g(512 / BN, BSZ * MAXN / BM);        // (4, 254)
        mm_fp16_kernel<1><<<g, 128, NSTG * STGSZ>>>(a2h, b2h, LB, out, HID, NCAT);
    }
}